// round 9
// baseline (speedup 1.0000x reference)
#include <cuda_runtime.h>
#include <cuda_bf16.h>
#include <cstdint>

// ---------------- problem constants ----------------
#define E_EDGES   10000
#define NRED      19
#define MP_STRIDE (NRED*384)   // 7296
#define X0_DIM    1088

// ---------------- scratch (__device__ globals) ----------------
__device__ float g_w1T [384*128];
__device__ float g_w2T [128*128];
__device__ float g_w3T [128*1920];
__device__ __nv_bfloat16 g_wm0_hi[1088*1920];
__device__ __nv_bfloat16 g_wm0_lo[1088*1920];
__device__ __nv_bfloat16 g_wm1_hi[512*1536];
__device__ __nv_bfloat16 g_wm1_lo[512*1536];
__device__ __nv_bfloat16 g_wm2_hi[384*1152];
__device__ __nv_bfloat16 g_wm2_lo[384*1152];
__device__ float g_wrad[(long)E_EDGES*1920];
__device__ __nv_bfloat16 g_mp_hi[(long)E_EDGES*MP_STRIDE];
__device__ __nv_bfloat16 g_mp_lo[(long)E_EDGES*MP_STRIDE];
__device__ float g_x0  [(long)E_EDGES*X0_DIM];
__device__ float g_ym1 [(long)E_EDGES*2*512];
__device__ float g_ym2 [(long)E_EDGES*2*384];

// permutation tables
__constant__ int c_MASKP[19] = {0,2,6,12,20, 3,7,13,21, 1,5,11,19, 8,14,22, 4,10,18};
__constant__ int c_MASK [19] = {0,1,2,3,4,5,6,7,8,10,11,12,13,14,18,19,20,21,22};
__constant__ int c_PERM [19] = {0,2,6,11,16, 3,7,12,17, 1,5,10,15, 8,13,18, 4,9,14};
__constant__ int c_LPERM[19] = {0,1,2,3,4, 1,2,3,4, 1,2,3,4, 2,3,4, 2,3,4};
__constant__ int c_LFULL[25] = {0,1,1,1,2,2,2,2,2,3,3,3,3,3,3,3,4,4,4,4,4,4,4,4,4};

__device__ __forceinline__ float sigm(float x){ return 1.f/(1.f+__expf(-x)); }

__device__ __forceinline__ uint32_t smem_u32(const void* p) {
    uint32_t a;
    asm("{ .reg .u64 t; cvta.to.shared.u64 t, %1; cvt.u32.u64 %0, t; }" : "=r"(a) : "l"(p));
    return a;
}
__device__ __forceinline__ void cp16(uint32_t dst, const void* src) {
    asm volatile("cp.async.cg.shared.global [%0], [%1], 16;" :: "r"(dst), "l"(src));
}
__device__ __forceinline__ void ldm_x4(uint32_t addr, uint32_t* r) {
    asm volatile("ldmatrix.sync.aligned.m8n8.x4.shared.b16 {%0,%1,%2,%3}, [%4];"
                 : "=r"(r[0]), "=r"(r[1]), "=r"(r[2]), "=r"(r[3]) : "r"(addr));
}
__device__ __forceinline__ void mma16816(float* d, const uint32_t* a, uint32_t b0, uint32_t b1) {
    asm volatile("mma.sync.aligned.m16n8k16.row.col.f32.bf16.bf16.f32 "
                 "{%0,%1,%2,%3}, {%4,%5,%6,%7}, {%8,%9}, {%0,%1,%2,%3};"
                 : "+f"(d[0]), "+f"(d[1]), "+f"(d[2]), "+f"(d[3])
                 : "r"(a[0]), "r"(a[1]), "r"(a[2]), "r"(a[3]), "r"(b0), "r"(b1));
}

// ---------------- K0 (fused): transposes + bf16 splits, single launch ----------------
__global__ void k0_fused(const float* __restrict__ w1, const float* __restrict__ w2,
                         const float* __restrict__ w3, const float* __restrict__ wm0,
                         const float* __restrict__ wm1, const float* __restrict__ wm2) {
    long i = (long)blockIdx.x*256 + threadIdx.x;
    if (i < 49152) { int r = (int)(i/384), c = (int)(i%384); g_w1T[c*128+r] = w1[i]; return; }
    i -= 49152;
    if (i < 16384) { int r = (int)(i/128), c = (int)(i%128); g_w2T[c*128+r] = w2[i]; return; }
    i -= 16384;
    if (i < 245760) { int r = (int)(i/128), c = (int)(i%128); g_w3T[c*1920+r] = w3[i]; return; }
    i -= 245760;
    if (i < 2088960) {
        float v = wm0[i]; __nv_bfloat16 h = __float2bfloat16(v);
        g_wm0_hi[i] = h; g_wm0_lo[i] = __float2bfloat16(v - __bfloat162float(h));
        return;
    }
    i -= 2088960;
    if (i < 786432) {
        float v = wm1[i]; __nv_bfloat16 h = __float2bfloat16(v);
        g_wm1_hi[i] = h; g_wm1_lo[i] = __float2bfloat16(v - __bfloat162float(h));
        return;
    }
    i -= 786432;
    if (i < 442368) {
        float v = wm2[i]; __nv_bfloat16 h = __float2bfloat16(v);
        g_wm2_hi[i] = h; g_wm2_lo[i] = __float2bfloat16(v - __bfloat162float(h));
    }
}

// ---------------- K1: radial MLP (16 edges/block) ----------------
__device__ __forceinline__ void ln_silu16(float* buf, const float* __restrict__ g, const float* __restrict__ b) {
    int tid = threadIdx.x, w = tid >> 5, lane = tid & 31;
    for (int le = w; le < 16; le += 8) {
        float s = 0.f, s2 = 0.f;
        #pragma unroll
        for (int q = 0; q < 4; q++) { float v = buf[le*128 + lane + 32*q]; s += v; s2 += v*v; }
        #pragma unroll
        for (int off = 16; off > 0; off >>= 1) {
            s  += __shfl_xor_sync(0xffffffffu, s,  off);
            s2 += __shfl_xor_sync(0xffffffffu, s2, off);
        }
        float mu = s * (1.f/128.f);
        float var = s2 * (1.f/128.f) - mu*mu;
        float rstd = rsqrtf(var + 1e-5f);
        #pragma unroll
        for (int q = 0; q < 4; q++) {
            int oo = lane + 32*q;
            float v = buf[le*128 + oo];
            v = (v - mu)*rstd*g[oo] + b[oo];
            buf[le*128 + oo] = v * sigm(v);
        }
    }
}

__launch_bounds__(256)
__global__ void k1_radial(const float* __restrict__ ed,
                          const float* __restrict__ semb, const float* __restrict__ temb,
                          const float* __restrict__ b1, const float* __restrict__ g1, const float* __restrict__ bb1,
                          const float* __restrict__ b2, const float* __restrict__ g2, const float* __restrict__ bb2,
                          const float* __restrict__ b3,
                          const int* __restrict__ an, const int* __restrict__ ei) {
    __shared__ float xe[16*384];
    __shared__ float h1[16*128];
    __shared__ float h2[16*128];
    int e0 = blockIdx.x * 16;
    int tid = threadIdx.x;

    for (int idx = tid; idx < 16*384; idx += 256) {
        int le = idx / 384, c = idx - le*384;
        int e = e0 + le;
        float v;
        if (c < 128)       v = ed[e*128 + c];
        else if (c < 256)  v = semb[an[ei[e]]*128 + (c-128)];
        else               v = temb[an[ei[E_EDGES + e]]*128 + (c-256)];
        xe[idx] = v;
    }
    __syncthreads();

    int o = tid & 127, hh = tid >> 7;
    {
        float acc[8]; float bv = b1[o];
        #pragma unroll
        for (int j = 0; j < 8; j++) acc[j] = bv;
        #pragma unroll 4
        for (int k = 0; k < 384; k++) {
            float wv = g_w1T[k*128 + o];
            #pragma unroll
            for (int j = 0; j < 8; j++) acc[j] += wv * xe[(hh*8+j)*384 + k];
        }
        #pragma unroll
        for (int j = 0; j < 8; j++) h1[(hh*8+j)*128 + o] = acc[j];
    }
    __syncthreads();
    ln_silu16(h1, g1, bb1);
    __syncthreads();
    {
        float acc[8]; float bv = b2[o];
        #pragma unroll
        for (int j = 0; j < 8; j++) acc[j] = bv;
        #pragma unroll 4
        for (int k = 0; k < 128; k++) {
            float wv = g_w2T[k*128 + o];
            #pragma unroll
            for (int j = 0; j < 8; j++) acc[j] += wv * h1[(hh*8+j)*128 + k];
        }
        #pragma unroll
        for (int j = 0; j < 8; j++) h2[(hh*8+j)*128 + o] = acc[j];
    }
    __syncthreads();
    ln_silu16(h2, g2, bb2);
    __syncthreads();
    for (int oo = tid; oo < 1920; oo += 256) {
        float acc[16];
        #pragma unroll
        for (int le = 0; le < 16; le++) acc[le] = 0.f;
        #pragma unroll 4
        for (int k = 0; k < 128; k++) {
            float wv = g_w3T[k*1920 + oo];
            #pragma unroll
            for (int le = 0; le < 16; le++) acc[le] += wv * h2[le*128 + k];
        }
        float bv = b3[oo];
        #pragma unroll
        for (int le = 0; le < 16; le++)
            g_wrad[(long)(e0+le)*1920 + oo] = acc[le] + bv;
    }
}

// ---------------- K2: msg build * w_rad, Wigner fwd, permuted bf16-split store ----------------
__launch_bounds__(256)
__global__ void k2_wfwd(const float* __restrict__ x, const float* __restrict__ ef,
                        const float* __restrict__ wig, const int* __restrict__ ei) {
    __shared__ float msg[25*384];
    __shared__ float wp[19*25];
    int e = blockIdx.x, tid = threadIdx.x;
    int src = ei[e], tgt = ei[E_EDGES + e];

    for (int idx = tid; idx < 475; idx += 256) {
        int j = idx / 25, n = idx - j*25;
        wp[idx] = wig[(long)e*625 + c_MASKP[j]*25 + n];
    }
    const float4* x4  = (const float4*)x;
    const float4* ef4 = (const float4*)ef;
    const float4* wr4 = (const float4*)(g_wrad + (long)e*1920);
    float4* msg4 = (float4*)msg;
    for (int idx = tid; idx < 25*96; idx += 256) {
        int n = idx / 96, c4 = idx - n*96;
        float4 v;
        if (c4 < 32)      v = x4[(long)src*800 + n*32 + c4];
        else if (c4 < 64) v = x4[(long)tgt*800 + n*32 + (c4-32)];
        else              v = ef4[(long)e*800 + n*32 + (c4-64)];
        float4 w = wr4[c_LFULL[n]*96 + c4];
        v.x *= w.x; v.y *= w.y; v.z *= w.z; v.w *= w.w;
        msg4[idx] = v;
    }
    __syncthreads();

    const float4* m4 = (const float4*)msg;
    for (int idx = tid; idx < 19*96; idx += 256) {
        float4 acc = make_float4(0.f,0.f,0.f,0.f);
        int j = idx / 96, c4 = idx - j*96;
        #pragma unroll
        for (int n = 0; n < 25; n++) {
            float w = wp[j*25 + n];
            float4 m = m4[n*96 + c4];
            acc.x += w*m.x; acc.y += w*m.y; acc.z += w*m.z; acc.w += w*m.w;
        }
        long base = (long)e*MP_STRIDE + (long)idx*4;
        __nv_bfloat16 h0 = __float2bfloat16(acc.x);
        __nv_bfloat16 h1 = __float2bfloat16(acc.y);
        __nv_bfloat16 h2 = __float2bfloat16(acc.z);
        __nv_bfloat16 h3 = __float2bfloat16(acc.w);
        __nv_bfloat162 hp0; hp0.x = h0; hp0.y = h1;
        __nv_bfloat162 hp1; hp1.x = h2; hp1.y = h3;
        ((__nv_bfloat162*)(g_mp_hi + base))[0] = hp0;
        ((__nv_bfloat162*)(g_mp_hi + base))[1] = hp1;
        __nv_bfloat162 lp0, lp1;
        lp0.x = __float2bfloat16(acc.x - __bfloat162float(h0));
        lp0.y = __float2bfloat16(acc.y - __bfloat162float(h1));
        lp1.x = __float2bfloat16(acc.z - __bfloat162float(h2));
        lp1.y = __float2bfloat16(acc.w - __bfloat162float(h3));
        ((__nv_bfloat162*)(g_mp_lo + base))[0] = lp0;
        ((__nv_bfloat162*)(g_mp_lo + base))[1] = lp1;
    }
}

// ---------------- K3 (merged): mma.sync bf16x3 GEMM, all 3 modes in one grid ----------------
// blocks: [0,711) mode0 (9 x 79), [711,1339) mode1 (4 x 157), [1339,1810) mode2 (3 x 157)
#define K3_ROWB   80
#define K3_STG    40960
#define K3_DSMEM  (2*K3_STG)   // 81920
#define K3_GRID   1810

__launch_bounds__(256, 2)
__global__ void k3_all(const float* __restrict__ bias) {
    int id = blockIdx.x;
    int mode, nbx, mby;
    if (id < 711)       { mode = 0; nbx = id % 9;            mby = id / 9; }
    else if (id < 1339) { int t = id - 711;  mode = 1; nbx = t & 3; mby = t >> 2; }
    else                { int t = id - 1339; mode = 2; nbx = t % 3; mby = t / 3; }

    const int N  = (mode==0) ? 1088 : (mode==1) ? 512 : 384;
    const int K  = (mode==0) ? 1920 : (mode==1) ? 1536 : 1152;
    const int M  = (mode==0) ? E_EDGES : 2*E_EDGES;
    const int KC = K >> 5;
    const __nv_bfloat16* __restrict__ Whi = (mode==0) ? g_wm0_hi : (mode==1) ? g_wm1_hi : g_wm2_hi;
    const __nv_bfloat16* __restrict__ Wlo = (mode==0) ? g_wm0_lo : (mode==1) ? g_wm1_lo : g_wm2_lo;
    float* __restrict__ C = (mode==0) ? g_x0 : (mode==1) ? g_ym1 : g_ym2;

    extern __shared__ char dsm[];
    const uint32_t smb = smem_u32(dsm);
    const int tid = threadIdx.x;
    const int wid = tid >> 5, lane = tid & 31;
    const int n0 = nbx * 128;
    const int m0 = mby * 128;
    const int wm = (wid & 1) * 64;
    const int wn = (wid >> 1) * 32;

    float acc[4][4][4];
    #pragma unroll
    for (int i = 0; i < 4; i++)
        #pragma unroll
        for (int j = 0; j < 4; j++)
            #pragma unroll
            for (int q = 0; q < 4; q++) acc[i][j][q] = 0.f;

    const int lr = tid >> 2, slot = tid & 3;
    const __nv_bfloat16* aP[2];
    const __nv_bfloat16* wP[2];
    #pragma unroll
    for (int j = 0; j < 2; j++) {
        int r = lr + 64*j;
        int gr = m0 + r; if (gr >= M) gr = 0;
        long ab;
        if (mode == 0)      ab = (long)gr*MP_STRIDE;
        else if (mode == 1) ab = (long)(gr>>1)*MP_STRIDE + 1920 + (long)(gr&1)*1536;
        else                ab = (long)(gr>>1)*MP_STRIDE + 4992 + (long)(gr&1)*1152;
        aP[j] = g_mp_hi + ab + slot*8;
        int gn = n0 + r; if (gn >= N) gn = N-1;
        wP[j] = Whi + (long)gn*K + slot*8;
    }
    const long adel = (const __nv_bfloat16*)g_mp_lo - (const __nv_bfloat16*)g_mp_hi;
    const long wdel = Wlo - Whi;

    auto issue = [&](int c) {
        if (c < KC) {
            int k0 = c * 32;
            uint32_t st = smb + (c & 1) * K3_STG;
            #pragma unroll
            for (int j = 0; j < 2; j++) {
                uint32_t d = st + (lr + 64*j)*K3_ROWB + slot*16;
                cp16(d,         aP[j] + k0);
                cp16(d + 10240, aP[j] + adel + k0);
                cp16(d + 20480, wP[j] + k0);
                cp16(d + 30720, wP[j] + wdel + k0);
            }
        }
        asm volatile("cp.async.commit_group;" ::: "memory");
    };

    issue(0); issue(1);

    const int a_row = lane & 15, a_kh = lane >> 4;
    const int b_nl  = (lane & 7) | ((lane >> 4) << 3);
    const int b_kh  = (lane >> 3) & 1;

    for (int c = 0; c < KC; c++) {
        uint32_t st = smb + (c & 1) * K3_STG;
        asm volatile("cp.async.wait_group 1;" ::: "memory");
        __syncthreads();
        uint32_t aH = st +         (wm + a_row)*K3_ROWB + a_kh*16;
        uint32_t bH = st + 20480 + (wn + b_nl)*K3_ROWB + b_kh*16;
        #pragma unroll
        for (int ks = 0; ks < 2; ks++) {
            uint32_t af[4][4], bf[2][4], tb[2][4];
            #pragma unroll
            for (int mi = 0; mi < 4; mi++) ldm_x4(aH + ks*32 + mi*16*K3_ROWB, af[mi]);
            #pragma unroll
            for (int nf = 0; nf < 2; nf++) ldm_x4(bH + ks*32 + nf*16*K3_ROWB, bf[nf]);
            #pragma unroll
            for (int mi = 0; mi < 4; mi++)
                #pragma unroll
                for (int ni = 0; ni < 4; ni++)
                    mma16816(acc[mi][ni], af[mi], bf[ni>>1][(ni&1)*2], bf[ni>>1][(ni&1)*2+1]);
            #pragma unroll
            for (int nf = 0; nf < 2; nf++) ldm_x4(bH + 10240 + ks*32 + nf*16*K3_ROWB, tb[nf]);
            #pragma unroll
            for (int mi = 0; mi < 4; mi++)
                #pragma unroll
                for (int ni = 0; ni < 4; ni++)
                    mma16816(acc[mi][ni], af[mi], tb[ni>>1][(ni&1)*2], tb[ni>>1][(ni&1)*2+1]);
            #pragma unroll
            for (int mi = 0; mi < 4; mi++) ldm_x4(aH + 10240 + ks*32 + mi*16*K3_ROWB, af[mi]);
            #pragma unroll
            for (int mi = 0; mi < 4; mi++)
                #pragma unroll
                for (int ni = 0; ni < 4; ni++)
                    mma16816(acc[mi][ni], af[mi], bf[ni>>1][(ni&1)*2], bf[ni>>1][(ni&1)*2+1]);
        }
        __syncthreads();
        issue(c + 2);
    }

    int tg = lane >> 2, tig = lane & 3;
    #pragma unroll
    for (int mi = 0; mi < 4; mi++) {
        #pragma unroll
        for (int ni = 0; ni < 4; ni++) {
            int row = m0 + wm + 16*mi + tg;
            int col = n0 + wn + 8*ni + 2*tig;
            if (col < N) {
                float bx = 0.f, by = 0.f;
                if (mode == 0) { float2 bb = *(const float2*)(bias + col); bx = bb.x; by = bb.y; }
                if (row < M) {
                    float2 v = make_float2(acc[mi][ni][0] + bx, acc[mi][ni][1] + by);
                    *(float2*)(C + (long)row*N + col) = v;
                }
                if (row + 8 < M) {
                    float2 v = make_float2(acc[mi][ni][2] + bx, acc[mi][ni][3] + by);
                    *(float2*)(C + (long)(row+8)*N + col) = v;
                }
            }
        }
    }
}

// ---------------- K5: recombine+gate + Wigner back + projection (4 edges/block) ----------------
// dynamic smem: s_w 4*475 | s_hl 4*1216 | s_full 4*1600 | s_pw 128*65
#define K5_DSMEM ((1900 + 4864 + 6400 + 8320)*4)   // 85936

__launch_bounds__(256)
__global__ void k5_out(const float* __restrict__ wig,
                       const float* __restrict__ pw, const float* __restrict__ pb,
                       float* __restrict__ out) {
    extern __shared__ float sm[];
    float* s_w    = sm;           // 1900
    float* s_hl   = sm + 1900;    // 4864
    float* s_full = sm + 6764;    // 6400
    float* s_pw   = sm + 13164;   // 8320
    int e0 = blockIdx.x * 4;
    int tid = threadIdx.x;

    for (int idx = tid; idx < 1900; idx += 256) {
        int e = idx / 475, rem = idx - e*475;
        int r = rem / 25, n = rem - r*25;
        s_w[idx] = wig[(long)(e0+e)*625 + c_MASK[r]*25 + n];
    }
    // fused recombine + gating + inverse perm
    for (int idx = tid; idx < 4864; idx += 256) {
        int e = idx / 1216, rem = idx - e*1216;
        int j = rem >> 6, i = rem & 63;
        const float* x0 = g_x0  + (long)(e0+e)*X0_DIM;
        const float* y1 = g_ym1 + (long)(e0+e)*1024;
        const float* y2 = g_ym2 + (long)(e0+e)*768;
        float val;
        if (j < 5)        val = x0[768 + (j<<6) + i];
        else if (j < 9)  { int jj = j-5;  val = y1[jj*64 + i]       - y1[768 + jj*64 + i]; }
        else if (j < 13) { int jj = j-9;  val = y1[512 + jj*64 + i] + y1[256 + jj*64 + i]; }
        else if (j < 16) { int jj = j-13; val = y2[jj*64 + i]       - y2[576 + jj*64 + i]; }
        else             { int jj = j-16; val = y2[384 + jj*64 + i] + y2[192 + jj*64 + i]; }
        if (j == 0) {
            val = val * sigm(val);
        } else {
            float gsrc = x0[512 + (c_LPERM[j]-1)*64 + i];
            val *= sigm(gsrc);
        }
        s_hl[e*1216 + c_PERM[j]*64 + i] = val;
    }
    __syncthreads();
    for (int idx = tid; idx < 6400; idx += 256) {
        int e = idx / 1600, rem = idx - e*1600;
        int n = rem >> 6, i = rem & 63;
        float acc = 0.f;
        #pragma unroll
        for (int r = 0; r < 19; r++)
            acc += s_w[e*475 + r*25 + n] * s_hl[e*1216 + r*64 + i];
        s_full[idx] = acc;
    }

    int o = tid & 127, ph = tid >> 7;
    for (int l = 0; l < 5; l++) {
        __syncthreads();
        for (int idx = tid; idx < 8192; idx += 256)
            s_pw[(idx >> 6)*65 + (idx & 63)] = pw[l*8192 + idx];
        __syncthreads();
        int nrows = 2*l + 1, nstart = l*l;
        int npairs = 4*nrows;
        const float* pwrow = &s_pw[o*65];
        for (int p = ph; p < npairs; p += 2) {
            int e = p & 3, nr = p >> 2;
            const float* fu = &s_full[(e*25 + nstart + nr)*64];
            float acc = 0.f;
            #pragma unroll
            for (int i0 = 0; i0 < 64; i0 += 4) {
                float4 f = *(const float4*)(fu + i0);
                acc += f.x*pwrow[i0] + f.y*pwrow[i0+1] + f.z*pwrow[i0+2] + f.w*pwrow[i0+3];
            }
            if (l == 0) acc += pb[o];
            out[(long)(e0+e)*3200 + (nstart+nr)*128 + o] = acc;
        }
    }
}

// ---------------- launch ----------------
extern "C" void kernel_launch(void* const* d_in, const int* in_sizes, int n_in,
                              void* d_out, int out_size) {
    const float* x    = (const float*)d_in[0];
    const float* ef   = (const float*)d_in[1];
    const float* ed   = (const float*)d_in[2];
    const float* wig  = (const float*)d_in[3];
    const float* semb = (const float*)d_in[4];
    const float* temb = (const float*)d_in[5];
    const float* w1   = (const float*)d_in[6];
    const float* b1   = (const float*)d_in[7];
    const float* g1   = (const float*)d_in[8];
    const float* bb1  = (const float*)d_in[9];
    const float* w2   = (const float*)d_in[10];
    const float* b2   = (const float*)d_in[11];
    const float* g2   = (const float*)d_in[12];
    const float* bb2  = (const float*)d_in[13];
    const float* w3   = (const float*)d_in[14];
    const float* b3   = (const float*)d_in[15];
    const float* wm0  = (const float*)d_in[16];
    const float* bm0  = (const float*)d_in[17];
    const float* wm1  = (const float*)d_in[18];
    const float* wm2  = (const float*)d_in[19];
    const float* pw   = (const float*)d_in[20];
    const float* pb   = (const float*)d_in[21];
    const int*   an   = (const int*)d_in[22];
    const int*   ei   = (const int*)d_in[23];
    float* out = (float*)d_out;

    static bool attr_done = false;
    if (!attr_done) {
        cudaFuncSetAttribute(k3_all, cudaFuncAttributeMaxDynamicSharedMemorySize, K3_DSMEM);
        cudaFuncSetAttribute(k5_out, cudaFuncAttributeMaxDynamicSharedMemorySize, K5_DSMEM);
        attr_done = true;
    }

    // launch 0: fused prelude
    k0_fused<<<14176, 256>>>(w1, w2, w3, wm0, wm1, wm2);

    // launch 1: radial MLP
    k1_radial<<<E_EDGES/16, 256>>>(ed, semb, temb, b1, g1, bb1, b2, g2, bb2, b3, an, ei);

    // launch 2: msg * w_rad + Wigner forward
    k2_wfwd<<<E_EDGES, 256>>>(x, ef, wig, ei);

    // launch 3 (profiled): merged tensor-core GEMMs
    k3_all<<<K3_GRID, 256, K3_DSMEM>>>(bm0);

    // launch 4: fused recombine + Wigner back + projection (4 edges/block)
    k5_out<<<E_EDGES/4, 256, K5_DSMEM>>>(wig, pw, pb, out);
}

// round 11
// speedup vs baseline: 1.1004x; 1.1004x over previous
#include <cuda_runtime.h>
#include <cuda_bf16.h>
#include <cstdint>

// ---------------- problem constants ----------------
#define E_EDGES   10000
#define NRED      19
#define MP_STRIDE (NRED*384)   // 7296
#define X0_DIM    1088

// ---------------- scratch (__device__ globals) ----------------
__device__ float g_w1T [384*128];
__device__ float g_w2T [128*128];
__device__ float g_w3T [128*1920];
__device__ __nv_bfloat16 g_wm0_hi[1088*1920];
__device__ __nv_bfloat16 g_wm0_lo[1088*1920];
__device__ __nv_bfloat16 g_wm1_hi[512*1536];
__device__ __nv_bfloat16 g_wm1_lo[512*1536];
__device__ __nv_bfloat16 g_wm2_hi[384*1152];
__device__ __nv_bfloat16 g_wm2_lo[384*1152];
__device__ float g_wrad[(long)E_EDGES*1920];
__device__ __nv_bfloat16 g_mp_hi[(long)E_EDGES*MP_STRIDE];
__device__ __nv_bfloat16 g_mp_lo[(long)E_EDGES*MP_STRIDE];
__device__ float g_x0  [(long)E_EDGES*X0_DIM];
__device__ float g_ym1 [(long)E_EDGES*2*512];
__device__ float g_ym2 [(long)E_EDGES*2*384];

// permutation tables
__constant__ int c_MASKP[19] = {0,2,6,12,20, 3,7,13,21, 1,5,11,19, 8,14,22, 4,10,18};
__constant__ int c_MASK [19] = {0,1,2,3,4,5,6,7,8,10,11,12,13,14,18,19,20,21,22};
__constant__ int c_PERM [19] = {0,2,6,11,16, 3,7,12,17, 1,5,10,15, 8,13,18, 4,9,14};
__constant__ int c_LPERM[19] = {0,1,2,3,4, 1,2,3,4, 1,2,3,4, 2,3,4, 2,3,4};
__constant__ int c_LFULL[25] = {0,1,1,1,2,2,2,2,2,3,3,3,3,3,3,3,4,4,4,4,4,4,4,4,4};

__device__ __forceinline__ float sigm(float x){ return 1.f/(1.f+__expf(-x)); }

__device__ __forceinline__ uint32_t smem_u32(const void* p) {
    uint32_t a;
    asm("{ .reg .u64 t; cvta.to.shared.u64 t, %1; cvt.u32.u64 %0, t; }" : "=r"(a) : "l"(p));
    return a;
}
__device__ __forceinline__ void cp16(uint32_t dst, const void* src) {
    asm volatile("cp.async.cg.shared.global [%0], [%1], 16;" :: "r"(dst), "l"(src));
}
__device__ __forceinline__ void ldm_x4(uint32_t addr, uint32_t* r) {
    asm volatile("ldmatrix.sync.aligned.m8n8.x4.shared.b16 {%0,%1,%2,%3}, [%4];"
                 : "=r"(r[0]), "=r"(r[1]), "=r"(r[2]), "=r"(r[3]) : "r"(addr));
}
__device__ __forceinline__ void mma16816(float* d, const uint32_t* a, uint32_t b0, uint32_t b1) {
    asm volatile("mma.sync.aligned.m16n8k16.row.col.f32.bf16.bf16.f32 "
                 "{%0,%1,%2,%3}, {%4,%5,%6,%7}, {%8,%9}, {%0,%1,%2,%3};"
                 : "+f"(d[0]), "+f"(d[1]), "+f"(d[2]), "+f"(d[3])
                 : "r"(a[0]), "r"(a[1]), "r"(a[2]), "r"(a[3]), "r"(b0), "r"(b1));
}

// ---------------- K0 (fused): transposes + bf16 splits, single launch ----------------
__global__ void k0_fused(const float* __restrict__ w1, const float* __restrict__ w2,
                         const float* __restrict__ w3, const float* __restrict__ wm0,
                         const float* __restrict__ wm1, const float* __restrict__ wm2) {
    long i = (long)blockIdx.x*256 + threadIdx.x;
    if (i < 49152) { int r = (int)(i/384), c = (int)(i%384); g_w1T[c*128+r] = w1[i]; return; }
    i -= 49152;
    if (i < 16384) { int r = (int)(i/128), c = (int)(i%128); g_w2T[c*128+r] = w2[i]; return; }
    i -= 16384;
    if (i < 245760) { int r = (int)(i/128), c = (int)(i%128); g_w3T[c*1920+r] = w3[i]; return; }
    i -= 245760;
    if (i < 2088960) {
        float v = wm0[i]; __nv_bfloat16 h = __float2bfloat16(v);
        g_wm0_hi[i] = h; g_wm0_lo[i] = __float2bfloat16(v - __bfloat162float(h));
        return;
    }
    i -= 2088960;
    if (i < 786432) {
        float v = wm1[i]; __nv_bfloat16 h = __float2bfloat16(v);
        g_wm1_hi[i] = h; g_wm1_lo[i] = __float2bfloat16(v - __bfloat162float(h));
        return;
    }
    i -= 786432;
    if (i < 442368) {
        float v = wm2[i]; __nv_bfloat16 h = __float2bfloat16(v);
        g_wm2_hi[i] = h; g_wm2_lo[i] = __float2bfloat16(v - __bfloat162float(h));
    }
}

// ---------------- K1: radial MLP (16 edges/block) ----------------
__device__ __forceinline__ void ln_silu16(float* buf, const float* __restrict__ g, const float* __restrict__ b) {
    int tid = threadIdx.x, w = tid >> 5, lane = tid & 31;
    for (int le = w; le < 16; le += 8) {
        float s = 0.f, s2 = 0.f;
        #pragma unroll
        for (int q = 0; q < 4; q++) { float v = buf[le*128 + lane + 32*q]; s += v; s2 += v*v; }
        #pragma unroll
        for (int off = 16; off > 0; off >>= 1) {
            s  += __shfl_xor_sync(0xffffffffu, s,  off);
            s2 += __shfl_xor_sync(0xffffffffu, s2, off);
        }
        float mu = s * (1.f/128.f);
        float var = s2 * (1.f/128.f) - mu*mu;
        float rstd = rsqrtf(var + 1e-5f);
        #pragma unroll
        for (int q = 0; q < 4; q++) {
            int oo = lane + 32*q;
            float v = buf[le*128 + oo];
            v = (v - mu)*rstd*g[oo] + b[oo];
            buf[le*128 + oo] = v * sigm(v);
        }
    }
}

__launch_bounds__(256)
__global__ void k1_radial(const float* __restrict__ ed,
                          const float* __restrict__ semb, const float* __restrict__ temb,
                          const float* __restrict__ b1, const float* __restrict__ g1, const float* __restrict__ bb1,
                          const float* __restrict__ b2, const float* __restrict__ g2, const float* __restrict__ bb2,
                          const float* __restrict__ b3,
                          const int* __restrict__ an, const int* __restrict__ ei) {
    __shared__ float xe[16*384];
    __shared__ float h1[16*128];
    __shared__ float h2[16*128];
    int e0 = blockIdx.x * 16;
    int tid = threadIdx.x;

    for (int idx = tid; idx < 16*384; idx += 256) {
        int le = idx / 384, c = idx - le*384;
        int e = e0 + le;
        float v;
        if (c < 128)       v = ed[e*128 + c];
        else if (c < 256)  v = semb[an[ei[e]]*128 + (c-128)];
        else               v = temb[an[ei[E_EDGES + e]]*128 + (c-256)];
        xe[idx] = v;
    }
    __syncthreads();

    int o = tid & 127, hh = tid >> 7;
    {
        float acc[8]; float bv = b1[o];
        #pragma unroll
        for (int j = 0; j < 8; j++) acc[j] = bv;
        #pragma unroll 4
        for (int k = 0; k < 384; k++) {
            float wv = g_w1T[k*128 + o];
            #pragma unroll
            for (int j = 0; j < 8; j++) acc[j] += wv * xe[(hh*8+j)*384 + k];
        }
        #pragma unroll
        for (int j = 0; j < 8; j++) h1[(hh*8+j)*128 + o] = acc[j];
    }
    __syncthreads();
    ln_silu16(h1, g1, bb1);
    __syncthreads();
    {
        float acc[8]; float bv = b2[o];
        #pragma unroll
        for (int j = 0; j < 8; j++) acc[j] = bv;
        #pragma unroll 4
        for (int k = 0; k < 128; k++) {
            float wv = g_w2T[k*128 + o];
            #pragma unroll
            for (int j = 0; j < 8; j++) acc[j] += wv * h1[(hh*8+j)*128 + k];
        }
        #pragma unroll
        for (int j = 0; j < 8; j++) h2[(hh*8+j)*128 + o] = acc[j];
    }
    __syncthreads();
    ln_silu16(h2, g2, bb2);
    __syncthreads();
    for (int oo = tid; oo < 1920; oo += 256) {
        float acc[16];
        #pragma unroll
        for (int le = 0; le < 16; le++) acc[le] = 0.f;
        #pragma unroll 4
        for (int k = 0; k < 128; k++) {
            float wv = g_w3T[k*1920 + oo];
            #pragma unroll
            for (int le = 0; le < 16; le++) acc[le] += wv * h2[le*128 + k];
        }
        float bv = b3[oo];
        #pragma unroll
        for (int le = 0; le < 16; le++)
            g_wrad[(long)(e0+le)*1920 + oo] = acc[le] + bv;
    }
}

// ---------------- K2: msg build * w_rad, Wigner fwd (multi-j per thread), bf16-split ----------------
__launch_bounds__(256)
__global__ void k2_wfwd(const float* __restrict__ x, const float* __restrict__ ef,
                        const float* __restrict__ wig, const int* __restrict__ ei) {
    __shared__ float msg[25*384];
    __shared__ float wp[20*25];   // row 19 = zero pad
    int e = blockIdx.x, tid = threadIdx.x;
    int src = ei[e], tgt = ei[E_EDGES + e];

    for (int idx = tid; idx < 500; idx += 256) {
        int j = idx / 25, n = idx - j*25;
        wp[idx] = (j < 19) ? wig[(long)e*625 + c_MASKP[j]*25 + n] : 0.f;
    }
    const float4* x4  = (const float4*)x;
    const float4* ef4 = (const float4*)ef;
    const float4* wr4 = (const float4*)(g_wrad + (long)e*1920);
    float4* msg4 = (float4*)msg;
    for (int idx = tid; idx < 25*96; idx += 256) {
        int n = idx / 96, c4 = idx - n*96;
        float4 v;
        if (c4 < 32)      v = x4[(long)src*800 + n*32 + c4];
        else if (c4 < 64) v = x4[(long)tgt*800 + n*32 + (c4-32)];
        else              v = ef4[(long)e*800 + n*32 + (c4-64)];
        float4 w = wr4[c_LFULL[n]*96 + c4];
        v.x *= w.x; v.y *= w.y; v.z *= w.z; v.w *= w.w;
        msg4[idx] = v;
    }
    __syncthreads();

    // einsum: thread owns (c4, 4 consecutive j) -> each msg float4 read once per 4 j's
    const float4* m4 = (const float4*)msg;
    for (int idx = tid; idx < 480; idx += 256) {
        int c4 = idx % 96, j0 = (idx / 96) * 4;
        float4 acc[4];
        #pragma unroll
        for (int jj = 0; jj < 4; jj++) acc[jj] = make_float4(0.f,0.f,0.f,0.f);
        #pragma unroll 5
        for (int n = 0; n < 25; n++) {
            float4 m = m4[n*96 + c4];
            #pragma unroll
            for (int jj = 0; jj < 4; jj++) {
                float w = wp[(j0+jj)*25 + n];
                acc[jj].x += w*m.x; acc[jj].y += w*m.y;
                acc[jj].z += w*m.z; acc[jj].w += w*m.w;
            }
        }
        #pragma unroll
        for (int jj = 0; jj < 4; jj++) {
            int j = j0 + jj;
            if (j < 19) {
                long base = (long)e*MP_STRIDE + (long)(j*96 + c4)*4;
                float4 a = acc[jj];
                __nv_bfloat16 h0 = __float2bfloat16(a.x);
                __nv_bfloat16 h1 = __float2bfloat16(a.y);
                __nv_bfloat16 h2 = __float2bfloat16(a.z);
                __nv_bfloat16 h3 = __float2bfloat16(a.w);
                __nv_bfloat162 hp0; hp0.x = h0; hp0.y = h1;
                __nv_bfloat162 hp1; hp1.x = h2; hp1.y = h3;
                ((__nv_bfloat162*)(g_mp_hi + base))[0] = hp0;
                ((__nv_bfloat162*)(g_mp_hi + base))[1] = hp1;
                __nv_bfloat162 lp0, lp1;
                lp0.x = __float2bfloat16(a.x - __bfloat162float(h0));
                lp0.y = __float2bfloat16(a.y - __bfloat162float(h1));
                lp1.x = __float2bfloat16(a.z - __bfloat162float(h2));
                lp1.y = __float2bfloat16(a.w - __bfloat162float(h3));
                ((__nv_bfloat162*)(g_mp_lo + base))[0] = lp0;
                ((__nv_bfloat162*)(g_mp_lo + base))[1] = lp1;
            }
        }
    }
}

// ---------------- K3 (merged): mma.sync bf16x3 GEMM, all 3 modes in one grid ----------------
#define K3_ROWB   80
#define K3_STG    40960
#define K3_DSMEM  (2*K3_STG)   // 81920
#define K3_GRID   1810

__launch_bounds__(256, 2)
__global__ void k3_all(const float* __restrict__ bias) {
    int id = blockIdx.x;
    int mode, nbx, mby;
    if (id < 711)       { mode = 0; nbx = id % 9;            mby = id / 9; }
    else if (id < 1339) { int t = id - 711;  mode = 1; nbx = t & 3; mby = t >> 2; }
    else                { int t = id - 1339; mode = 2; nbx = t % 3; mby = t / 3; }

    const int N  = (mode==0) ? 1088 : (mode==1) ? 512 : 384;
    const int K  = (mode==0) ? 1920 : (mode==1) ? 1536 : 1152;
    const int M  = (mode==0) ? E_EDGES : 2*E_EDGES;
    const int KC = K >> 5;
    const __nv_bfloat16* __restrict__ Whi = (mode==0) ? g_wm0_hi : (mode==1) ? g_wm1_hi : g_wm2_hi;
    const __nv_bfloat16* __restrict__ Wlo = (mode==0) ? g_wm0_lo : (mode==1) ? g_wm1_lo : g_wm2_lo;
    float* __restrict__ C = (mode==0) ? g_x0 : (mode==1) ? g_ym1 : g_ym2;

    extern __shared__ char dsm[];
    const uint32_t smb = smem_u32(dsm);
    const int tid = threadIdx.x;
    const int wid = tid >> 5, lane = tid & 31;
    const int n0 = nbx * 128;
    const int m0 = mby * 128;
    const int wm = (wid & 1) * 64;
    const int wn = (wid >> 1) * 32;

    float acc[4][4][4];
    #pragma unroll
    for (int i = 0; i < 4; i++)
        #pragma unroll
        for (int j = 0; j < 4; j++)
            #pragma unroll
            for (int q = 0; q < 4; q++) acc[i][j][q] = 0.f;

    const int lr = tid >> 2, slot = tid & 3;
    const __nv_bfloat16* aP[2];
    const __nv_bfloat16* wP[2];
    #pragma unroll
    for (int j = 0; j < 2; j++) {
        int r = lr + 64*j;
        int gr = m0 + r; if (gr >= M) gr = 0;
        long ab;
        if (mode == 0)      ab = (long)gr*MP_STRIDE;
        else if (mode == 1) ab = (long)(gr>>1)*MP_STRIDE + 1920 + (long)(gr&1)*1536;
        else                ab = (long)(gr>>1)*MP_STRIDE + 4992 + (long)(gr&1)*1152;
        aP[j] = g_mp_hi + ab + slot*8;
        int gn = n0 + r; if (gn >= N) gn = N-1;
        wP[j] = Whi + (long)gn*K + slot*8;
    }
    const long adel = (const __nv_bfloat16*)g_mp_lo - (const __nv_bfloat16*)g_mp_hi;
    const long wdel = Wlo - Whi;

    auto issue = [&](int c) {
        if (c < KC) {
            int k0 = c * 32;
            uint32_t st = smb + (c & 1) * K3_STG;
            #pragma unroll
            for (int j = 0; j < 2; j++) {
                uint32_t d = st + (lr + 64*j)*K3_ROWB + slot*16;
                cp16(d,         aP[j] + k0);
                cp16(d + 10240, aP[j] + adel + k0);
                cp16(d + 20480, wP[j] + k0);
                cp16(d + 30720, wP[j] + wdel + k0);
            }
        }
        asm volatile("cp.async.commit_group;" ::: "memory");
    };

    issue(0); issue(1);

    const int a_row = lane & 15, a_kh = lane >> 4;
    const int b_nl  = (lane & 7) | ((lane >> 4) << 3);
    const int b_kh  = (lane >> 3) & 1;

    for (int c = 0; c < KC; c++) {
        uint32_t st = smb + (c & 1) * K3_STG;
        asm volatile("cp.async.wait_group 1;" ::: "memory");
        __syncthreads();
        uint32_t aH = st +         (wm + a_row)*K3_ROWB + a_kh*16;
        uint32_t bH = st + 20480 + (wn + b_nl)*K3_ROWB + b_kh*16;
        #pragma unroll
        for (int ks = 0; ks < 2; ks++) {
            uint32_t af[4][4], bf[2][4], tb[2][4];
            #pragma unroll
            for (int mi = 0; mi < 4; mi++) ldm_x4(aH + ks*32 + mi*16*K3_ROWB, af[mi]);
            #pragma unroll
            for (int nf = 0; nf < 2; nf++) ldm_x4(bH + ks*32 + nf*16*K3_ROWB, bf[nf]);
            #pragma unroll
            for (int mi = 0; mi < 4; mi++)
                #pragma unroll
                for (int ni = 0; ni < 4; ni++)
                    mma16816(acc[mi][ni], af[mi], bf[ni>>1][(ni&1)*2], bf[ni>>1][(ni&1)*2+1]);
            #pragma unroll
            for (int nf = 0; nf < 2; nf++) ldm_x4(bH + 10240 + ks*32 + nf*16*K3_ROWB, tb[nf]);
            #pragma unroll
            for (int mi = 0; mi < 4; mi++)
                #pragma unroll
                for (int ni = 0; ni < 4; ni++)
                    mma16816(acc[mi][ni], af[mi], tb[ni>>1][(ni&1)*2], tb[ni>>1][(ni&1)*2+1]);
            #pragma unroll
            for (int mi = 0; mi < 4; mi++) ldm_x4(aH + 10240 + ks*32 + mi*16*K3_ROWB, af[mi]);
            #pragma unroll
            for (int mi = 0; mi < 4; mi++)
                #pragma unroll
                for (int ni = 0; ni < 4; ni++)
                    mma16816(acc[mi][ni], af[mi], bf[ni>>1][(ni&1)*2], bf[ni>>1][(ni&1)*2+1]);
        }
        __syncthreads();
        issue(c + 2);
    }

    int tg = lane >> 2, tig = lane & 3;
    #pragma unroll
    for (int mi = 0; mi < 4; mi++) {
        #pragma unroll
        for (int ni = 0; ni < 4; ni++) {
            int row = m0 + wm + 16*mi + tg;
            int col = n0 + wn + 8*ni + 2*tig;
            if (col < N) {
                float bx = 0.f, by = 0.f;
                if (mode == 0) { float2 bb = *(const float2*)(bias + col); bx = bb.x; by = bb.y; }
                if (row < M) {
                    float2 v = make_float2(acc[mi][ni][0] + bx, acc[mi][ni][1] + by);
                    *(float2*)(C + (long)row*N + col) = v;
                }
                if (row + 8 < M) {
                    float2 v = make_float2(acc[mi][ni][2] + bx, acc[mi][ni][3] + by);
                    *(float2*)(C + (long)(row+8)*N + col) = v;
                }
            }
        }
    }
}

// ---------------- K5: recombine+gate + Wigner back + projection (4 edges/block) ----------------
// dynamic smem: s_w 4*475 | s_hl 4*1216 | s_full 4*1600 | s_pw 128*65
#define K5_DSMEM ((1900 + 4864 + 6400 + 8320)*4)   // 85936

__launch_bounds__(256)
__global__ void k5_out(const float* __restrict__ wig,
                       const float* __restrict__ pw, const float* __restrict__ pb,
                       float* __restrict__ out) {
    extern __shared__ float sm[];
    float* s_w    = sm;           // 1900
    float* s_hl   = sm + 1900;    // 4864
    float* s_full = sm + 6764;    // 6400
    float* s_pw   = sm + 13164;   // 8320
    int e0 = blockIdx.x * 4;
    int tid = threadIdx.x;

    for (int idx = tid; idx < 1900; idx += 256) {
        int e = idx / 475, rem = idx - e*475;
        int r = rem / 25, n = rem - r*25;
        s_w[idx] = wig[(long)(e0+e)*625 + c_MASK[r]*25 + n];
    }
    for (int idx = tid; idx < 4864; idx += 256) {
        int e = idx / 1216, rem = idx - e*1216;
        int j = rem >> 6, i = rem & 63;
        const float* x0 = g_x0  + (long)(e0+e)*X0_DIM;
        const float* y1 = g_ym1 + (long)(e0+e)*1024;
        const float* y2 = g_ym2 + (long)(e0+e)*768;
        float val;
        if (j < 5)        val = x0[768 + (j<<6) + i];
        else if (j < 9)  { int jj = j-5;  val = y1[jj*64 + i]       - y1[768 + jj*64 + i]; }
        else if (j < 13) { int jj = j-9;  val = y1[512 + jj*64 + i] + y1[256 + jj*64 + i]; }
        else if (j < 16) { int jj = j-13; val = y2[jj*64 + i]       - y2[576 + jj*64 + i]; }
        else             { int jj = j-16; val = y2[384 + jj*64 + i] + y2[192 + jj*64 + i]; }
        if (j == 0) {
            val = val * sigm(val);
        } else {
            float gsrc = x0[512 + (c_LPERM[j]-1)*64 + i];
            val *= sigm(gsrc);
        }
        s_hl[e*1216 + c_PERM[j]*64 + i] = val;
    }
    __syncthreads();
    for (int idx = tid; idx < 6400; idx += 256) {
        int e = idx / 1600, rem = idx - e*1600;
        int n = rem >> 6, i = rem & 63;
        float acc = 0.f;
        #pragma unroll
        for (int r = 0; r < 19; r++)
            acc += s_w[e*475 + r*25 + n] * s_hl[e*1216 + r*64 + i];
        s_full[idx] = acc;
    }

    int o = tid & 127, ph = tid >> 7;
    for (int l = 0; l < 5; l++) {
        __syncthreads();
        for (int idx = tid; idx < 8192; idx += 256)
            s_pw[(idx >> 6)*65 + (idx & 63)] = pw[l*8192 + idx];
        __syncthreads();
        // register-cache this thread's proj row (scalar LDS: stride-65 rows are
        // conflict-free; float4 here would be misaligned — o*65*4 % 16 != 0)
        float pwreg[64];
        const float* prow = &s_pw[o*65];
        #pragma unroll
        for (int i0 = 0; i0 < 64; i0++) pwreg[i0] = prow[i0];
        int nrows = 2*l + 1, nstart = l*l;
        int npairs = 4*nrows;
        for (int p = ph; p < npairs; p += 2) {
            int e = p & 3, nr = p >> 2;
            const float* fu = &s_full[(e*25 + nstart + nr)*64];
            float acc = 0.f;
            #pragma unroll
            for (int i0 = 0; i0 < 64; i0 += 4) {
                float4 f = *(const float4*)(fu + i0);
                acc += f.x*pwreg[i0] + f.y*pwreg[i0+1] + f.z*pwreg[i0+2] + f.w*pwreg[i0+3];
            }
            if (l == 0) acc += pb[o];
            out[(long)(e0+e)*3200 + (nstart+nr)*128 + o] = acc;
        }
    }
}

// ---------------- launch ----------------
extern "C" void kernel_launch(void* const* d_in, const int* in_sizes, int n_in,
                              void* d_out, int out_size) {
    const float* x    = (const float*)d_in[0];
    const float* ef   = (const float*)d_in[1];
    const float* ed   = (const float*)d_in[2];
    const float* wig  = (const float*)d_in[3];
    const float* semb = (const float*)d_in[4];
    const float* temb = (const float*)d_in[5];
    const float* w1   = (const float*)d_in[6];
    const float* b1   = (const float*)d_in[7];
    const float* g1   = (const float*)d_in[8];
    const float* bb1  = (const float*)d_in[9];
    const float* w2   = (const float*)d_in[10];
    const float* b2   = (const float*)d_in[11];
    const float* g2   = (const float*)d_in[12];
    const float* bb2  = (const float*)d_in[13];
    const float* w3   = (const float*)d_in[14];
    const float* b3   = (const float*)d_in[15];
    const float* wm0  = (const float*)d_in[16];
    const float* bm0  = (const float*)d_in[17];
    const float* wm1  = (const float*)d_in[18];
    const float* wm2  = (const float*)d_in[19];
    const float* pw   = (const float*)d_in[20];
    const float* pb   = (const float*)d_in[21];
    const int*   an   = (const int*)d_in[22];
    const int*   ei   = (const int*)d_in[23];
    float* out = (float*)d_out;

    static bool attr_done = false;
    if (!attr_done) {
        cudaFuncSetAttribute(k3_all, cudaFuncAttributeMaxDynamicSharedMemorySize, K3_DSMEM);
        cudaFuncSetAttribute(k5_out, cudaFuncAttributeMaxDynamicSharedMemorySize, K5_DSMEM);
        attr_done = true;
    }

    // launch 0: fused prelude
    k0_fused<<<14176, 256>>>(w1, w2, w3, wm0, wm1, wm2);

    // launch 1: radial MLP
    k1_radial<<<E_EDGES/16, 256>>>(ed, semb, temb, b1, g1, bb1, b2, g2, bb2, b3, an, ei);

    // launch 2: msg * w_rad + Wigner forward
    k2_wfwd<<<E_EDGES, 256>>>(x, ef, wig, ei);

    // launch 3 (profiled): merged tensor-core GEMMs
    k3_all<<<K3_GRID, 256, K3_DSMEM>>>(bm0);

    // launch 4: fused recombine + Wigner back + projection (4 edges/block)
    k5_out<<<E_EDGES/4, 256, K5_DSMEM>>>(wig, pw, pb, out);
}

// round 12
// speedup vs baseline: 1.3153x; 1.1953x over previous
#include <cuda_runtime.h>
#include <cuda_bf16.h>
#include <cstdint>

// ---------------- problem constants ----------------
#define E_EDGES   10000
#define NRED      19
#define MP_STRIDE (NRED*384)   // 7296
#define X0_DIM    1088

// ---------------- scratch (__device__ globals) ----------------
__device__ float g_w1T [384*128];
__device__ float g_w2T [128*128];
__device__ __nv_bfloat16 g_w3s_hi[1920*128];
__device__ __nv_bfloat16 g_w3s_lo[1920*128];
__device__ __nv_bfloat16 g_wm0_hi[1088*1920];
__device__ __nv_bfloat16 g_wm0_lo[1088*1920];
__device__ __nv_bfloat16 g_wm1_hi[512*1536];
__device__ __nv_bfloat16 g_wm1_lo[512*1536];
__device__ __nv_bfloat16 g_wm2_hi[384*1152];
__device__ __nv_bfloat16 g_wm2_lo[384*1152];
__device__ __nv_bfloat16 g_h2_hi[(long)E_EDGES*128];
__device__ __nv_bfloat16 g_h2_lo[(long)E_EDGES*128];
__device__ float g_wrad[(long)E_EDGES*1920];
__device__ __nv_bfloat16 g_mp_hi[(long)E_EDGES*MP_STRIDE];
__device__ __nv_bfloat16 g_mp_lo[(long)E_EDGES*MP_STRIDE];
__device__ float g_x0  [(long)E_EDGES*X0_DIM];
__device__ float g_ym1 [(long)E_EDGES*2*512];
__device__ float g_ym2 [(long)E_EDGES*2*384];

// permutation tables
__constant__ int c_MASKP[19] = {0,2,6,12,20, 3,7,13,21, 1,5,11,19, 8,14,22, 4,10,18};
__constant__ int c_MASK [19] = {0,1,2,3,4,5,6,7,8,10,11,12,13,14,18,19,20,21,22};
__constant__ int c_PERM [19] = {0,2,6,11,16, 3,7,12,17, 1,5,10,15, 8,13,18, 4,9,14};
__constant__ int c_LPERM[19] = {0,1,2,3,4, 1,2,3,4, 1,2,3,4, 2,3,4, 2,3,4};
__constant__ int c_LFULL[25] = {0,1,1,1,2,2,2,2,2,3,3,3,3,3,3,3,4,4,4,4,4,4,4,4,4};

__device__ __forceinline__ float sigm(float x){ return 1.f/(1.f+__expf(-x)); }

__device__ __forceinline__ uint32_t smem_u32(const void* p) {
    uint32_t a;
    asm("{ .reg .u64 t; cvta.to.shared.u64 t, %1; cvt.u32.u64 %0, t; }" : "=r"(a) : "l"(p));
    return a;
}
__device__ __forceinline__ void cp16(uint32_t dst, const void* src) {
    asm volatile("cp.async.cg.shared.global [%0], [%1], 16;" :: "r"(dst), "l"(src));
}
__device__ __forceinline__ void ldm_x4(uint32_t addr, uint32_t* r) {
    asm volatile("ldmatrix.sync.aligned.m8n8.x4.shared.b16 {%0,%1,%2,%3}, [%4];"
                 : "=r"(r[0]), "=r"(r[1]), "=r"(r[2]), "=r"(r[3]) : "r"(addr));
}
__device__ __forceinline__ void mma16816(float* d, const uint32_t* a, uint32_t b0, uint32_t b1) {
    asm volatile("mma.sync.aligned.m16n8k16.row.col.f32.bf16.bf16.f32 "
                 "{%0,%1,%2,%3}, {%4,%5,%6,%7}, {%8,%9}, {%0,%1,%2,%3};"
                 : "+f"(d[0]), "+f"(d[1]), "+f"(d[2]), "+f"(d[3])
                 : "r"(a[0]), "r"(a[1]), "r"(a[2]), "r"(a[3]), "r"(b0), "r"(b1));
}

// ---------------- K0 (fused): transposes + bf16 splits, single launch ----------------
__global__ void k0_fused(const float* __restrict__ w1, const float* __restrict__ w2,
                         const float* __restrict__ w3, const float* __restrict__ wm0,
                         const float* __restrict__ wm1, const float* __restrict__ wm2) {
    long i = (long)blockIdx.x*256 + threadIdx.x;
    if (i < 49152) { int r = (int)(i/384), c = (int)(i%384); g_w1T[c*128+r] = w1[i]; return; }
    i -= 49152;
    if (i < 16384) { int r = (int)(i/128), c = (int)(i%128); g_w2T[c*128+r] = w2[i]; return; }
    i -= 16384;
    if (i < 245760) {
        float v = w3[i]; __nv_bfloat16 h = __float2bfloat16(v);
        g_w3s_hi[i] = h; g_w3s_lo[i] = __float2bfloat16(v - __bfloat162float(h));
        return;
    }
    i -= 245760;
    if (i < 2088960) {
        float v = wm0[i]; __nv_bfloat16 h = __float2bfloat16(v);
        g_wm0_hi[i] = h; g_wm0_lo[i] = __float2bfloat16(v - __bfloat162float(h));
        return;
    }
    i -= 2088960;
    if (i < 786432) {
        float v = wm1[i]; __nv_bfloat16 h = __float2bfloat16(v);
        g_wm1_hi[i] = h; g_wm1_lo[i] = __float2bfloat16(v - __bfloat162float(h));
        return;
    }
    i -= 786432;
    if (i < 442368) {
        float v = wm2[i]; __nv_bfloat16 h = __float2bfloat16(v);
        g_wm2_hi[i] = h; g_wm2_lo[i] = __float2bfloat16(v - __bfloat162float(h));
    }
}

// ---------------- K1: radial MLP layers 1-2 (16 edges/block), h2 -> bf16 split ----------------
__device__ __forceinline__ void ln_silu16(float* buf, const float* __restrict__ g, const float* __restrict__ b) {
    int tid = threadIdx.x, w = tid >> 5, lane = tid & 31;
    for (int le = w; le < 16; le += 8) {
        float s = 0.f, s2 = 0.f;
        #pragma unroll
        for (int q = 0; q < 4; q++) { float v = buf[le*128 + lane + 32*q]; s += v; s2 += v*v; }
        #pragma unroll
        for (int off = 16; off > 0; off >>= 1) {
            s  += __shfl_xor_sync(0xffffffffu, s,  off);
            s2 += __shfl_xor_sync(0xffffffffu, s2, off);
        }
        float mu = s * (1.f/128.f);
        float var = s2 * (1.f/128.f) - mu*mu;
        float rstd = rsqrtf(var + 1e-5f);
        #pragma unroll
        for (int q = 0; q < 4; q++) {
            int oo = lane + 32*q;
            float v = buf[le*128 + oo];
            v = (v - mu)*rstd*g[oo] + b[oo];
            buf[le*128 + oo] = v * sigm(v);
        }
    }
}

__launch_bounds__(256)
__global__ void k1_radial(const float* __restrict__ ed,
                          const float* __restrict__ semb, const float* __restrict__ temb,
                          const float* __restrict__ b1, const float* __restrict__ g1, const float* __restrict__ bb1,
                          const float* __restrict__ b2, const float* __restrict__ g2, const float* __restrict__ bb2,
                          const int* __restrict__ an, const int* __restrict__ ei) {
    __shared__ float xe[16*384];
    __shared__ float h1[16*128];
    __shared__ float h2[16*128];
    int e0 = blockIdx.x * 16;
    int tid = threadIdx.x;

    for (int idx = tid; idx < 16*384; idx += 256) {
        int le = idx / 384, c = idx - le*384;
        int e = e0 + le;
        float v;
        if (c < 128)       v = ed[e*128 + c];
        else if (c < 256)  v = semb[an[ei[e]]*128 + (c-128)];
        else               v = temb[an[ei[E_EDGES + e]]*128 + (c-256)];
        xe[idx] = v;
    }
    __syncthreads();

    int o = tid & 127, hh = tid >> 7;
    {
        float acc[8]; float bv = b1[o];
        #pragma unroll
        for (int j = 0; j < 8; j++) acc[j] = bv;
        #pragma unroll 4
        for (int k = 0; k < 384; k++) {
            float wv = g_w1T[k*128 + o];
            #pragma unroll
            for (int j = 0; j < 8; j++) acc[j] += wv * xe[(hh*8+j)*384 + k];
        }
        #pragma unroll
        for (int j = 0; j < 8; j++) h1[(hh*8+j)*128 + o] = acc[j];
    }
    __syncthreads();
    ln_silu16(h1, g1, bb1);
    __syncthreads();
    {
        float acc[8]; float bv = b2[o];
        #pragma unroll
        for (int j = 0; j < 8; j++) acc[j] = bv;
        #pragma unroll 4
        for (int k = 0; k < 128; k++) {
            float wv = g_w2T[k*128 + o];
            #pragma unroll
            for (int j = 0; j < 8; j++) acc[j] += wv * h1[(hh*8+j)*128 + k];
        }
        #pragma unroll
        for (int j = 0; j < 8; j++) h2[(hh*8+j)*128 + o] = acc[j];
    }
    __syncthreads();
    ln_silu16(h2, g2, bb2);
    __syncthreads();
    // store h2 as bf16 hi/lo for the tensor-core layer-3 GEMM
    for (int idx = tid; idx < 2048; idx += 256) {
        float v = h2[idx];
        long base = (long)e0*128 + idx;
        __nv_bfloat16 h = __float2bfloat16(v);
        g_h2_hi[base] = h;
        g_h2_lo[base] = __float2bfloat16(v - __bfloat162float(h));
    }
}

// ---------------- K1G: layer-3 GEMM  g_wrad[10000,1920] = h2 @ w3^T + b3 (bf16x3 mma) ----------------
#define K3_ROWB   80
#define K3_STG    40960
#define K3_DSMEM  (2*K3_STG)   // 81920

__launch_bounds__(256, 2)
__global__ void k1_gemm(const float* __restrict__ bias) {
    const int N = 1920, K = 128, M = E_EDGES, KC = 4;
    extern __shared__ char dsm[];
    const uint32_t smb = smem_u32(dsm);
    const int tid = threadIdx.x;
    const int wid = tid >> 5, lane = tid & 31;
    const int n0 = blockIdx.x * 128;
    const int m0 = blockIdx.y * 128;
    const int wm = (wid & 1) * 64;
    const int wn = (wid >> 1) * 32;

    float acc[4][4][4];
    #pragma unroll
    for (int i = 0; i < 4; i++)
        #pragma unroll
        for (int j = 0; j < 4; j++)
            #pragma unroll
            for (int q = 0; q < 4; q++) acc[i][j][q] = 0.f;

    const int lr = tid >> 2, slot = tid & 3;
    const __nv_bfloat16* aP[2];
    const __nv_bfloat16* wP[2];
    #pragma unroll
    for (int j = 0; j < 2; j++) {
        int r = lr + 64*j;
        int gr = m0 + r; if (gr >= M) gr = 0;
        aP[j] = g_h2_hi + (long)gr*128 + slot*8;
        int gn = n0 + r;
        wP[j] = g_w3s_hi + (long)gn*K + slot*8;
    }
    const long adel = (const __nv_bfloat16*)g_h2_lo  - (const __nv_bfloat16*)g_h2_hi;
    const long wdel = (const __nv_bfloat16*)g_w3s_lo - (const __nv_bfloat16*)g_w3s_hi;

    auto issue = [&](int c) {
        if (c < KC) {
            int k0 = c * 32;
            uint32_t st = smb + (c & 1) * K3_STG;
            #pragma unroll
            for (int j = 0; j < 2; j++) {
                uint32_t d = st + (lr + 64*j)*K3_ROWB + slot*16;
                cp16(d,         aP[j] + k0);
                cp16(d + 10240, aP[j] + adel + k0);
                cp16(d + 20480, wP[j] + k0);
                cp16(d + 30720, wP[j] + wdel + k0);
            }
        }
        asm volatile("cp.async.commit_group;" ::: "memory");
    };

    issue(0); issue(1);

    const int a_row = lane & 15, a_kh = lane >> 4;
    const int b_nl  = (lane & 7) | ((lane >> 4) << 3);
    const int b_kh  = (lane >> 3) & 1;

    for (int c = 0; c < KC; c++) {
        uint32_t st = smb + (c & 1) * K3_STG;
        asm volatile("cp.async.wait_group 1;" ::: "memory");
        __syncthreads();
        uint32_t aH = st +         (wm + a_row)*K3_ROWB + a_kh*16;
        uint32_t bH = st + 20480 + (wn + b_nl)*K3_ROWB + b_kh*16;
        #pragma unroll
        for (int ks = 0; ks < 2; ks++) {
            uint32_t af[4][4], bf[2][4], tb[2][4];
            #pragma unroll
            for (int mi = 0; mi < 4; mi++) ldm_x4(aH + ks*32 + mi*16*K3_ROWB, af[mi]);
            #pragma unroll
            for (int nf = 0; nf < 2; nf++) ldm_x4(bH + ks*32 + nf*16*K3_ROWB, bf[nf]);
            #pragma unroll
            for (int mi = 0; mi < 4; mi++)
                #pragma unroll
                for (int ni = 0; ni < 4; ni++)
                    mma16816(acc[mi][ni], af[mi], bf[ni>>1][(ni&1)*2], bf[ni>>1][(ni&1)*2+1]);
            #pragma unroll
            for (int nf = 0; nf < 2; nf++) ldm_x4(bH + 10240 + ks*32 + nf*16*K3_ROWB, tb[nf]);
            #pragma unroll
            for (int mi = 0; mi < 4; mi++)
                #pragma unroll
                for (int ni = 0; ni < 4; ni++)
                    mma16816(acc[mi][ni], af[mi], tb[ni>>1][(ni&1)*2], tb[ni>>1][(ni&1)*2+1]);
            #pragma unroll
            for (int mi = 0; mi < 4; mi++) ldm_x4(aH + 10240 + ks*32 + mi*16*K3_ROWB, af[mi]);
            #pragma unroll
            for (int mi = 0; mi < 4; mi++)
                #pragma unroll
                for (int ni = 0; ni < 4; ni++)
                    mma16816(acc[mi][ni], af[mi], bf[ni>>1][(ni&1)*2], bf[ni>>1][(ni&1)*2+1]);
        }
        __syncthreads();
        issue(c + 2);
    }

    int tg = lane >> 2, tig = lane & 3;
    #pragma unroll
    for (int mi = 0; mi < 4; mi++) {
        #pragma unroll
        for (int ni = 0; ni < 4; ni++) {
            int row = m0 + wm + 16*mi + tg;
            int col = n0 + wn + 8*ni + 2*tig;
            float2 bb = *(const float2*)(bias + col);
            if (row < M) {
                float2 v = make_float2(acc[mi][ni][0] + bb.x, acc[mi][ni][1] + bb.y);
                *(float2*)(g_wrad + (long)row*N + col) = v;
            }
            if (row + 8 < M) {
                float2 v = make_float2(acc[mi][ni][2] + bb.x, acc[mi][ni][3] + bb.y);
                *(float2*)(g_wrad + (long)(row+8)*N + col) = v;
            }
        }
    }
}

// ---------------- K2: msg build * w_rad, Wigner fwd (multi-j per thread), bf16-split ----------------
__launch_bounds__(256)
__global__ void k2_wfwd(const float* __restrict__ x, const float* __restrict__ ef,
                        const float* __restrict__ wig, const int* __restrict__ ei) {
    __shared__ float msg[25*384];
    __shared__ float wp[20*25];   // row 19 = zero pad
    int e = blockIdx.x, tid = threadIdx.x;
    int src = ei[e], tgt = ei[E_EDGES + e];

    for (int idx = tid; idx < 500; idx += 256) {
        int j = idx / 25, n = idx - j*25;
        wp[idx] = (j < 19) ? wig[(long)e*625 + c_MASKP[j]*25 + n] : 0.f;
    }
    const float4* x4  = (const float4*)x;
    const float4* ef4 = (const float4*)ef;
    const float4* wr4 = (const float4*)(g_wrad + (long)e*1920);
    float4* msg4 = (float4*)msg;
    for (int idx = tid; idx < 25*96; idx += 256) {
        int n = idx / 96, c4 = idx - n*96;
        float4 v;
        if (c4 < 32)      v = x4[(long)src*800 + n*32 + c4];
        else if (c4 < 64) v = x4[(long)tgt*800 + n*32 + (c4-32)];
        else              v = ef4[(long)e*800 + n*32 + (c4-64)];
        float4 w = wr4[c_LFULL[n]*96 + c4];
        v.x *= w.x; v.y *= w.y; v.z *= w.z; v.w *= w.w;
        msg4[idx] = v;
    }
    __syncthreads();

    const float4* m4 = (const float4*)msg;
    for (int idx = tid; idx < 480; idx += 256) {
        int c4 = idx % 96, j0 = (idx / 96) * 4;
        float4 acc[4];
        #pragma unroll
        for (int jj = 0; jj < 4; jj++) acc[jj] = make_float4(0.f,0.f,0.f,0.f);
        #pragma unroll 5
        for (int n = 0; n < 25; n++) {
            float4 m = m4[n*96 + c4];
            #pragma unroll
            for (int jj = 0; jj < 4; jj++) {
                float w = wp[(j0+jj)*25 + n];
                acc[jj].x += w*m.x; acc[jj].y += w*m.y;
                acc[jj].z += w*m.z; acc[jj].w += w*m.w;
            }
        }
        #pragma unroll
        for (int jj = 0; jj < 4; jj++) {
            int j = j0 + jj;
            if (j < 19) {
                long base = (long)e*MP_STRIDE + (long)(j*96 + c4)*4;
                float4 a = acc[jj];
                __nv_bfloat16 h0 = __float2bfloat16(a.x);
                __nv_bfloat16 h1 = __float2bfloat16(a.y);
                __nv_bfloat16 h2 = __float2bfloat16(a.z);
                __nv_bfloat16 h3 = __float2bfloat16(a.w);
                __nv_bfloat162 hp0; hp0.x = h0; hp0.y = h1;
                __nv_bfloat162 hp1; hp1.x = h2; hp1.y = h3;
                ((__nv_bfloat162*)(g_mp_hi + base))[0] = hp0;
                ((__nv_bfloat162*)(g_mp_hi + base))[1] = hp1;
                __nv_bfloat162 lp0, lp1;
                lp0.x = __float2bfloat16(a.x - __bfloat162float(h0));
                lp0.y = __float2bfloat16(a.y - __bfloat162float(h1));
                lp1.x = __float2bfloat16(a.z - __bfloat162float(h2));
                lp1.y = __float2bfloat16(a.w - __bfloat162float(h3));
                ((__nv_bfloat162*)(g_mp_lo + base))[0] = lp0;
                ((__nv_bfloat162*)(g_mp_lo + base))[1] = lp1;
            }
        }
    }
}

// ---------------- K3 (merged): mma.sync bf16x3 GEMM, all 3 modes in one grid ----------------
#define K3_GRID   1810

__launch_bounds__(256, 2)
__global__ void k3_all(const float* __restrict__ bias) {
    int id = blockIdx.x;
    int mode, nbx, mby;
    if (id < 711)       { mode = 0; nbx = id % 9;            mby = id / 9; }
    else if (id < 1339) { int t = id - 711;  mode = 1; nbx = t & 3; mby = t >> 2; }
    else                { int t = id - 1339; mode = 2; nbx = t % 3; mby = t / 3; }

    const int N  = (mode==0) ? 1088 : (mode==1) ? 512 : 384;
    const int K  = (mode==0) ? 1920 : (mode==1) ? 1536 : 1152;
    const int M  = (mode==0) ? E_EDGES : 2*E_EDGES;
    const int KC = K >> 5;
    const __nv_bfloat16* __restrict__ Whi = (mode==0) ? g_wm0_hi : (mode==1) ? g_wm1_hi : g_wm2_hi;
    const __nv_bfloat16* __restrict__ Wlo = (mode==0) ? g_wm0_lo : (mode==1) ? g_wm1_lo : g_wm2_lo;
    float* __restrict__ C = (mode==0) ? g_x0 : (mode==1) ? g_ym1 : g_ym2;

    extern __shared__ char dsm[];
    const uint32_t smb = smem_u32(dsm);
    const int tid = threadIdx.x;
    const int wid = tid >> 5, lane = tid & 31;
    const int n0 = nbx * 128;
    const int m0 = mby * 128;
    const int wm = (wid & 1) * 64;
    const int wn = (wid >> 1) * 32;

    float acc[4][4][4];
    #pragma unroll
    for (int i = 0; i < 4; i++)
        #pragma unroll
        for (int j = 0; j < 4; j++)
            #pragma unroll
            for (int q = 0; q < 4; q++) acc[i][j][q] = 0.f;

    const int lr = tid >> 2, slot = tid & 3;
    const __nv_bfloat16* aP[2];
    const __nv_bfloat16* wP[2];
    #pragma unroll
    for (int j = 0; j < 2; j++) {
        int r = lr + 64*j;
        int gr = m0 + r; if (gr >= M) gr = 0;
        long ab;
        if (mode == 0)      ab = (long)gr*MP_STRIDE;
        else if (mode == 1) ab = (long)(gr>>1)*MP_STRIDE + 1920 + (long)(gr&1)*1536;
        else                ab = (long)(gr>>1)*MP_STRIDE + 4992 + (long)(gr&1)*1152;
        aP[j] = g_mp_hi + ab + slot*8;
        int gn = n0 + r; if (gn >= N) gn = N-1;
        wP[j] = Whi + (long)gn*K + slot*8;
    }
    const long adel = (const __nv_bfloat16*)g_mp_lo - (const __nv_bfloat16*)g_mp_hi;
    const long wdel = Wlo - Whi;

    auto issue = [&](int c) {
        if (c < KC) {
            int k0 = c * 32;
            uint32_t st = smb + (c & 1) * K3_STG;
            #pragma unroll
            for (int j = 0; j < 2; j++) {
                uint32_t d = st + (lr + 64*j)*K3_ROWB + slot*16;
                cp16(d,         aP[j] + k0);
                cp16(d + 10240, aP[j] + adel + k0);
                cp16(d + 20480, wP[j] + k0);
                cp16(d + 30720, wP[j] + wdel + k0);
            }
        }
        asm volatile("cp.async.commit_group;" ::: "memory");
    };

    issue(0); issue(1);

    const int a_row = lane & 15, a_kh = lane >> 4;
    const int b_nl  = (lane & 7) | ((lane >> 4) << 3);
    const int b_kh  = (lane >> 3) & 1;

    for (int c = 0; c < KC; c++) {
        uint32_t st = smb + (c & 1) * K3_STG;
        asm volatile("cp.async.wait_group 1;" ::: "memory");
        __syncthreads();
        uint32_t aH = st +         (wm + a_row)*K3_ROWB + a_kh*16;
        uint32_t bH = st + 20480 + (wn + b_nl)*K3_ROWB + b_kh*16;
        #pragma unroll
        for (int ks = 0; ks < 2; ks++) {
            uint32_t af[4][4], bf[2][4], tb[2][4];
            #pragma unroll
            for (int mi = 0; mi < 4; mi++) ldm_x4(aH + ks*32 + mi*16*K3_ROWB, af[mi]);
            #pragma unroll
            for (int nf = 0; nf < 2; nf++) ldm_x4(bH + ks*32 + nf*16*K3_ROWB, bf[nf]);
            #pragma unroll
            for (int mi = 0; mi < 4; mi++)
                #pragma unroll
                for (int ni = 0; ni < 4; ni++)
                    mma16816(acc[mi][ni], af[mi], bf[ni>>1][(ni&1)*2], bf[ni>>1][(ni&1)*2+1]);
            #pragma unroll
            for (int nf = 0; nf < 2; nf++) ldm_x4(bH + 10240 + ks*32 + nf*16*K3_ROWB, tb[nf]);
            #pragma unroll
            for (int mi = 0; mi < 4; mi++)
                #pragma unroll
                for (int ni = 0; ni < 4; ni++)
                    mma16816(acc[mi][ni], af[mi], tb[ni>>1][(ni&1)*2], tb[ni>>1][(ni&1)*2+1]);
            #pragma unroll
            for (int mi = 0; mi < 4; mi++) ldm_x4(aH + 10240 + ks*32 + mi*16*K3_ROWB, af[mi]);
            #pragma unroll
            for (int mi = 0; mi < 4; mi++)
                #pragma unroll
                for (int ni = 0; ni < 4; ni++)
                    mma16816(acc[mi][ni], af[mi], bf[ni>>1][(ni&1)*2], bf[ni>>1][(ni&1)*2+1]);
        }
        __syncthreads();
        issue(c + 2);
    }

    int tg = lane >> 2, tig = lane & 3;
    #pragma unroll
    for (int mi = 0; mi < 4; mi++) {
        #pragma unroll
        for (int ni = 0; ni < 4; ni++) {
            int row = m0 + wm + 16*mi + tg;
            int col = n0 + wn + 8*ni + 2*tig;
            if (col < N) {
                float bx = 0.f, by = 0.f;
                if (mode == 0) { float2 bb = *(const float2*)(bias + col); bx = bb.x; by = bb.y; }
                if (row < M) {
                    float2 v = make_float2(acc[mi][ni][0] + bx, acc[mi][ni][1] + by);
                    *(float2*)(C + (long)row*N + col) = v;
                }
                if (row + 8 < M) {
                    float2 v = make_float2(acc[mi][ni][2] + bx, acc[mi][ni][3] + by);
                    *(float2*)(C + (long)(row+8)*N + col) = v;
                }
            }
        }
    }
}

// ---------------- K5: recombine+gate + Wigner back + projection (4 edges/block) ----------------
#define K5_DSMEM ((1900 + 4864 + 6400 + 8320)*4)   // 85936

__launch_bounds__(256)
__global__ void k5_out(const float* __restrict__ wig,
                       const float* __restrict__ pw, const float* __restrict__ pb,
                       float* __restrict__ out) {
    extern __shared__ float sm[];
    float* s_w    = sm;           // 1900
    float* s_hl   = sm + 1900;    // 4864
    float* s_full = sm + 6764;    // 6400
    float* s_pw   = sm + 13164;   // 8320
    int e0 = blockIdx.x * 4;
    int tid = threadIdx.x;

    for (int idx = tid; idx < 1900; idx += 256) {
        int e = idx / 475, rem = idx - e*475;
        int r = rem / 25, n = rem - r*25;
        s_w[idx] = wig[(long)(e0+e)*625 + c_MASK[r]*25 + n];
    }
    for (int idx = tid; idx < 4864; idx += 256) {
        int e = idx / 1216, rem = idx - e*1216;
        int j = rem >> 6, i = rem & 63;
        const float* x0 = g_x0  + (long)(e0+e)*X0_DIM;
        const float* y1 = g_ym1 + (long)(e0+e)*1024;
        const float* y2 = g_ym2 + (long)(e0+e)*768;
        float val;
        if (j < 5)        val = x0[768 + (j<<6) + i];
        else if (j < 9)  { int jj = j-5;  val = y1[jj*64 + i]       - y1[768 + jj*64 + i]; }
        else if (j < 13) { int jj = j-9;  val = y1[512 + jj*64 + i] + y1[256 + jj*64 + i]; }
        else if (j < 16) { int jj = j-13; val = y2[jj*64 + i]       - y2[576 + jj*64 + i]; }
        else             { int jj = j-16; val = y2[384 + jj*64 + i] + y2[192 + jj*64 + i]; }
        if (j == 0) {
            val = val * sigm(val);
        } else {
            float gsrc = x0[512 + (c_LPERM[j]-1)*64 + i];
            val *= sigm(gsrc);
        }
        s_hl[e*1216 + c_PERM[j]*64 + i] = val;
    }
    __syncthreads();
    for (int idx = tid; idx < 6400; idx += 256) {
        int e = idx / 1600, rem = idx - e*1600;
        int n = rem >> 6, i = rem & 63;
        float acc = 0.f;
        #pragma unroll
        for (int r = 0; r < 19; r++)
            acc += s_w[e*475 + r*25 + n] * s_hl[e*1216 + r*64 + i];
        s_full[idx] = acc;
    }

    int o = tid & 127, ph = tid >> 7;
    for (int l = 0; l < 5; l++) {
        __syncthreads();
        for (int idx = tid; idx < 8192; idx += 256)
            s_pw[(idx >> 6)*65 + (idx & 63)] = pw[l*8192 + idx];
        __syncthreads();
        float pwreg[64];
        const float* prow = &s_pw[o*65];
        #pragma unroll
        for (int i0 = 0; i0 < 64; i0++) pwreg[i0] = prow[i0];
        int nrows = 2*l + 1, nstart = l*l;
        int npairs = 4*nrows;
        for (int p = ph; p < npairs; p += 2) {
            int e = p & 3, nr = p >> 2;
            const float* fu = &s_full[(e*25 + nstart + nr)*64];
            float acc = 0.f;
            #pragma unroll
            for (int i0 = 0; i0 < 64; i0 += 4) {
                float4 f = *(const float4*)(fu + i0);
                acc += f.x*pwreg[i0] + f.y*pwreg[i0+1] + f.z*pwreg[i0+2] + f.w*pwreg[i0+3];
            }
            if (l == 0) acc += pb[o];
            out[(long)(e0+e)*3200 + (nstart+nr)*128 + o] = acc;
        }
    }
}

// ---------------- launch ----------------
extern "C" void kernel_launch(void* const* d_in, const int* in_sizes, int n_in,
                              void* d_out, int out_size) {
    const float* x    = (const float*)d_in[0];
    const float* ef   = (const float*)d_in[1];
    const float* ed   = (const float*)d_in[2];
    const float* wig  = (const float*)d_in[3];
    const float* semb = (const float*)d_in[4];
    const float* temb = (const float*)d_in[5];
    const float* w1   = (const float*)d_in[6];
    const float* b1   = (const float*)d_in[7];
    const float* g1   = (const float*)d_in[8];
    const float* bb1  = (const float*)d_in[9];
    const float* w2   = (const float*)d_in[10];
    const float* b2   = (const float*)d_in[11];
    const float* g2   = (const float*)d_in[12];
    const float* bb2  = (const float*)d_in[13];
    const float* w3   = (const float*)d_in[14];
    const float* b3   = (const float*)d_in[15];
    const float* wm0  = (const float*)d_in[16];
    const float* bm0  = (const float*)d_in[17];
    const float* wm1  = (const float*)d_in[18];
    const float* wm2  = (const float*)d_in[19];
    const float* pw   = (const float*)d_in[20];
    const float* pb   = (const float*)d_in[21];
    const int*   an   = (const int*)d_in[22];
    const int*   ei   = (const int*)d_in[23];
    float* out = (float*)d_out;

    static bool attr_done = false;
    if (!attr_done) {
        cudaFuncSetAttribute(k3_all,  cudaFuncAttributeMaxDynamicSharedMemorySize, K3_DSMEM);
        cudaFuncSetAttribute(k1_gemm, cudaFuncAttributeMaxDynamicSharedMemorySize, K3_DSMEM);
        cudaFuncSetAttribute(k5_out,  cudaFuncAttributeMaxDynamicSharedMemorySize, K5_DSMEM);
        attr_done = true;
    }

    // launch 0: fused prelude (transposes + bf16 splits)
    k0_fused<<<14176, 256>>>(w1, w2, w3, wm0, wm1, wm2);

    // launch 1: radial MLP layers 1-2
    k1_radial<<<E_EDGES/16, 256>>>(ed, semb, temb, b1, g1, bb1, b2, g2, bb2, an, ei);

    // launch 2: radial layer-3 GEMM on tensor cores
    k1_gemm<<<dim3(15, 79), 256, K3_DSMEM>>>(b3);

    // launch 3 (profiled): msg * w_rad + Wigner forward
    k2_wfwd<<<E_EDGES, 256>>>(x, ef, wig, ei);

    // launch 4: merged tensor-core GEMMs
    k3_all<<<K3_GRID, 256, K3_DSMEM>>>(bm0);

    // launch 5: fused recombine + Wigner back + projection
    k5_out<<<E_EDGES/4, 256, K5_DSMEM>>>(wig, pw, pb, out);
}

// round 13
// speedup vs baseline: 1.5992x; 1.2159x over previous
#include <cuda_runtime.h>
#include <cuda_bf16.h>
#include <cstdint>

// ---------------- problem constants ----------------
#define E_EDGES   10000
#define NRED      19
#define MP_STRIDE (NRED*384)   // 7296
#define X0_DIM    1088

// ---------------- scratch (__device__ globals) ----------------
__device__ float g_w1T [384*128];
__device__ float g_w2T [128*128];
__device__ __nv_bfloat16 g_w3s_hi[1920*128];
__device__ __nv_bfloat16 g_w3s_lo[1920*128];
__device__ __nv_bfloat16 g_wm0_hi[1088*1920];
__device__ __nv_bfloat16 g_wm0_lo[1088*1920];
__device__ __nv_bfloat16 g_wm1_hi[512*1536];
__device__ __nv_bfloat16 g_wm1_lo[512*1536];
__device__ __nv_bfloat16 g_wm2_hi[384*1152];
__device__ __nv_bfloat16 g_wm2_lo[384*1152];
__device__ __nv_bfloat16 g_pw_hi[5*128*64];
__device__ __nv_bfloat16 g_pw_lo[5*128*64];
__device__ __nv_bfloat16 g_h2_hi[(long)E_EDGES*128];
__device__ __nv_bfloat16 g_h2_lo[(long)E_EDGES*128];
__device__ float g_wrad[(long)E_EDGES*1920];
__device__ __nv_bfloat16 g_mp_hi[(long)E_EDGES*MP_STRIDE];
__device__ __nv_bfloat16 g_mp_lo[(long)E_EDGES*MP_STRIDE];
__device__ float g_x0  [(long)E_EDGES*X0_DIM];
__device__ float g_ym1 [(long)E_EDGES*2*512];
__device__ float g_ym2 [(long)E_EDGES*2*384];
__device__ __nv_bfloat16 g_full_hi[(long)E_EDGES*1600];
__device__ __nv_bfloat16 g_full_lo[(long)E_EDGES*1600];

// permutation tables
__constant__ int c_MASKP[19] = {0,2,6,12,20, 3,7,13,21, 1,5,11,19, 8,14,22, 4,10,18};
__constant__ int c_MASK [19] = {0,1,2,3,4,5,6,7,8,10,11,12,13,14,18,19,20,21,22};
__constant__ int c_PERM [19] = {0,2,6,11,16, 3,7,12,17, 1,5,10,15, 8,13,18, 4,9,14};
__constant__ int c_LPERM[19] = {0,1,2,3,4, 1,2,3,4, 1,2,3,4, 2,3,4, 2,3,4};
__constant__ int c_LFULL[25] = {0,1,1,1,2,2,2,2,2,3,3,3,3,3,3,3,4,4,4,4,4,4,4,4,4};

__device__ __forceinline__ float sigm(float x){ return 1.f/(1.f+__expf(-x)); }

__device__ __forceinline__ uint32_t smem_u32(const void* p) {
    uint32_t a;
    asm("{ .reg .u64 t; cvta.to.shared.u64 t, %1; cvt.u32.u64 %0, t; }" : "=r"(a) : "l"(p));
    return a;
}
__device__ __forceinline__ void cp16(uint32_t dst, const void* src) {
    asm volatile("cp.async.cg.shared.global [%0], [%1], 16;" :: "r"(dst), "l"(src));
}
__device__ __forceinline__ void ldm_x4(uint32_t addr, uint32_t* r) {
    asm volatile("ldmatrix.sync.aligned.m8n8.x4.shared.b16 {%0,%1,%2,%3}, [%4];"
                 : "=r"(r[0]), "=r"(r[1]), "=r"(r[2]), "=r"(r[3]) : "r"(addr));
}
__device__ __forceinline__ void mma16816(float* d, const uint32_t* a, uint32_t b0, uint32_t b1) {
    asm volatile("mma.sync.aligned.m16n8k16.row.col.f32.bf16.bf16.f32 "
                 "{%0,%1,%2,%3}, {%4,%5,%6,%7}, {%8,%9}, {%0,%1,%2,%3};"
                 : "+f"(d[0]), "+f"(d[1]), "+f"(d[2]), "+f"(d[3])
                 : "r"(a[0]), "r"(a[1]), "r"(a[2]), "r"(a[3]), "r"(b0), "r"(b1));
}

// ---------------- K0 (fused): transposes + bf16 splits, single launch ----------------
__global__ void k0_fused(const float* __restrict__ w1, const float* __restrict__ w2,
                         const float* __restrict__ w3, const float* __restrict__ wm0,
                         const float* __restrict__ wm1, const float* __restrict__ wm2,
                         const float* __restrict__ pw) {
    long i = (long)blockIdx.x*256 + threadIdx.x;
    if (i < 49152) { int r = (int)(i/384), c = (int)(i%384); g_w1T[c*128+r] = w1[i]; return; }
    i -= 49152;
    if (i < 16384) { int r = (int)(i/128), c = (int)(i%128); g_w2T[c*128+r] = w2[i]; return; }
    i -= 16384;
    if (i < 245760) {
        float v = w3[i]; __nv_bfloat16 h = __float2bfloat16(v);
        g_w3s_hi[i] = h; g_w3s_lo[i] = __float2bfloat16(v - __bfloat162float(h));
        return;
    }
    i -= 245760;
    if (i < 2088960) {
        float v = wm0[i]; __nv_bfloat16 h = __float2bfloat16(v);
        g_wm0_hi[i] = h; g_wm0_lo[i] = __float2bfloat16(v - __bfloat162float(h));
        return;
    }
    i -= 2088960;
    if (i < 786432) {
        float v = wm1[i]; __nv_bfloat16 h = __float2bfloat16(v);
        g_wm1_hi[i] = h; g_wm1_lo[i] = __float2bfloat16(v - __bfloat162float(h));
        return;
    }
    i -= 786432;
    if (i < 442368) {
        float v = wm2[i]; __nv_bfloat16 h = __float2bfloat16(v);
        g_wm2_hi[i] = h; g_wm2_lo[i] = __float2bfloat16(v - __bfloat162float(h));
        return;
    }
    i -= 442368;
    if (i < 40960) {
        float v = pw[i]; __nv_bfloat16 h = __float2bfloat16(v);
        g_pw_hi[i] = h; g_pw_lo[i] = __float2bfloat16(v - __bfloat162float(h));
    }
}

// ---------------- K1: radial MLP layers 1-2 (16 edges/block), h2 -> bf16 split ----------------
__device__ __forceinline__ void ln_silu16(float* buf, const float* __restrict__ g, const float* __restrict__ b) {
    int tid = threadIdx.x, w = tid >> 5, lane = tid & 31;
    for (int le = w; le < 16; le += 8) {
        float s = 0.f, s2 = 0.f;
        #pragma unroll
        for (int q = 0; q < 4; q++) { float v = buf[le*128 + lane + 32*q]; s += v; s2 += v*v; }
        #pragma unroll
        for (int off = 16; off > 0; off >>= 1) {
            s  += __shfl_xor_sync(0xffffffffu, s,  off);
            s2 += __shfl_xor_sync(0xffffffffu, s2, off);
        }
        float mu = s * (1.f/128.f);
        float var = s2 * (1.f/128.f) - mu*mu;
        float rstd = rsqrtf(var + 1e-5f);
        #pragma unroll
        for (int q = 0; q < 4; q++) {
            int oo = lane + 32*q;
            float v = buf[le*128 + oo];
            v = (v - mu)*rstd*g[oo] + b[oo];
            buf[le*128 + oo] = v * sigm(v);
        }
    }
}

__launch_bounds__(256)
__global__ void k1_radial(const float* __restrict__ ed,
                          const float* __restrict__ semb, const float* __restrict__ temb,
                          const float* __restrict__ b1, const float* __restrict__ g1, const float* __restrict__ bb1,
                          const float* __restrict__ b2, const float* __restrict__ g2, const float* __restrict__ bb2,
                          const int* __restrict__ an, const int* __restrict__ ei) {
    __shared__ float xe[16*384];
    __shared__ float h1[16*128];
    __shared__ float h2[16*128];
    int e0 = blockIdx.x * 16;
    int tid = threadIdx.x;

    for (int idx = tid; idx < 16*384; idx += 256) {
        int le = idx / 384, c = idx - le*384;
        int e = e0 + le;
        float v;
        if (c < 128)       v = ed[e*128 + c];
        else if (c < 256)  v = semb[an[ei[e]]*128 + (c-128)];
        else               v = temb[an[ei[E_EDGES + e]]*128 + (c-256)];
        xe[idx] = v;
    }
    __syncthreads();

    int o = tid & 127, hh = tid >> 7;
    {
        float acc[8]; float bv = b1[o];
        #pragma unroll
        for (int j = 0; j < 8; j++) acc[j] = bv;
        #pragma unroll 4
        for (int k = 0; k < 384; k++) {
            float wv = g_w1T[k*128 + o];
            #pragma unroll
            for (int j = 0; j < 8; j++) acc[j] += wv * xe[(hh*8+j)*384 + k];
        }
        #pragma unroll
        for (int j = 0; j < 8; j++) h1[(hh*8+j)*128 + o] = acc[j];
    }
    __syncthreads();
    ln_silu16(h1, g1, bb1);
    __syncthreads();
    {
        float acc[8]; float bv = b2[o];
        #pragma unroll
        for (int j = 0; j < 8; j++) acc[j] = bv;
        #pragma unroll 4
        for (int k = 0; k < 128; k++) {
            float wv = g_w2T[k*128 + o];
            #pragma unroll
            for (int j = 0; j < 8; j++) acc[j] += wv * h1[(hh*8+j)*128 + k];
        }
        #pragma unroll
        for (int j = 0; j < 8; j++) h2[(hh*8+j)*128 + o] = acc[j];
    }
    __syncthreads();
    ln_silu16(h2, g2, bb2);
    __syncthreads();
    for (int idx = tid; idx < 2048; idx += 256) {
        float v = h2[idx];
        long base = (long)e0*128 + idx;
        __nv_bfloat16 h = __float2bfloat16(v);
        g_h2_hi[base] = h;
        g_h2_lo[base] = __float2bfloat16(v - __bfloat162float(h));
    }
}

// ---------------- K1G: layer-3 GEMM  g_wrad = h2 @ w3^T + b3 (bf16x3 mma) ----------------
#define K3_ROWB   80
#define K3_STG    40960
#define K3_DSMEM  (2*K3_STG)   // 81920

__launch_bounds__(256, 2)
__global__ void k1_gemm(const float* __restrict__ bias) {
    const int N = 1920, K = 128, M = E_EDGES, KC = 4;
    extern __shared__ char dsm[];
    const uint32_t smb = smem_u32(dsm);
    const int tid = threadIdx.x;
    const int wid = tid >> 5, lane = tid & 31;
    const int n0 = blockIdx.x * 128;
    const int m0 = blockIdx.y * 128;
    const int wm = (wid & 1) * 64;
    const int wn = (wid >> 1) * 32;

    float acc[4][4][4];
    #pragma unroll
    for (int i = 0; i < 4; i++)
        #pragma unroll
        for (int j = 0; j < 4; j++)
            #pragma unroll
            for (int q = 0; q < 4; q++) acc[i][j][q] = 0.f;

    const int lr = tid >> 2, slot = tid & 3;
    const __nv_bfloat16* aP[2];
    const __nv_bfloat16* wP[2];
    #pragma unroll
    for (int j = 0; j < 2; j++) {
        int r = lr + 64*j;
        int gr = m0 + r; if (gr >= M) gr = 0;
        aP[j] = g_h2_hi + (long)gr*128 + slot*8;
        int gn = n0 + r;
        wP[j] = g_w3s_hi + (long)gn*K + slot*8;
    }
    const long adel = (const __nv_bfloat16*)g_h2_lo  - (const __nv_bfloat16*)g_h2_hi;
    const long wdel = (const __nv_bfloat16*)g_w3s_lo - (const __nv_bfloat16*)g_w3s_hi;

    auto issue = [&](int c) {
        if (c < KC) {
            int k0 = c * 32;
            uint32_t st = smb + (c & 1) * K3_STG;
            #pragma unroll
            for (int j = 0; j < 2; j++) {
                uint32_t d = st + (lr + 64*j)*K3_ROWB + slot*16;
                cp16(d,         aP[j] + k0);
                cp16(d + 10240, aP[j] + adel + k0);
                cp16(d + 20480, wP[j] + k0);
                cp16(d + 30720, wP[j] + wdel + k0);
            }
        }
        asm volatile("cp.async.commit_group;" ::: "memory");
    };

    issue(0); issue(1);

    const int a_row = lane & 15, a_kh = lane >> 4;
    const int b_nl  = (lane & 7) | ((lane >> 4) << 3);
    const int b_kh  = (lane >> 3) & 1;

    for (int c = 0; c < KC; c++) {
        uint32_t st = smb + (c & 1) * K3_STG;
        asm volatile("cp.async.wait_group 1;" ::: "memory");
        __syncthreads();
        uint32_t aH = st +         (wm + a_row)*K3_ROWB + a_kh*16;
        uint32_t bH = st + 20480 + (wn + b_nl)*K3_ROWB + b_kh*16;
        #pragma unroll
        for (int ks = 0; ks < 2; ks++) {
            uint32_t af[4][4], bf[2][4], tb[2][4];
            #pragma unroll
            for (int mi = 0; mi < 4; mi++) ldm_x4(aH + ks*32 + mi*16*K3_ROWB, af[mi]);
            #pragma unroll
            for (int nf = 0; nf < 2; nf++) ldm_x4(bH + ks*32 + nf*16*K3_ROWB, bf[nf]);
            #pragma unroll
            for (int mi = 0; mi < 4; mi++)
                #pragma unroll
                for (int ni = 0; ni < 4; ni++)
                    mma16816(acc[mi][ni], af[mi], bf[ni>>1][(ni&1)*2], bf[ni>>1][(ni&1)*2+1]);
            #pragma unroll
            for (int nf = 0; nf < 2; nf++) ldm_x4(bH + 10240 + ks*32 + nf*16*K3_ROWB, tb[nf]);
            #pragma unroll
            for (int mi = 0; mi < 4; mi++)
                #pragma unroll
                for (int ni = 0; ni < 4; ni++)
                    mma16816(acc[mi][ni], af[mi], tb[ni>>1][(ni&1)*2], tb[ni>>1][(ni&1)*2+1]);
            #pragma unroll
            for (int mi = 0; mi < 4; mi++) ldm_x4(aH + 10240 + ks*32 + mi*16*K3_ROWB, af[mi]);
            #pragma unroll
            for (int mi = 0; mi < 4; mi++)
                #pragma unroll
                for (int ni = 0; ni < 4; ni++)
                    mma16816(acc[mi][ni], af[mi], bf[ni>>1][(ni&1)*2], bf[ni>>1][(ni&1)*2+1]);
        }
        __syncthreads();
        issue(c + 2);
    }

    int tg = lane >> 2, tig = lane & 3;
    #pragma unroll
    for (int mi = 0; mi < 4; mi++) {
        #pragma unroll
        for (int ni = 0; ni < 4; ni++) {
            int row = m0 + wm + 16*mi + tg;
            int col = n0 + wn + 8*ni + 2*tig;
            float2 bb = *(const float2*)(bias + col);
            if (row < M) {
                float2 v = make_float2(acc[mi][ni][0] + bb.x, acc[mi][ni][1] + bb.y);
                *(float2*)(g_wrad + (long)row*N + col) = v;
            }
            if (row + 8 < M) {
                float2 v = make_float2(acc[mi][ni][2] + bb.x, acc[mi][ni][3] + bb.y);
                *(float2*)(g_wrad + (long)(row+8)*N + col) = v;
            }
        }
    }
}

// ---------------- K2: msg build * w_rad, Wigner fwd (multi-j per thread), bf16-split ----------------
__launch_bounds__(256)
__global__ void k2_wfwd(const float* __restrict__ x, const float* __restrict__ ef,
                        const float* __restrict__ wig, const int* __restrict__ ei) {
    __shared__ float msg[25*384];
    __shared__ float wp[20*25];   // row 19 = zero pad
    int e = blockIdx.x, tid = threadIdx.x;
    int src = ei[e], tgt = ei[E_EDGES + e];

    for (int idx = tid; idx < 500; idx += 256) {
        int j = idx / 25, n = idx - j*25;
        wp[idx] = (j < 19) ? wig[(long)e*625 + c_MASKP[j]*25 + n] : 0.f;
    }
    const float4* x4  = (const float4*)x;
    const float4* ef4 = (const float4*)ef;
    const float4* wr4 = (const float4*)(g_wrad + (long)e*1920);
    float4* msg4 = (float4*)msg;
    for (int idx = tid; idx < 25*96; idx += 256) {
        int n = idx / 96, c4 = idx - n*96;
        float4 v;
        if (c4 < 32)      v = x4[(long)src*800 + n*32 + c4];
        else if (c4 < 64) v = x4[(long)tgt*800 + n*32 + (c4-32)];
        else              v = ef4[(long)e*800 + n*32 + (c4-64)];
        float4 w = wr4[c_LFULL[n]*96 + c4];
        v.x *= w.x; v.y *= w.y; v.z *= w.z; v.w *= w.w;
        msg4[idx] = v;
    }
    __syncthreads();

    const float4* m4 = (const float4*)msg;
    for (int idx = tid; idx < 480; idx += 256) {
        int c4 = idx % 96, j0 = (idx / 96) * 4;
        float4 acc[4];
        #pragma unroll
        for (int jj = 0; jj < 4; jj++) acc[jj] = make_float4(0.f,0.f,0.f,0.f);
        #pragma unroll 5
        for (int n = 0; n < 25; n++) {
            float4 m = m4[n*96 + c4];
            #pragma unroll
            for (int jj = 0; jj < 4; jj++) {
                float w = wp[(j0+jj)*25 + n];
                acc[jj].x += w*m.x; acc[jj].y += w*m.y;
                acc[jj].z += w*m.z; acc[jj].w += w*m.w;
            }
        }
        #pragma unroll
        for (int jj = 0; jj < 4; jj++) {
            int j = j0 + jj;
            if (j < 19) {
                long base = (long)e*MP_STRIDE + (long)(j*96 + c4)*4;
                float4 a = acc[jj];
                __nv_bfloat16 h0 = __float2bfloat16(a.x);
                __nv_bfloat16 h1 = __float2bfloat16(a.y);
                __nv_bfloat16 h2 = __float2bfloat16(a.z);
                __nv_bfloat16 h3 = __float2bfloat16(a.w);
                __nv_bfloat162 hp0; hp0.x = h0; hp0.y = h1;
                __nv_bfloat162 hp1; hp1.x = h2; hp1.y = h3;
                ((__nv_bfloat162*)(g_mp_hi + base))[0] = hp0;
                ((__nv_bfloat162*)(g_mp_hi + base))[1] = hp1;
                __nv_bfloat162 lp0, lp1;
                lp0.x = __float2bfloat16(a.x - __bfloat162float(h0));
                lp0.y = __float2bfloat16(a.y - __bfloat162float(h1));
                lp1.x = __float2bfloat16(a.z - __bfloat162float(h2));
                lp1.y = __float2bfloat16(a.w - __bfloat162float(h3));
                ((__nv_bfloat162*)(g_mp_lo + base))[0] = lp0;
                ((__nv_bfloat162*)(g_mp_lo + base))[1] = lp1;
            }
        }
    }
}

// ---------------- K3 (merged): mma.sync bf16x3 GEMM, all 3 modes in one grid ----------------
#define K3_GRID   1810

__launch_bounds__(256, 2)
__global__ void k3_all(const float* __restrict__ bias) {
    int id = blockIdx.x;
    int mode, nbx, mby;
    if (id < 711)       { mode = 0; nbx = id % 9;            mby = id / 9; }
    else if (id < 1339) { int t = id - 711;  mode = 1; nbx = t & 3; mby = t >> 2; }
    else                { int t = id - 1339; mode = 2; nbx = t % 3; mby = t / 3; }

    const int N  = (mode==0) ? 1088 : (mode==1) ? 512 : 384;
    const int K  = (mode==0) ? 1920 : (mode==1) ? 1536 : 1152;
    const int M  = (mode==0) ? E_EDGES : 2*E_EDGES;
    const int KC = K >> 5;
    const __nv_bfloat16* __restrict__ Whi = (mode==0) ? g_wm0_hi : (mode==1) ? g_wm1_hi : g_wm2_hi;
    const __nv_bfloat16* __restrict__ Wlo = (mode==0) ? g_wm0_lo : (mode==1) ? g_wm1_lo : g_wm2_lo;
    float* __restrict__ C = (mode==0) ? g_x0 : (mode==1) ? g_ym1 : g_ym2;

    extern __shared__ char dsm[];
    const uint32_t smb = smem_u32(dsm);
    const int tid = threadIdx.x;
    const int wid = tid >> 5, lane = tid & 31;
    const int n0 = nbx * 128;
    const int m0 = mby * 128;
    const int wm = (wid & 1) * 64;
    const int wn = (wid >> 1) * 32;

    float acc[4][4][4];
    #pragma unroll
    for (int i = 0; i < 4; i++)
        #pragma unroll
        for (int j = 0; j < 4; j++)
            #pragma unroll
            for (int q = 0; q < 4; q++) acc[i][j][q] = 0.f;

    const int lr = tid >> 2, slot = tid & 3;
    const __nv_bfloat16* aP[2];
    const __nv_bfloat16* wP[2];
    #pragma unroll
    for (int j = 0; j < 2; j++) {
        int r = lr + 64*j;
        int gr = m0 + r; if (gr >= M) gr = 0;
        long ab;
        if (mode == 0)      ab = (long)gr*MP_STRIDE;
        else if (mode == 1) ab = (long)(gr>>1)*MP_STRIDE + 1920 + (long)(gr&1)*1536;
        else                ab = (long)(gr>>1)*MP_STRIDE + 4992 + (long)(gr&1)*1152;
        aP[j] = g_mp_hi + ab + slot*8;
        int gn = n0 + r; if (gn >= N) gn = N-1;
        wP[j] = Whi + (long)gn*K + slot*8;
    }
    const long adel = (const __nv_bfloat16*)g_mp_lo - (const __nv_bfloat16*)g_mp_hi;
    const long wdel = Wlo - Whi;

    auto issue = [&](int c) {
        if (c < KC) {
            int k0 = c * 32;
            uint32_t st = smb + (c & 1) * K3_STG;
            #pragma unroll
            for (int j = 0; j < 2; j++) {
                uint32_t d = st + (lr + 64*j)*K3_ROWB + slot*16;
                cp16(d,         aP[j] + k0);
                cp16(d + 10240, aP[j] + adel + k0);
                cp16(d + 20480, wP[j] + k0);
                cp16(d + 30720, wP[j] + wdel + k0);
            }
        }
        asm volatile("cp.async.commit_group;" ::: "memory");
    };

    issue(0); issue(1);

    const int a_row = lane & 15, a_kh = lane >> 4;
    const int b_nl  = (lane & 7) | ((lane >> 4) << 3);
    const int b_kh  = (lane >> 3) & 1;

    for (int c = 0; c < KC; c++) {
        uint32_t st = smb + (c & 1) * K3_STG;
        asm volatile("cp.async.wait_group 1;" ::: "memory");
        __syncthreads();
        uint32_t aH = st +         (wm + a_row)*K3_ROWB + a_kh*16;
        uint32_t bH = st + 20480 + (wn + b_nl)*K3_ROWB + b_kh*16;
        #pragma unroll
        for (int ks = 0; ks < 2; ks++) {
            uint32_t af[4][4], bf[2][4], tb[2][4];
            #pragma unroll
            for (int mi = 0; mi < 4; mi++) ldm_x4(aH + ks*32 + mi*16*K3_ROWB, af[mi]);
            #pragma unroll
            for (int nf = 0; nf < 2; nf++) ldm_x4(bH + ks*32 + nf*16*K3_ROWB, bf[nf]);
            #pragma unroll
            for (int mi = 0; mi < 4; mi++)
                #pragma unroll
                for (int ni = 0; ni < 4; ni++)
                    mma16816(acc[mi][ni], af[mi], bf[ni>>1][(ni&1)*2], bf[ni>>1][(ni&1)*2+1]);
            #pragma unroll
            for (int nf = 0; nf < 2; nf++) ldm_x4(bH + 10240 + ks*32 + nf*16*K3_ROWB, tb[nf]);
            #pragma unroll
            for (int mi = 0; mi < 4; mi++)
                #pragma unroll
                for (int ni = 0; ni < 4; ni++)
                    mma16816(acc[mi][ni], af[mi], tb[ni>>1][(ni&1)*2], tb[ni>>1][(ni&1)*2+1]);
            #pragma unroll
            for (int mi = 0; mi < 4; mi++) ldm_x4(aH + 10240 + ks*32 + mi*16*K3_ROWB, af[mi]);
            #pragma unroll
            for (int mi = 0; mi < 4; mi++)
                #pragma unroll
                for (int ni = 0; ni < 4; ni++)
                    mma16816(acc[mi][ni], af[mi], bf[ni>>1][(ni&1)*2], bf[ni>>1][(ni&1)*2+1]);
        }
        __syncthreads();
        issue(c + 2);
    }

    int tg = lane >> 2, tig = lane & 3;
    #pragma unroll
    for (int mi = 0; mi < 4; mi++) {
        #pragma unroll
        for (int ni = 0; ni < 4; ni++) {
            int row = m0 + wm + 16*mi + tg;
            int col = n0 + wn + 8*ni + 2*tig;
            if (col < N) {
                float bx = 0.f, by = 0.f;
                if (mode == 0) { float2 bb = *(const float2*)(bias + col); bx = bb.x; by = bb.y; }
                if (row < M) {
                    float2 v = make_float2(acc[mi][ni][0] + bx, acc[mi][ni][1] + by);
                    *(float2*)(C + (long)row*N + col) = v;
                }
                if (row + 8 < M) {
                    float2 v = make_float2(acc[mi][ni][2] + bx, acc[mi][ni][3] + by);
                    *(float2*)(C + (long)(row+8)*N + col) = v;
                }
            }
        }
    }
}

// ---------------- K5a: recombine+gate + Wigner back -> g_full (bf16 split), 4 edges/block ----------------
__launch_bounds__(256)
__global__ void k5a_wback(const float* __restrict__ wig) {
    __shared__ float s_w [1900];
    __shared__ float s_hl[4864];
    int e0 = blockIdx.x * 4;
    int tid = threadIdx.x;

    for (int idx = tid; idx < 1900; idx += 256) {
        int e = idx / 475, rem = idx - e*475;
        int r = rem / 25, n = rem - r*25;
        s_w[idx] = wig[(long)(e0+e)*625 + c_MASK[r]*25 + n];
    }
    for (int idx = tid; idx < 4864; idx += 256) {
        int e = idx / 1216, rem = idx - e*1216;
        int j = rem >> 6, i = rem & 63;
        const float* x0 = g_x0  + (long)(e0+e)*X0_DIM;
        const float* y1 = g_ym1 + (long)(e0+e)*1024;
        const float* y2 = g_ym2 + (long)(e0+e)*768;
        float val;
        if (j < 5)        val = x0[768 + (j<<6) + i];
        else if (j < 9)  { int jj = j-5;  val = y1[jj*64 + i]       - y1[768 + jj*64 + i]; }
        else if (j < 13) { int jj = j-9;  val = y1[512 + jj*64 + i] + y1[256 + jj*64 + i]; }
        else if (j < 16) { int jj = j-13; val = y2[jj*64 + i]       - y2[576 + jj*64 + i]; }
        else             { int jj = j-16; val = y2[384 + jj*64 + i] + y2[192 + jj*64 + i]; }
        if (j == 0) {
            val = val * sigm(val);
        } else {
            float gsrc = x0[512 + (c_LPERM[j]-1)*64 + i];
            val *= sigm(gsrc);
        }
        s_hl[e*1216 + c_PERM[j]*64 + i] = val;
    }
    __syncthreads();
    for (int idx = tid; idx < 6400; idx += 256) {
        int e = idx / 1600, rem = idx - e*1600;
        int n = rem >> 6, i = rem & 63;
        float acc = 0.f;
        #pragma unroll
        for (int r = 0; r < 19; r++)
            acc += s_w[e*475 + r*25 + n] * s_hl[e*1216 + r*64 + i];
        long base = (long)e0*1600 + idx;
        __nv_bfloat16 h = __float2bfloat16(acc);
        g_full_hi[base] = h;
        g_full_lo[base] = __float2bfloat16(acc - __bfloat162float(h));
    }
}

// ---------------- K5b (merged per-l): projection GEMM out = full @ pw[l]^T (+pb at l=0) ----------------
// grid blocks: l=0:[0,79) l=1:[79,314) l=2:[314,705) l=3:[705,1252) l=4:[1252,1956)
#define K5B_GRID 1956

__launch_bounds__(256, 2)
__global__ void k5b_proj(const float* __restrict__ pb, float* __restrict__ out) {
    int id = blockIdx.x;
    int l, mb;
    if (id < 79)        { l = 0; mb = id; }
    else if (id < 314)  { l = 1; mb = id - 79; }
    else if (id < 705)  { l = 2; mb = id - 314; }
    else if (id < 1252) { l = 3; mb = id - 705; }
    else                { l = 4; mb = id - 1252; }
    const int nl = 2*l + 1;
    const int Ml = E_EDGES * nl;
    const int nstart = l*l;
    const int m0 = mb * 128;
    const int KC = 2;   // K = 64

    extern __shared__ char dsm[];
    const uint32_t smb = smem_u32(dsm);
    const int tid = threadIdx.x;
    const int wid = tid >> 5, lane = tid & 31;
    const int wm = (wid & 1) * 64;
    const int wn = (wid >> 1) * 32;

    float acc[4][4][4];
    #pragma unroll
    for (int i = 0; i < 4; i++)
        #pragma unroll
        for (int j = 0; j < 4; j++)
            #pragma unroll
            for (int q = 0; q < 4; q++) acc[i][j][q] = 0.f;

    const int lr = tid >> 2, slot = tid & 3;
    const __nv_bfloat16* aP[2];
    const __nv_bfloat16* wP[2];
    #pragma unroll
    for (int j = 0; j < 2; j++) {
        int gr = m0 + lr + 64*j; if (gr >= Ml) gr = 0;
        int e = gr / nl, r = gr - e*nl;
        aP[j] = g_full_hi + (long)e*1600 + (nstart + r)*64 + slot*8;
        int gn = lr + 64*j;   // 0..127 = output channel
        wP[j] = g_pw_hi + (long)l*8192 + (long)gn*64 + slot*8;
    }
    const long adel = (const __nv_bfloat16*)g_full_lo - (const __nv_bfloat16*)g_full_hi;
    const long wdel = (const __nv_bfloat16*)g_pw_lo   - (const __nv_bfloat16*)g_pw_hi;

    auto issue = [&](int c) {
        if (c < KC) {
            int k0 = c * 32;
            uint32_t st = smb + (c & 1) * K3_STG;
            #pragma unroll
            for (int j = 0; j < 2; j++) {
                uint32_t d = st + (lr + 64*j)*K3_ROWB + slot*16;
                cp16(d,         aP[j] + k0);
                cp16(d + 10240, aP[j] + adel + k0);
                cp16(d + 20480, wP[j] + k0);
                cp16(d + 30720, wP[j] + wdel + k0);
            }
        }
        asm volatile("cp.async.commit_group;" ::: "memory");
    };

    issue(0); issue(1);

    const int a_row = lane & 15, a_kh = lane >> 4;
    const int b_nl  = (lane & 7) | ((lane >> 4) << 3);
    const int b_kh  = (lane >> 3) & 1;

    for (int c = 0; c < KC; c++) {
        uint32_t st = smb + (c & 1) * K3_STG;
        asm volatile("cp.async.wait_group 1;" ::: "memory");
        __syncthreads();
        uint32_t aH = st +         (wm + a_row)*K3_ROWB + a_kh*16;
        uint32_t bH = st + 20480 + (wn + b_nl)*K3_ROWB + b_kh*16;
        #pragma unroll
        for (int ks = 0; ks < 2; ks++) {
            uint32_t af[4][4], bf[2][4], tb[2][4];
            #pragma unroll
            for (int mi = 0; mi < 4; mi++) ldm_x4(aH + ks*32 + mi*16*K3_ROWB, af[mi]);
            #pragma unroll
            for (int nf = 0; nf < 2; nf++) ldm_x4(bH + ks*32 + nf*16*K3_ROWB, bf[nf]);
            #pragma unroll
            for (int mi = 0; mi < 4; mi++)
                #pragma unroll
                for (int ni = 0; ni < 4; ni++)
                    mma16816(acc[mi][ni], af[mi], bf[ni>>1][(ni&1)*2], bf[ni>>1][(ni&1)*2+1]);
            #pragma unroll
            for (int nf = 0; nf < 2; nf++) ldm_x4(bH + 10240 + ks*32 + nf*16*K3_ROWB, tb[nf]);
            #pragma unroll
            for (int mi = 0; mi < 4; mi++)
                #pragma unroll
                for (int ni = 0; ni < 4; ni++)
                    mma16816(acc[mi][ni], af[mi], tb[ni>>1][(ni&1)*2], tb[ni>>1][(ni&1)*2+1]);
            #pragma unroll
            for (int mi = 0; mi < 4; mi++) ldm_x4(aH + 10240 + ks*32 + mi*16*K3_ROWB, af[mi]);
            #pragma unroll
            for (int mi = 0; mi < 4; mi++)
                #pragma unroll
                for (int ni = 0; ni < 4; ni++)
                    mma16816(acc[mi][ni], af[mi], bf[ni>>1][(ni&1)*2], bf[ni>>1][(ni&1)*2+1]);
        }
        __syncthreads();
        issue(c + 2);
    }

    int tg = lane >> 2, tig = lane & 3;
    #pragma unroll
    for (int mi = 0; mi < 4; mi++) {
        #pragma unroll
        for (int ni = 0; ni < 4; ni++) {
            int col = wn + 8*ni + 2*tig;
            float bx = 0.f, by = 0.f;
            if (l == 0) { float2 bb = *(const float2*)(pb + col); bx = bb.x; by = bb.y; }
            #pragma unroll
            for (int h = 0; h < 2; h++) {
                int row = m0 + wm + 16*mi + tg + 8*h;
                if (row < Ml) {
                    int e = row / nl, r = row - e*nl;
                    float2 v = make_float2(acc[mi][ni][2*h] + bx, acc[mi][ni][2*h+1] + by);
                    *(float2*)(out + (long)e*3200 + (nstart + r)*128 + col) = v;
                }
            }
        }
    }
}

// ---------------- launch ----------------
extern "C" void kernel_launch(void* const* d_in, const int* in_sizes, int n_in,
                              void* d_out, int out_size) {
    const float* x    = (const float*)d_in[0];
    const float* ef   = (const float*)d_in[1];
    const float* ed   = (const float*)d_in[2];
    const float* wig  = (const float*)d_in[3];
    const float* semb = (const float*)d_in[4];
    const float* temb = (const float*)d_in[5];
    const float* w1   = (const float*)d_in[6];
    const float* b1   = (const float*)d_in[7];
    const float* g1   = (const float*)d_in[8];
    const float* bb1  = (const float*)d_in[9];
    const float* w2   = (const float*)d_in[10];
    const float* b2   = (const float*)d_in[11];
    const float* g2   = (const float*)d_in[12];
    const float* bb2  = (const float*)d_in[13];
    const float* w3   = (const float*)d_in[14];
    const float* b3   = (const float*)d_in[15];
    const float* wm0  = (const float*)d_in[16];
    const float* bm0  = (const float*)d_in[17];
    const float* wm1  = (const float*)d_in[18];
    const float* wm2  = (const float*)d_in[19];
    const float* pw   = (const float*)d_in[20];
    const float* pb   = (const float*)d_in[21];
    const int*   an   = (const int*)d_in[22];
    const int*   ei   = (const int*)d_in[23];
    float* out = (float*)d_out;

    static bool attr_done = false;
    if (!attr_done) {
        cudaFuncSetAttribute(k3_all,   cudaFuncAttributeMaxDynamicSharedMemorySize, K3_DSMEM);
        cudaFuncSetAttribute(k1_gemm,  cudaFuncAttributeMaxDynamicSharedMemorySize, K3_DSMEM);
        cudaFuncSetAttribute(k5b_proj, cudaFuncAttributeMaxDynamicSharedMemorySize, K3_DSMEM);
        attr_done = true;
    }

    // launch 0: fused prelude (transposes + bf16 splits, incl. proj_w)
    k0_fused<<<14336, 256>>>(w1, w2, w3, wm0, wm1, wm2, pw);

    // launch 1: radial MLP layers 1-2
    k1_radial<<<E_EDGES/16, 256>>>(ed, semb, temb, b1, g1, bb1, b2, g2, bb2, an, ei);

    // launch 2: radial layer-3 GEMM on tensor cores
    k1_gemm<<<dim3(15, 79), 256, K3_DSMEM>>>(b3);

    // launch 3 (profiled): msg * w_rad + Wigner forward
    k2_wfwd<<<E_EDGES, 256>>>(x, ef, wig, ei);

    // launch 4: merged tensor-core GEMMs
    k3_all<<<K3_GRID, 256, K3_DSMEM>>>(bm0);

    // launch 5: recombine + Wigner back -> bf16 split full
    k5a_wback<<<E_EDGES/4, 256>>>(wig);

    // launch 6: projection GEMM (per-l merged)
    k5b_proj<<<K5B_GRID, 256, K3_DSMEM>>>(pb, out);
}

// round 14
// speedup vs baseline: 1.7608x; 1.1010x over previous
#include <cuda_runtime.h>
#include <cuda_bf16.h>
#include <cstdint>

// ---------------- problem constants ----------------
#define E_EDGES   10000
#define NRED      19
#define MP_STRIDE (NRED*384)   // 7296
#define X0_DIM    576          // only used columns of the m0 GEMM (512..1088 of original)

// ---------------- scratch (__device__ globals) ----------------
__device__ float g_w1T [384*128];
__device__ float g_w2T [128*128];
__device__ __nv_bfloat16 g_w3s_hi[1920*128];
__device__ __nv_bfloat16 g_w3s_lo[1920*128];
__device__ __nv_bfloat16 g_wm0_hi[1088*1920];
__device__ __nv_bfloat16 g_wm0_lo[1088*1920];
__device__ __nv_bfloat16 g_wm1_hi[512*1536];
__device__ __nv_bfloat16 g_wm1_lo[512*1536];
__device__ __nv_bfloat16 g_wm2_hi[384*1152];
__device__ __nv_bfloat16 g_wm2_lo[384*1152];
__device__ __nv_bfloat16 g_pw_hi[5*128*64];
__device__ __nv_bfloat16 g_pw_lo[5*128*64];
__device__ __nv_bfloat16 g_h2_hi[(long)E_EDGES*128];
__device__ __nv_bfloat16 g_h2_lo[(long)E_EDGES*128];
__device__ float g_wrad[(long)E_EDGES*1920];
__device__ __nv_bfloat16 g_mp_hi[(long)E_EDGES*MP_STRIDE];
__device__ __nv_bfloat16 g_mp_lo[(long)E_EDGES*MP_STRIDE];
__device__ float g_x0  [(long)E_EDGES*X0_DIM];
__device__ float g_ym1 [(long)E_EDGES*2*512];
__device__ float g_ym2 [(long)E_EDGES*2*384];
__device__ __nv_bfloat16 g_full_hi[(long)E_EDGES*1600];
__device__ __nv_bfloat16 g_full_lo[(long)E_EDGES*1600];

// permutation tables
__constant__ int c_MASKP[19] = {0,2,6,12,20, 3,7,13,21, 1,5,11,19, 8,14,22, 4,10,18};
__constant__ int c_MASK [19] = {0,1,2,3,4,5,6,7,8,10,11,12,13,14,18,19,20,21,22};
__constant__ int c_PERM [19] = {0,2,6,11,16, 3,7,12,17, 1,5,10,15, 8,13,18, 4,9,14};
__constant__ int c_LPERM[19] = {0,1,2,3,4, 1,2,3,4, 1,2,3,4, 2,3,4, 2,3,4};
__constant__ int c_LFULL[25] = {0,1,1,1,2,2,2,2,2,3,3,3,3,3,3,3,4,4,4,4,4,4,4,4,4};

__device__ __forceinline__ float sigm(float x){ return 1.f/(1.f+__expf(-x)); }

__device__ __forceinline__ uint32_t smem_u32(const void* p) {
    uint32_t a;
    asm("{ .reg .u64 t; cvta.to.shared.u64 t, %1; cvt.u32.u64 %0, t; }" : "=r"(a) : "l"(p));
    return a;
}
__device__ __forceinline__ void cp16(uint32_t dst, const void* src) {
    asm volatile("cp.async.cg.shared.global [%0], [%1], 16;" :: "r"(dst), "l"(src));
}
__device__ __forceinline__ void ldm_x4(uint32_t addr, uint32_t* r) {
    asm volatile("ldmatrix.sync.aligned.m8n8.x4.shared.b16 {%0,%1,%2,%3}, [%4];"
                 : "=r"(r[0]), "=r"(r[1]), "=r"(r[2]), "=r"(r[3]) : "r"(addr));
}
__device__ __forceinline__ void mma16816(float* d, const uint32_t* a, uint32_t b0, uint32_t b1) {
    asm volatile("mma.sync.aligned.m16n8k16.row.col.f32.bf16.bf16.f32 "
                 "{%0,%1,%2,%3}, {%4,%5,%6,%7}, {%8,%9}, {%0,%1,%2,%3};"
                 : "+f"(d[0]), "+f"(d[1]), "+f"(d[2]), "+f"(d[3])
                 : "r"(a[0]), "r"(a[1]), "r"(a[2]), "r"(a[3]), "r"(b0), "r"(b1));
}

// ---------------- K0 (fused): transposes + bf16 splits, single launch ----------------
__global__ void k0_fused(const float* __restrict__ w1, const float* __restrict__ w2,
                         const float* __restrict__ w3, const float* __restrict__ wm0,
                         const float* __restrict__ wm1, const float* __restrict__ wm2,
                         const float* __restrict__ pw) {
    long i = (long)blockIdx.x*256 + threadIdx.x;
    if (i < 49152) { int r = (int)(i/384), c = (int)(i%384); g_w1T[c*128+r] = w1[i]; return; }
    i -= 49152;
    if (i < 16384) { int r = (int)(i/128), c = (int)(i%128); g_w2T[c*128+r] = w2[i]; return; }
    i -= 16384;
    if (i < 245760) {
        float v = w3[i]; __nv_bfloat16 h = __float2bfloat16(v);
        g_w3s_hi[i] = h; g_w3s_lo[i] = __float2bfloat16(v - __bfloat162float(h));
        return;
    }
    i -= 245760;
    if (i < 1105920) {   // only rows 512..1088 of wm0 are live
        long ii = i + (long)512*1920;
        float v = wm0[ii]; __nv_bfloat16 h = __float2bfloat16(v);
        g_wm0_hi[ii] = h; g_wm0_lo[ii] = __float2bfloat16(v - __bfloat162float(h));
        return;
    }
    i -= 1105920;
    if (i < 786432) {
        float v = wm1[i]; __nv_bfloat16 h = __float2bfloat16(v);
        g_wm1_hi[i] = h; g_wm1_lo[i] = __float2bfloat16(v - __bfloat162float(h));
        return;
    }
    i -= 786432;
    if (i < 442368) {
        float v = wm2[i]; __nv_bfloat16 h = __float2bfloat16(v);
        g_wm2_hi[i] = h; g_wm2_lo[i] = __float2bfloat16(v - __bfloat162float(h));
        return;
    }
    i -= 442368;
    if (i < 40960) {
        float v = pw[i]; __nv_bfloat16 h = __float2bfloat16(v);
        g_pw_hi[i] = h; g_pw_lo[i] = __float2bfloat16(v - __bfloat162float(h));
    }
}

// ---------------- K1: radial MLP layers 1-2 (16 edges/block), h2 -> bf16 split ----------------
__device__ __forceinline__ void ln_silu16(float* buf, const float* __restrict__ g, const float* __restrict__ b) {
    int tid = threadIdx.x, w = tid >> 5, lane = tid & 31;
    for (int le = w; le < 16; le += 8) {
        float s = 0.f, s2 = 0.f;
        #pragma unroll
        for (int q = 0; q < 4; q++) { float v = buf[le*128 + lane + 32*q]; s += v; s2 += v*v; }
        #pragma unroll
        for (int off = 16; off > 0; off >>= 1) {
            s  += __shfl_xor_sync(0xffffffffu, s,  off);
            s2 += __shfl_xor_sync(0xffffffffu, s2, off);
        }
        float mu = s * (1.f/128.f);
        float var = s2 * (1.f/128.f) - mu*mu;
        float rstd = rsqrtf(var + 1e-5f);
        #pragma unroll
        for (int q = 0; q < 4; q++) {
            int oo = lane + 32*q;
            float v = buf[le*128 + oo];
            v = (v - mu)*rstd*g[oo] + b[oo];
            buf[le*128 + oo] = v * sigm(v);
        }
    }
}

__launch_bounds__(256)
__global__ void k1_radial(const float* __restrict__ ed,
                          const float* __restrict__ semb, const float* __restrict__ temb,
                          const float* __restrict__ b1, const float* __restrict__ g1, const float* __restrict__ bb1,
                          const float* __restrict__ b2, const float* __restrict__ g2, const float* __restrict__ bb2,
                          const int* __restrict__ an, const int* __restrict__ ei) {
    __shared__ float xe[16*384];
    __shared__ float h1[16*128];
    __shared__ float h2[16*128];
    int e0 = blockIdx.x * 16;
    int tid = threadIdx.x;

    for (int idx = tid; idx < 16*384; idx += 256) {
        int le = idx / 384, c = idx - le*384;
        int e = e0 + le;
        float v;
        if (c < 128)       v = ed[e*128 + c];
        else if (c < 256)  v = semb[an[ei[e]]*128 + (c-128)];
        else               v = temb[an[ei[E_EDGES + e]]*128 + (c-256)];
        xe[idx] = v;
    }
    __syncthreads();

    int o = tid & 127, hh = tid >> 7;
    {
        float acc[8]; float bv = b1[o];
        #pragma unroll
        for (int j = 0; j < 8; j++) acc[j] = bv;
        #pragma unroll 4
        for (int k = 0; k < 384; k++) {
            float wv = g_w1T[k*128 + o];
            #pragma unroll
            for (int j = 0; j < 8; j++) acc[j] += wv * xe[(hh*8+j)*384 + k];
        }
        #pragma unroll
        for (int j = 0; j < 8; j++) h1[(hh*8+j)*128 + o] = acc[j];
    }
    __syncthreads();
    ln_silu16(h1, g1, bb1);
    __syncthreads();
    {
        float acc[8]; float bv = b2[o];
        #pragma unroll
        for (int j = 0; j < 8; j++) acc[j] = bv;
        #pragma unroll 4
        for (int k = 0; k < 128; k++) {
            float wv = g_w2T[k*128 + o];
            #pragma unroll
            for (int j = 0; j < 8; j++) acc[j] += wv * h1[(hh*8+j)*128 + k];
        }
        #pragma unroll
        for (int j = 0; j < 8; j++) h2[(hh*8+j)*128 + o] = acc[j];
    }
    __syncthreads();
    ln_silu16(h2, g2, bb2);
    __syncthreads();
    for (int idx = tid; idx < 2048; idx += 256) {
        float v = h2[idx];
        long base = (long)e0*128 + idx;
        __nv_bfloat16 h = __float2bfloat16(v);
        g_h2_hi[base] = h;
        g_h2_lo[base] = __float2bfloat16(v - __bfloat162float(h));
    }
}

// ---------------- K1G: layer-3 GEMM  g_wrad = h2 @ w3^T + b3 (bf16x3 mma) ----------------
#define K3_ROWB   80
#define K3_STG    40960
#define K3_DSMEM  (2*K3_STG)   // 81920

__launch_bounds__(256, 2)
__global__ void k1_gemm(const float* __restrict__ bias) {
    const int N = 1920, K = 128, M = E_EDGES, KC = 4;
    extern __shared__ char dsm[];
    const uint32_t smb = smem_u32(dsm);
    const int tid = threadIdx.x;
    const int wid = tid >> 5, lane = tid & 31;
    const int n0 = blockIdx.x * 128;
    const int m0 = blockIdx.y * 128;
    const int wm = (wid & 1) * 64;
    const int wn = (wid >> 1) * 32;

    float acc[4][4][4];
    #pragma unroll
    for (int i = 0; i < 4; i++)
        #pragma unroll
        for (int j = 0; j < 4; j++)
            #pragma unroll
            for (int q = 0; q < 4; q++) acc[i][j][q] = 0.f;

    const int lr = tid >> 2, slot = tid & 3;
    const __nv_bfloat16* aP[2];
    const __nv_bfloat16* wP[2];
    #pragma unroll
    for (int j = 0; j < 2; j++) {
        int r = lr + 64*j;
        int gr = m0 + r; if (gr >= M) gr = 0;
        aP[j] = g_h2_hi + (long)gr*128 + slot*8;
        int gn = n0 + r;
        wP[j] = g_w3s_hi + (long)gn*K + slot*8;
    }
    const long adel = (const __nv_bfloat16*)g_h2_lo  - (const __nv_bfloat16*)g_h2_hi;
    const long wdel = (const __nv_bfloat16*)g_w3s_lo - (const __nv_bfloat16*)g_w3s_hi;

    auto issue = [&](int c) {
        if (c < KC) {
            int k0 = c * 32;
            uint32_t st = smb + (c & 1) * K3_STG;
            #pragma unroll
            for (int j = 0; j < 2; j++) {
                uint32_t d = st + (lr + 64*j)*K3_ROWB + slot*16;
                cp16(d,         aP[j] + k0);
                cp16(d + 10240, aP[j] + adel + k0);
                cp16(d + 20480, wP[j] + k0);
                cp16(d + 30720, wP[j] + wdel + k0);
            }
        }
        asm volatile("cp.async.commit_group;" ::: "memory");
    };

    issue(0); issue(1);

    const int a_row = lane & 15, a_kh = lane >> 4;
    const int b_nl  = (lane & 7) | ((lane >> 4) << 3);
    const int b_kh  = (lane >> 3) & 1;

    for (int c = 0; c < KC; c++) {
        uint32_t st = smb + (c & 1) * K3_STG;
        asm volatile("cp.async.wait_group 1;" ::: "memory");
        __syncthreads();
        uint32_t aH = st +         (wm + a_row)*K3_ROWB + a_kh*16;
        uint32_t bH = st + 20480 + (wn + b_nl)*K3_ROWB + b_kh*16;
        #pragma unroll
        for (int ks = 0; ks < 2; ks++) {
            uint32_t af[4][4], bf[2][4], tb[2][4];
            #pragma unroll
            for (int mi = 0; mi < 4; mi++) ldm_x4(aH + ks*32 + mi*16*K3_ROWB, af[mi]);
            #pragma unroll
            for (int nf = 0; nf < 2; nf++) ldm_x4(bH + ks*32 + nf*16*K3_ROWB, bf[nf]);
            #pragma unroll
            for (int mi = 0; mi < 4; mi++)
                #pragma unroll
                for (int ni = 0; ni < 4; ni++)
                    mma16816(acc[mi][ni], af[mi], bf[ni>>1][(ni&1)*2], bf[ni>>1][(ni&1)*2+1]);
            #pragma unroll
            for (int nf = 0; nf < 2; nf++) ldm_x4(bH + 10240 + ks*32 + nf*16*K3_ROWB, tb[nf]);
            #pragma unroll
            for (int mi = 0; mi < 4; mi++)
                #pragma unroll
                for (int ni = 0; ni < 4; ni++)
                    mma16816(acc[mi][ni], af[mi], tb[ni>>1][(ni&1)*2], tb[ni>>1][(ni&1)*2+1]);
            #pragma unroll
            for (int mi = 0; mi < 4; mi++) ldm_x4(aH + 10240 + ks*32 + mi*16*K3_ROWB, af[mi]);
            #pragma unroll
            for (int mi = 0; mi < 4; mi++)
                #pragma unroll
                for (int ni = 0; ni < 4; ni++)
                    mma16816(acc[mi][ni], af[mi], bf[ni>>1][(ni&1)*2], bf[ni>>1][(ni&1)*2+1]);
        }
        __syncthreads();
        issue(c + 2);
    }

    int tg = lane >> 2, tig = lane & 3;
    #pragma unroll
    for (int mi = 0; mi < 4; mi++) {
        #pragma unroll
        for (int ni = 0; ni < 4; ni++) {
            int row = m0 + wm + 16*mi + tg;
            int col = n0 + wn + 8*ni + 2*tig;
            float2 bb = *(const float2*)(bias + col);
            if (row < M) {
                float2 v = make_float2(acc[mi][ni][0] + bb.x, acc[mi][ni][1] + bb.y);
                *(float2*)(g_wrad + (long)row*N + col) = v;
            }
            if (row + 8 < M) {
                float2 v = make_float2(acc[mi][ni][2] + bb.x, acc[mi][ni][3] + bb.y);
                *(float2*)(g_wrad + (long)(row+8)*N + col) = v;
            }
        }
    }
}

// ---------------- K2: msg build * w_rad, Wigner fwd (8-j groups), bf16-split ----------------
__launch_bounds__(256)
__global__ void k2_wfwd(const float* __restrict__ x, const float* __restrict__ ef,
                        const float* __restrict__ wig, const int* __restrict__ ei) {
    __shared__ float msg[25*384];
    __shared__ float wp[24*25];   // rows 19..23 = zero pad
    int e = blockIdx.x, tid = threadIdx.x;
    int src = ei[e], tgt = ei[E_EDGES + e];

    for (int idx = tid; idx < 600; idx += 256) {
        int j = idx / 25, n = idx - j*25;
        wp[idx] = (j < 19) ? wig[(long)e*625 + c_MASKP[j]*25 + n] : 0.f;
    }
    const float4* x4  = (const float4*)x;
    const float4* ef4 = (const float4*)ef;
    const float4* wr4 = (const float4*)(g_wrad + (long)e*1920);
    float4* msg4 = (float4*)msg;
    for (int idx = tid; idx < 25*96; idx += 256) {
        int n = idx / 96, c4 = idx - n*96;
        float4 v;
        if (c4 < 32)      v = x4[(long)src*800 + n*32 + c4];
        else if (c4 < 64) v = x4[(long)tgt*800 + n*32 + (c4-32)];
        else              v = ef4[(long)e*800 + n*32 + (c4-64)];
        float4 w = wr4[c_LFULL[n]*96 + c4];
        v.x *= w.x; v.y *= w.y; v.z *= w.z; v.w *= w.w;
        msg4[idx] = v;
    }
    __syncthreads();

    // einsum: thread owns (c4, 8 consecutive j) -> 3 j-groups; msg float4 read once per 8 j's
    const float4* m4 = (const float4*)msg;
    for (int idx = tid; idx < 288; idx += 256) {
        int c4 = idx % 96, j0 = (idx / 96) * 8;
        float4 acc[8];
        #pragma unroll
        for (int jj = 0; jj < 8; jj++) acc[jj] = make_float4(0.f,0.f,0.f,0.f);
        #pragma unroll 5
        for (int n = 0; n < 25; n++) {
            float4 m = m4[n*96 + c4];
            #pragma unroll
            for (int jj = 0; jj < 8; jj++) {
                float w = wp[(j0+jj)*25 + n];
                acc[jj].x += w*m.x; acc[jj].y += w*m.y;
                acc[jj].z += w*m.z; acc[jj].w += w*m.w;
            }
        }
        #pragma unroll
        for (int jj = 0; jj < 8; jj++) {
            int j = j0 + jj;
            if (j < 19) {
                long base = (long)e*MP_STRIDE + (long)(j*96 + c4)*4;
                float4 a = acc[jj];
                __nv_bfloat16 h0 = __float2bfloat16(a.x);
                __nv_bfloat16 h1 = __float2bfloat16(a.y);
                __nv_bfloat16 h2 = __float2bfloat16(a.z);
                __nv_bfloat16 h3 = __float2bfloat16(a.w);
                __nv_bfloat162 hp0; hp0.x = h0; hp0.y = h1;
                __nv_bfloat162 hp1; hp1.x = h2; hp1.y = h3;
                ((__nv_bfloat162*)(g_mp_hi + base))[0] = hp0;
                ((__nv_bfloat162*)(g_mp_hi + base))[1] = hp1;
                __nv_bfloat162 lp0, lp1;
                lp0.x = __float2bfloat16(a.x - __bfloat162float(h0));
                lp0.y = __float2bfloat16(a.y - __bfloat162float(h1));
                lp1.x = __float2bfloat16(a.z - __bfloat162float(h2));
                lp1.y = __float2bfloat16(a.w - __bfloat162float(h3));
                ((__nv_bfloat162*)(g_mp_lo + base))[0] = lp0;
                ((__nv_bfloat162*)(g_mp_lo + base))[1] = lp1;
            }
        }
    }
}

// ---------------- K3 (merged): mma.sync bf16x3 GEMM, all 3 modes in one grid ----------------
// mode0 now only computes live columns 512..1088 (N=576, weight rows offset by 512).
// blocks: [0,395) mode0 (5 x 79), [395,1023) mode1 (4 x 157), [1023,1494) mode2 (3 x 157)
#define K3_GRID   1494

__launch_bounds__(256, 2)
__global__ void k3_all(const float* __restrict__ bias) {
    int id = blockIdx.x;
    int mode, nbx, mby;
    if (id < 395)       { mode = 0; nbx = id % 5;            mby = id / 5; }
    else if (id < 1023) { int t = id - 395;  mode = 1; nbx = t & 3; mby = t >> 2; }
    else                { int t = id - 1023; mode = 2; nbx = t % 3; mby = t / 3; }

    const int N  = (mode==0) ? 576  : (mode==1) ? 512 : 384;
    const int K  = (mode==0) ? 1920 : (mode==1) ? 1536 : 1152;
    const int M  = (mode==0) ? E_EDGES : 2*E_EDGES;
    const int KC = K >> 5;
    const __nv_bfloat16* __restrict__ Whi = (mode==0) ? g_wm0_hi + (long)512*1920 : (mode==1) ? g_wm1_hi : g_wm2_hi;
    const __nv_bfloat16* __restrict__ Wlo = (mode==0) ? g_wm0_lo + (long)512*1920 : (mode==1) ? g_wm1_lo : g_wm2_lo;
    float* __restrict__ C = (mode==0) ? g_x0 : (mode==1) ? g_ym1 : g_ym2;

    extern __shared__ char dsm[];
    const uint32_t smb = smem_u32(dsm);
    const int tid = threadIdx.x;
    const int wid = tid >> 5, lane = tid & 31;
    const int n0 = nbx * 128;
    const int m0 = mby * 128;
    const int wm = (wid & 1) * 64;
    const int wn = (wid >> 1) * 32;

    float acc[4][4][4];
    #pragma unroll
    for (int i = 0; i < 4; i++)
        #pragma unroll
        for (int j = 0; j < 4; j++)
            #pragma unroll
            for (int q = 0; q < 4; q++) acc[i][j][q] = 0.f;

    const int lr = tid >> 2, slot = tid & 3;
    const __nv_bfloat16* aP[2];
    const __nv_bfloat16* wP[2];
    #pragma unroll
    for (int j = 0; j < 2; j++) {
        int r = lr + 64*j;
        int gr = m0 + r; if (gr >= M) gr = 0;
        long ab;
        if (mode == 0)      ab = (long)gr*MP_STRIDE;
        else if (mode == 1) ab = (long)(gr>>1)*MP_STRIDE + 1920 + (long)(gr&1)*1536;
        else                ab = (long)(gr>>1)*MP_STRIDE + 4992 + (long)(gr&1)*1152;
        aP[j] = g_mp_hi + ab + slot*8;
        int gn = n0 + r; if (gn >= N) gn = N-1;
        wP[j] = Whi + (long)gn*K + slot*8;
    }
    const long adel = (const __nv_bfloat16*)g_mp_lo - (const __nv_bfloat16*)g_mp_hi;
    const long wdel = Wlo - Whi;

    auto issue = [&](int c) {
        if (c < KC) {
            int k0 = c * 32;
            uint32_t st = smb + (c & 1) * K3_STG;
            #pragma unroll
            for (int j = 0; j < 2; j++) {
                uint32_t d = st + (lr + 64*j)*K3_ROWB + slot*16;
                cp16(d,         aP[j] + k0);
                cp16(d + 10240, aP[j] + adel + k0);
                cp16(d + 20480, wP[j] + k0);
                cp16(d + 30720, wP[j] + wdel + k0);
            }
        }
        asm volatile("cp.async.commit_group;" ::: "memory");
    };

    issue(0); issue(1);

    const int a_row = lane & 15, a_kh = lane >> 4;
    const int b_nl  = (lane & 7) | ((lane >> 4) << 3);
    const int b_kh  = (lane >> 3) & 1;

    for (int c = 0; c < KC; c++) {
        uint32_t st = smb + (c & 1) * K3_STG;
        asm volatile("cp.async.wait_group 1;" ::: "memory");
        __syncthreads();
        uint32_t aH = st +         (wm + a_row)*K3_ROWB + a_kh*16;
        uint32_t bH = st + 20480 + (wn + b_nl)*K3_ROWB + b_kh*16;
        #pragma unroll
        for (int ks = 0; ks < 2; ks++) {
            uint32_t af[4][4], bf[2][4], tb[2][4];
            #pragma unroll
            for (int mi = 0; mi < 4; mi++) ldm_x4(aH + ks*32 + mi*16*K3_ROWB, af[mi]);
            #pragma unroll
            for (int nf = 0; nf < 2; nf++) ldm_x4(bH + ks*32 + nf*16*K3_ROWB, bf[nf]);
            #pragma unroll
            for (int mi = 0; mi < 4; mi++)
                #pragma unroll
                for (int ni = 0; ni < 4; ni++)
                    mma16816(acc[mi][ni], af[mi], bf[ni>>1][(ni&1)*2], bf[ni>>1][(ni&1)*2+1]);
            #pragma unroll
            for (int nf = 0; nf < 2; nf++) ldm_x4(bH + 10240 + ks*32 + nf*16*K3_ROWB, tb[nf]);
            #pragma unroll
            for (int mi = 0; mi < 4; mi++)
                #pragma unroll
                for (int ni = 0; ni < 4; ni++)
                    mma16816(acc[mi][ni], af[mi], tb[ni>>1][(ni&1)*2], tb[ni>>1][(ni&1)*2+1]);
            #pragma unroll
            for (int mi = 0; mi < 4; mi++) ldm_x4(aH + 10240 + ks*32 + mi*16*K3_ROWB, af[mi]);
            #pragma unroll
            for (int mi = 0; mi < 4; mi++)
                #pragma unroll
                for (int ni = 0; ni < 4; ni++)
                    mma16816(acc[mi][ni], af[mi], bf[ni>>1][(ni&1)*2], bf[ni>>1][(ni&1)*2+1]);
        }
        __syncthreads();
        issue(c + 2);
    }

    int tg = lane >> 2, tig = lane & 3;
    #pragma unroll
    for (int mi = 0; mi < 4; mi++) {
        #pragma unroll
        for (int ni = 0; ni < 4; ni++) {
            int row = m0 + wm + 16*mi + tg;
            int col = n0 + wn + 8*ni + 2*tig;
            if (col < N) {
                float bx = 0.f, by = 0.f;
                if (mode == 0) { float2 bb = *(const float2*)(bias + 512 + col); bx = bb.x; by = bb.y; }
                if (row < M) {
                    float2 v = make_float2(acc[mi][ni][0] + bx, acc[mi][ni][1] + by);
                    *(float2*)(C + (long)row*N + col) = v;
                }
                if (row + 8 < M) {
                    float2 v = make_float2(acc[mi][ni][2] + bx, acc[mi][ni][3] + by);
                    *(float2*)(C + (long)(row+8)*N + col) = v;
                }
            }
        }
    }
}

// ---------------- K5a: recombine+gate + Wigner back -> g_full (bf16 split), 4 edges/block ----------------
__launch_bounds__(256)
__global__ void k5a_wback(const float* __restrict__ wig) {
    __shared__ float s_w [1900];
    __shared__ float s_hl[4864];
    int e0 = blockIdx.x * 4;
    int tid = threadIdx.x;

    for (int idx = tid; idx < 1900; idx += 256) {
        int e = idx / 475, rem = idx - e*475;
        int r = rem / 25, n = rem - r*25;
        s_w[idx] = wig[(long)(e0+e)*625 + c_MASK[r]*25 + n];
    }
    for (int idx = tid; idx < 4864; idx += 256) {
        int e = idx / 1216, rem = idx - e*1216;
        int j = rem >> 6, i = rem & 63;
        const float* x0 = g_x0  + (long)(e0+e)*X0_DIM;   // cols = old 512..1088
        const float* y1 = g_ym1 + (long)(e0+e)*1024;
        const float* y2 = g_ym2 + (long)(e0+e)*768;
        float val;
        if (j < 5)        val = x0[256 + (j<<6) + i];
        else if (j < 9)  { int jj = j-5;  val = y1[jj*64 + i]       - y1[768 + jj*64 + i]; }
        else if (j < 13) { int jj = j-9;  val = y1[512 + jj*64 + i] + y1[256 + jj*64 + i]; }
        else if (j < 16) { int jj = j-13; val = y2[jj*64 + i]       - y2[576 + jj*64 + i]; }
        else             { int jj = j-16; val = y2[384 + jj*64 + i] + y2[192 + jj*64 + i]; }
        if (j == 0) {
            val = val * sigm(val);
        } else {
            float gsrc = x0[(c_LPERM[j]-1)*64 + i];
            val *= sigm(gsrc);
        }
        s_hl[e*1216 + c_PERM[j]*64 + i] = val;
    }
    __syncthreads();
    for (int idx = tid; idx < 6400; idx += 256) {
        int e = idx / 1600, rem = idx - e*1600;
        int n = rem >> 6, i = rem & 63;
        float acc = 0.f;
        #pragma unroll
        for (int r = 0; r < 19; r++)
            acc += s_w[e*475 + r*25 + n] * s_hl[e*1216 + r*64 + i];
        long base = (long)e0*1600 + idx;
        __nv_bfloat16 h = __float2bfloat16(acc);
        g_full_hi[base] = h;
        g_full_lo[base] = __float2bfloat16(acc - __bfloat162float(h));
    }
}

// ---------------- K5b (merged per-l): projection GEMM out = full @ pw[l]^T (+pb at l=0) ----------------
#define K5B_GRID 1956

__launch_bounds__(256, 2)
__global__ void k5b_proj(const float* __restrict__ pb, float* __restrict__ out) {
    int id = blockIdx.x;
    int l, mb;
    if (id < 79)        { l = 0; mb = id; }
    else if (id < 314)  { l = 1; mb = id - 79; }
    else if (id < 705)  { l = 2; mb = id - 314; }
    else if (id < 1252) { l = 3; mb = id - 705; }
    else                { l = 4; mb = id - 1252; }
    const int nl = 2*l + 1;
    const int Ml = E_EDGES * nl;
    const int nstart = l*l;
    const int m0 = mb * 128;
    const int KC = 2;   // K = 64

    extern __shared__ char dsm[];
    const uint32_t smb = smem_u32(dsm);
    const int tid = threadIdx.x;
    const int wid = tid >> 5, lane = tid & 31;
    const int wm = (wid & 1) * 64;
    const int wn = (wid >> 1) * 32;

    float acc[4][4][4];
    #pragma unroll
    for (int i = 0; i < 4; i++)
        #pragma unroll
        for (int j = 0; j < 4; j++)
            #pragma unroll
            for (int q = 0; q < 4; q++) acc[i][j][q] = 0.f;

    const int lr = tid >> 2, slot = tid & 3;
    const __nv_bfloat16* aP[2];
    const __nv_bfloat16* wP[2];
    #pragma unroll
    for (int j = 0; j < 2; j++) {
        int gr = m0 + lr + 64*j; if (gr >= Ml) gr = 0;
        int e = gr / nl, r = gr - e*nl;
        aP[j] = g_full_hi + (long)e*1600 + (nstart + r)*64 + slot*8;
        int gn = lr + 64*j;
        wP[j] = g_pw_hi + (long)l*8192 + (long)gn*64 + slot*8;
    }
    const long adel = (const __nv_bfloat16*)g_full_lo - (const __nv_bfloat16*)g_full_hi;
    const long wdel = (const __nv_bfloat16*)g_pw_lo   - (const __nv_bfloat16*)g_pw_hi;

    auto issue = [&](int c) {
        if (c < KC) {
            int k0 = c * 32;
            uint32_t st = smb + (c & 1) * K3_STG;
            #pragma unroll
            for (int j = 0; j < 2; j++) {
                uint32_t d = st + (lr + 64*j)*K3_ROWB + slot*16;
                cp16(d,         aP[j] + k0);
                cp16(d + 10240, aP[j] + adel + k0);
                cp16(d + 20480, wP[j] + k0);
                cp16(d + 30720, wP[j] + wdel + k0);
            }
        }
        asm volatile("cp.async.commit_group;" ::: "memory");
    };

    issue(0); issue(1);

    const int a_row = lane & 15, a_kh = lane >> 4;
    const int b_nl  = (lane & 7) | ((lane >> 4) << 3);
    const int b_kh  = (lane >> 3) & 1;

    for (int c = 0; c < KC; c++) {
        uint32_t st = smb + (c & 1) * K3_STG;
        asm volatile("cp.async.wait_group 1;" ::: "memory");
        __syncthreads();
        uint32_t aH = st +         (wm + a_row)*K3_ROWB + a_kh*16;
        uint32_t bH = st + 20480 + (wn + b_nl)*K3_ROWB + b_kh*16;
        #pragma unroll
        for (int ks = 0; ks < 2; ks++) {
            uint32_t af[4][4], bf[2][4], tb[2][4];
            #pragma unroll
            for (int mi = 0; mi < 4; mi++) ldm_x4(aH + ks*32 + mi*16*K3_ROWB, af[mi]);
            #pragma unroll
            for (int nf = 0; nf < 2; nf++) ldm_x4(bH + ks*32 + nf*16*K3_ROWB, bf[nf]);
            #pragma unroll
            for (int mi = 0; mi < 4; mi++)
                #pragma unroll
                for (int ni = 0; ni < 4; ni++)
                    mma16816(acc[mi][ni], af[mi], bf[ni>>1][(ni&1)*2], bf[ni>>1][(ni&1)*2+1]);
            #pragma unroll
            for (int nf = 0; nf < 2; nf++) ldm_x4(bH + 10240 + ks*32 + nf*16*K3_ROWB, tb[nf]);
            #pragma unroll
            for (int mi = 0; mi < 4; mi++)
                #pragma unroll
                for (int ni = 0; ni < 4; ni++)
                    mma16816(acc[mi][ni], af[mi], tb[ni>>1][(ni&1)*2], tb[ni>>1][(ni&1)*2+1]);
            #pragma unroll
            for (int mi = 0; mi < 4; mi++) ldm_x4(aH + 10240 + ks*32 + mi*16*K3_ROWB, af[mi]);
            #pragma unroll
            for (int mi = 0; mi < 4; mi++)
                #pragma unroll
                for (int ni = 0; ni < 4; ni++)
                    mma16816(acc[mi][ni], af[mi], bf[ni>>1][(ni&1)*2], bf[ni>>1][(ni&1)*2+1]);
        }
        __syncthreads();
        issue(c + 2);
    }

    int tg = lane >> 2, tig = lane & 3;
    #pragma unroll
    for (int mi = 0; mi < 4; mi++) {
        #pragma unroll
        for (int ni = 0; ni < 4; ni++) {
            int col = wn + 8*ni + 2*tig;
            float bx = 0.f, by = 0.f;
            if (l == 0) { float2 bb = *(const float2*)(pb + col); bx = bb.x; by = bb.y; }
            #pragma unroll
            for (int h = 0; h < 2; h++) {
                int row = m0 + wm + 16*mi + tg + 8*h;
                if (row < Ml) {
                    int e = row / nl, r = row - e*nl;
                    float2 v = make_float2(acc[mi][ni][2*h] + bx, acc[mi][ni][2*h+1] + by);
                    *(float2*)(out + (long)e*3200 + (nstart + r)*128 + col) = v;
                }
            }
        }
    }
}

// ---------------- launch ----------------
extern "C" void kernel_launch(void* const* d_in, const int* in_sizes, int n_in,
                              void* d_out, int out_size) {
    const float* x    = (const float*)d_in[0];
    const float* ef   = (const float*)d_in[1];
    const float* ed   = (const float*)d_in[2];
    const float* wig  = (const float*)d_in[3];
    const float* semb = (const float*)d_in[4];
    const float* temb = (const float*)d_in[5];
    const float* w1   = (const float*)d_in[6];
    const float* b1   = (const float*)d_in[7];
    const float* g1   = (const float*)d_in[8];
    const float* bb1  = (const float*)d_in[9];
    const float* w2   = (const float*)d_in[10];
    const float* b2   = (const float*)d_in[11];
    const float* g2   = (const float*)d_in[12];
    const float* bb2  = (const float*)d_in[13];
    const float* w3   = (const float*)d_in[14];
    const float* b3   = (const float*)d_in[15];
    const float* wm0  = (const float*)d_in[16];
    const float* bm0  = (const float*)d_in[17];
    const float* wm1  = (const float*)d_in[18];
    const float* wm2  = (const float*)d_in[19];
    const float* pw   = (const float*)d_in[20];
    const float* pb   = (const float*)d_in[21];
    const int*   an   = (const int*)d_in[22];
    const int*   ei   = (const int*)d_in[23];
    float* out = (float*)d_out;

    static bool attr_done = false;
    if (!attr_done) {
        cudaFuncSetAttribute(k3_all,   cudaFuncAttributeMaxDynamicSharedMemorySize, K3_DSMEM);
        cudaFuncSetAttribute(k1_gemm,  cudaFuncAttributeMaxDynamicSharedMemorySize, K3_DSMEM);
        cudaFuncSetAttribute(k5b_proj, cudaFuncAttributeMaxDynamicSharedMemorySize, K3_DSMEM);
        attr_done = true;
    }

    // launch 0: fused prelude (transposes + bf16 splits; wm0 live rows only)
    k0_fused<<<10496, 256>>>(w1, w2, w3, wm0, wm1, wm2, pw);

    // launch 1: radial MLP layers 1-2
    k1_radial<<<E_EDGES/16, 256>>>(ed, semb, temb, b1, g1, bb1, b2, g2, bb2, an, ei);

    // launch 2: radial layer-3 GEMM on tensor cores
    k1_gemm<<<dim3(15, 79), 256, K3_DSMEM>>>(b3);

    // launch 3 (profiled): msg * w_rad + Wigner forward
    k2_wfwd<<<E_EDGES, 256>>>(x, ef, wig, ei);

    // launch 4: merged tensor-core GEMMs (mode0 trimmed to live columns)
    k3_all<<<K3_GRID, 256, K3_DSMEM>>>(bm0);

    // launch 5: recombine + Wigner back -> bf16 split full
    k5a_wback<<<E_EDGES/4, 256>>>(wig);

    // launch 6: projection GEMM (per-l merged)
    k5b_proj<<<K5B_GRID, 256, K3_DSMEM>>>(pb, out);
}

// round 15
// speedup vs baseline: 1.8385x; 1.0441x over previous
#include <cuda_runtime.h>
#include <cuda_bf16.h>
#include <cstdint>

// ---------------- problem constants ----------------
#define E_EDGES   10000
#define NRED      19
#define MP_STRIDE (NRED*384)   // 7296
#define X0_DIM    576          // only used columns of the m0 GEMM (512..1088 of original)

// ---------------- scratch (__device__ globals) ----------------
__device__ float g_w1T [384*128];
__device__ float g_w2T [128*128];
__device__ __nv_bfloat16 g_w3s_hi[1920*128];
__device__ __nv_bfloat16 g_w3s_lo[1920*128];
__device__ __nv_bfloat16 g_wm0_hi[1088*1920];
__device__ __nv_bfloat16 g_wm0_lo[1088*1920];
__device__ __nv_bfloat16 g_wm1_hi[512*1536];
__device__ __nv_bfloat16 g_wm1_lo[512*1536];
__device__ __nv_bfloat16 g_wm2_hi[384*1152];
__device__ __nv_bfloat16 g_wm2_lo[384*1152];
__device__ __nv_bfloat16 g_pw_hi[5*128*64];
__device__ __nv_bfloat16 g_pw_lo[5*128*64];
__device__ __nv_bfloat16 g_h2_hi[(long)E_EDGES*128];
__device__ __nv_bfloat16 g_h2_lo[(long)E_EDGES*128];
__device__ float g_wrad[(long)E_EDGES*1920];
__device__ __nv_bfloat16 g_mp_hi[(long)E_EDGES*MP_STRIDE];
__device__ __nv_bfloat16 g_mp_lo[(long)E_EDGES*MP_STRIDE];
__device__ float g_x0  [(long)E_EDGES*X0_DIM];
__device__ float g_ym1 [(long)E_EDGES*2*512];
__device__ float g_ym2 [(long)E_EDGES*2*384];
__device__ __nv_bfloat16 g_full_hi[(long)E_EDGES*1600];
__device__ __nv_bfloat16 g_full_lo[(long)E_EDGES*1600];

// permutation tables
__constant__ int c_MASKP[19] = {0,2,6,12,20, 3,7,13,21, 1,5,11,19, 8,14,22, 4,10,18};
__constant__ int c_MASK [19] = {0,1,2,3,4,5,6,7,8,10,11,12,13,14,18,19,20,21,22};
__constant__ int c_PERM [19] = {0,2,6,11,16, 3,7,12,17, 1,5,10,15, 8,13,18, 4,9,14};
__constant__ int c_LPERM[19] = {0,1,2,3,4, 1,2,3,4, 1,2,3,4, 2,3,4, 2,3,4};
__constant__ int c_LFULL[25] = {0,1,1,1,2,2,2,2,2,3,3,3,3,3,3,3,4,4,4,4,4,4,4,4,4};

__device__ __forceinline__ float sigm(float x){ return 1.f/(1.f+__expf(-x)); }

__device__ __forceinline__ uint32_t smem_u32(const void* p) {
    uint32_t a;
    asm("{ .reg .u64 t; cvta.to.shared.u64 t, %1; cvt.u32.u64 %0, t; }" : "=r"(a) : "l"(p));
    return a;
}
__device__ __forceinline__ void cp16(uint32_t dst, const void* src) {
    asm volatile("cp.async.cg.shared.global [%0], [%1], 16;" :: "r"(dst), "l"(src));
}
__device__ __forceinline__ void ldm_x4(uint32_t addr, uint32_t* r) {
    asm volatile("ldmatrix.sync.aligned.m8n8.x4.shared.b16 {%0,%1,%2,%3}, [%4];"
                 : "=r"(r[0]), "=r"(r[1]), "=r"(r[2]), "=r"(r[3]) : "r"(addr));
}
__device__ __forceinline__ void mma16816(float* d, const uint32_t* a, uint32_t b0, uint32_t b1) {
    asm volatile("mma.sync.aligned.m16n8k16.row.col.f32.bf16.bf16.f32 "
                 "{%0,%1,%2,%3}, {%4,%5,%6,%7}, {%8,%9}, {%0,%1,%2,%3};"
                 : "+f"(d[0]), "+f"(d[1]), "+f"(d[2]), "+f"(d[3])
                 : "r"(a[0]), "r"(a[1]), "r"(a[2]), "r"(a[3]), "r"(b0), "r"(b1));
}

// ---------------- K0 (fused): transposes + bf16 splits, single launch ----------------
__global__ void k0_fused(const float* __restrict__ w1, const float* __restrict__ w2,
                         const float* __restrict__ w3, const float* __restrict__ wm0,
                         const float* __restrict__ wm1, const float* __restrict__ wm2,
                         const float* __restrict__ pw) {
    long i = (long)blockIdx.x*256 + threadIdx.x;
    if (i < 49152) { int r = (int)(i/384), c = (int)(i%384); g_w1T[c*128+r] = w1[i]; return; }
    i -= 49152;
    if (i < 16384) { int r = (int)(i/128), c = (int)(i%128); g_w2T[c*128+r] = w2[i]; return; }
    i -= 16384;
    if (i < 245760) {
        float v = w3[i]; __nv_bfloat16 h = __float2bfloat16(v);
        g_w3s_hi[i] = h; g_w3s_lo[i] = __float2bfloat16(v - __bfloat162float(h));
        return;
    }
    i -= 245760;
    if (i < 1105920) {   // only rows 512..1088 of wm0 are live
        long ii = i + (long)512*1920;
        float v = wm0[ii]; __nv_bfloat16 h = __float2bfloat16(v);
        g_wm0_hi[ii] = h; g_wm0_lo[ii] = __float2bfloat16(v - __bfloat162float(h));
        return;
    }
    i -= 1105920;
    if (i < 786432) {
        float v = wm1[i]; __nv_bfloat16 h = __float2bfloat16(v);
        g_wm1_hi[i] = h; g_wm1_lo[i] = __float2bfloat16(v - __bfloat162float(h));
        return;
    }
    i -= 786432;
    if (i < 442368) {
        float v = wm2[i]; __nv_bfloat16 h = __float2bfloat16(v);
        g_wm2_hi[i] = h; g_wm2_lo[i] = __float2bfloat16(v - __bfloat162float(h));
        return;
    }
    i -= 442368;
    if (i < 40960) {
        float v = pw[i]; __nv_bfloat16 h = __float2bfloat16(v);
        g_pw_hi[i] = h; g_pw_lo[i] = __float2bfloat16(v - __bfloat162float(h));
    }
}

// ---------------- K1: radial MLP layers 1-2 (16 edges/block), h2 -> bf16 split ----------------
__device__ __forceinline__ void ln_silu16(float* buf, const float* __restrict__ g, const float* __restrict__ b) {
    int tid = threadIdx.x, w = tid >> 5, lane = tid & 31;
    for (int le = w; le < 16; le += 8) {
        float s = 0.f, s2 = 0.f;
        #pragma unroll
        for (int q = 0; q < 4; q++) { float v = buf[le*128 + lane + 32*q]; s += v; s2 += v*v; }
        #pragma unroll
        for (int off = 16; off > 0; off >>= 1) {
            s  += __shfl_xor_sync(0xffffffffu, s,  off);
            s2 += __shfl_xor_sync(0xffffffffu, s2, off);
        }
        float mu = s * (1.f/128.f);
        float var = s2 * (1.f/128.f) - mu*mu;
        float rstd = rsqrtf(var + 1e-5f);
        #pragma unroll
        for (int q = 0; q < 4; q++) {
            int oo = lane + 32*q;
            float v = buf[le*128 + oo];
            v = (v - mu)*rstd*g[oo] + b[oo];
            buf[le*128 + oo] = v * sigm(v);
        }
    }
}

__launch_bounds__(256)
__global__ void k1_radial(const float* __restrict__ ed,
                          const float* __restrict__ semb, const float* __restrict__ temb,
                          const float* __restrict__ b1, const float* __restrict__ g1, const float* __restrict__ bb1,
                          const float* __restrict__ b2, const float* __restrict__ g2, const float* __restrict__ bb2,
                          const int* __restrict__ an, const int* __restrict__ ei) {
    __shared__ float xe[16*384];
    __shared__ float h1[16*128];
    __shared__ float h2[16*128];
    int e0 = blockIdx.x * 16;
    int tid = threadIdx.x;

    for (int idx = tid; idx < 16*384; idx += 256) {
        int le = idx / 384, c = idx - le*384;
        int e = e0 + le;
        float v;
        if (c < 128)       v = ed[e*128 + c];
        else if (c < 256)  v = semb[an[ei[e]]*128 + (c-128)];
        else               v = temb[an[ei[E_EDGES + e]]*128 + (c-256)];
        xe[idx] = v;
    }
    __syncthreads();

    int o = tid & 127, hh = tid >> 7;
    {
        float acc[8]; float bv = b1[o];
        #pragma unroll
        for (int j = 0; j < 8; j++) acc[j] = bv;
        #pragma unroll 4
        for (int k = 0; k < 384; k++) {
            float wv = g_w1T[k*128 + o];
            #pragma unroll
            for (int j = 0; j < 8; j++) acc[j] += wv * xe[(hh*8+j)*384 + k];
        }
        #pragma unroll
        for (int j = 0; j < 8; j++) h1[(hh*8+j)*128 + o] = acc[j];
    }
    __syncthreads();
    ln_silu16(h1, g1, bb1);
    __syncthreads();
    {
        float acc[8]; float bv = b2[o];
        #pragma unroll
        for (int j = 0; j < 8; j++) acc[j] = bv;
        #pragma unroll 4
        for (int k = 0; k < 128; k++) {
            float wv = g_w2T[k*128 + o];
            #pragma unroll
            for (int j = 0; j < 8; j++) acc[j] += wv * h1[(hh*8+j)*128 + k];
        }
        #pragma unroll
        for (int j = 0; j < 8; j++) h2[(hh*8+j)*128 + o] = acc[j];
    }
    __syncthreads();
    ln_silu16(h2, g2, bb2);
    __syncthreads();
    for (int idx = tid; idx < 2048; idx += 256) {
        float v = h2[idx];
        long base = (long)e0*128 + idx;
        __nv_bfloat16 h = __float2bfloat16(v);
        g_h2_hi[base] = h;
        g_h2_lo[base] = __float2bfloat16(v - __bfloat162float(h));
    }
}

// ---------------- K1G: layer-3 GEMM  g_wrad = h2 @ w3^T + b3 (bf16x3 mma) ----------------
#define K3_ROWB   80
#define K3_STG    40960
#define K3_DSMEM  (2*K3_STG)   // 81920

__launch_bounds__(256, 2)
__global__ void k1_gemm(const float* __restrict__ bias) {
    const int N = 1920, K = 128, M = E_EDGES, KC = 4;
    extern __shared__ char dsm[];
    const uint32_t smb = smem_u32(dsm);
    const int tid = threadIdx.x;
    const int wid = tid >> 5, lane = tid & 31;
    const int n0 = blockIdx.x * 128;
    const int m0 = blockIdx.y * 128;
    const int wm = (wid & 1) * 64;
    const int wn = (wid >> 1) * 32;

    float acc[4][4][4];
    #pragma unroll
    for (int i = 0; i < 4; i++)
        #pragma unroll
        for (int j = 0; j < 4; j++)
            #pragma unroll
            for (int q = 0; q < 4; q++) acc[i][j][q] = 0.f;

    const int lr = tid >> 2, slot = tid & 3;
    const __nv_bfloat16* aP[2];
    const __nv_bfloat16* wP[2];
    #pragma unroll
    for (int j = 0; j < 2; j++) {
        int r = lr + 64*j;
        int gr = m0 + r; if (gr >= M) gr = 0;
        aP[j] = g_h2_hi + (long)gr*128 + slot*8;
        int gn = n0 + r;
        wP[j] = g_w3s_hi + (long)gn*K + slot*8;
    }
    const long adel = (const __nv_bfloat16*)g_h2_lo  - (const __nv_bfloat16*)g_h2_hi;
    const long wdel = (const __nv_bfloat16*)g_w3s_lo - (const __nv_bfloat16*)g_w3s_hi;

    auto issue = [&](int c) {
        if (c < KC) {
            int k0 = c * 32;
            uint32_t st = smb + (c & 1) * K3_STG;
            #pragma unroll
            for (int j = 0; j < 2; j++) {
                uint32_t d = st + (lr + 64*j)*K3_ROWB + slot*16;
                cp16(d,         aP[j] + k0);
                cp16(d + 10240, aP[j] + adel + k0);
                cp16(d + 20480, wP[j] + k0);
                cp16(d + 30720, wP[j] + wdel + k0);
            }
        }
        asm volatile("cp.async.commit_group;" ::: "memory");
    };

    issue(0); issue(1);

    const int a_row = lane & 15, a_kh = lane >> 4;
    const int b_nl  = (lane & 7) | ((lane >> 4) << 3);
    const int b_kh  = (lane >> 3) & 1;

    for (int c = 0; c < KC; c++) {
        uint32_t st = smb + (c & 1) * K3_STG;
        asm volatile("cp.async.wait_group 1;" ::: "memory");
        __syncthreads();
        uint32_t aH = st +         (wm + a_row)*K3_ROWB + a_kh*16;
        uint32_t bH = st + 20480 + (wn + b_nl)*K3_ROWB + b_kh*16;
        #pragma unroll
        for (int ks = 0; ks < 2; ks++) {
            uint32_t af[4][4], bf[2][4], tb[2][4];
            #pragma unroll
            for (int mi = 0; mi < 4; mi++) ldm_x4(aH + ks*32 + mi*16*K3_ROWB, af[mi]);
            #pragma unroll
            for (int nf = 0; nf < 2; nf++) ldm_x4(bH + ks*32 + nf*16*K3_ROWB, bf[nf]);
            #pragma unroll
            for (int mi = 0; mi < 4; mi++)
                #pragma unroll
                for (int ni = 0; ni < 4; ni++)
                    mma16816(acc[mi][ni], af[mi], bf[ni>>1][(ni&1)*2], bf[ni>>1][(ni&1)*2+1]);
            #pragma unroll
            for (int nf = 0; nf < 2; nf++) ldm_x4(bH + 10240 + ks*32 + nf*16*K3_ROWB, tb[nf]);
            #pragma unroll
            for (int mi = 0; mi < 4; mi++)
                #pragma unroll
                for (int ni = 0; ni < 4; ni++)
                    mma16816(acc[mi][ni], af[mi], tb[ni>>1][(ni&1)*2], tb[ni>>1][(ni&1)*2+1]);
            #pragma unroll
            for (int mi = 0; mi < 4; mi++) ldm_x4(aH + 10240 + ks*32 + mi*16*K3_ROWB, af[mi]);
            #pragma unroll
            for (int mi = 0; mi < 4; mi++)
                #pragma unroll
                for (int ni = 0; ni < 4; ni++)
                    mma16816(acc[mi][ni], af[mi], bf[ni>>1][(ni&1)*2], bf[ni>>1][(ni&1)*2+1]);
        }
        __syncthreads();
        issue(c + 2);
    }

    int tg = lane >> 2, tig = lane & 3;
    #pragma unroll
    for (int mi = 0; mi < 4; mi++) {
        #pragma unroll
        for (int ni = 0; ni < 4; ni++) {
            int row = m0 + wm + 16*mi + tg;
            int col = n0 + wn + 8*ni + 2*tig;
            float2 bb = *(const float2*)(bias + col);
            if (row < M) {
                float2 v = make_float2(acc[mi][ni][0] + bb.x, acc[mi][ni][1] + bb.y);
                *(float2*)(g_wrad + (long)row*N + col) = v;
            }
            if (row + 8 < M) {
                float2 v = make_float2(acc[mi][ni][2] + bb.x, acc[mi][ni][3] + bb.y);
                *(float2*)(g_wrad + (long)(row+8)*N + col) = v;
            }
        }
    }
}

// ---------------- K2: msg build * w_rad, Wigner fwd (4-j groups), bf16-split ----------------
__launch_bounds__(256)
__global__ void k2_wfwd(const float* __restrict__ x, const float* __restrict__ ef,
                        const float* __restrict__ wig, const int* __restrict__ ei) {
    __shared__ float msg[25*384];
    __shared__ float wp[20*25];   // row 19 = zero pad
    int e = blockIdx.x, tid = threadIdx.x;
    int src = ei[e], tgt = ei[E_EDGES + e];

    for (int idx = tid; idx < 500; idx += 256) {
        int j = idx / 25, n = idx - j*25;
        wp[idx] = (j < 19) ? wig[(long)e*625 + c_MASKP[j]*25 + n] : 0.f;
    }
    const float4* x4  = (const float4*)x;
    const float4* ef4 = (const float4*)ef;
    const float4* wr4 = (const float4*)(g_wrad + (long)e*1920);
    float4* msg4 = (float4*)msg;
    for (int idx = tid; idx < 25*96; idx += 256) {
        int n = idx / 96, c4 = idx - n*96;
        float4 v;
        if (c4 < 32)      v = x4[(long)src*800 + n*32 + c4];
        else if (c4 < 64) v = x4[(long)tgt*800 + n*32 + (c4-32)];
        else              v = ef4[(long)e*800 + n*32 + (c4-64)];
        float4 w = wr4[c_LFULL[n]*96 + c4];
        v.x *= w.x; v.y *= w.y; v.z *= w.z; v.w *= w.w;
        msg4[idx] = v;
    }
    __syncthreads();

    const float4* m4 = (const float4*)msg;
    for (int idx = tid; idx < 480; idx += 256) {
        int c4 = idx % 96, j0 = (idx / 96) * 4;
        float4 acc[4];
        #pragma unroll
        for (int jj = 0; jj < 4; jj++) acc[jj] = make_float4(0.f,0.f,0.f,0.f);
        #pragma unroll 5
        for (int n = 0; n < 25; n++) {
            float4 m = m4[n*96 + c4];
            #pragma unroll
            for (int jj = 0; jj < 4; jj++) {
                float w = wp[(j0+jj)*25 + n];
                acc[jj].x += w*m.x; acc[jj].y += w*m.y;
                acc[jj].z += w*m.z; acc[jj].w += w*m.w;
            }
        }
        #pragma unroll
        for (int jj = 0; jj < 4; jj++) {
            int j = j0 + jj;
            if (j < 19) {
                long base = (long)e*MP_STRIDE + (long)(j*96 + c4)*4;
                float4 a = acc[jj];
                __nv_bfloat16 h0 = __float2bfloat16(a.x);
                __nv_bfloat16 h1 = __float2bfloat16(a.y);
                __nv_bfloat16 h2 = __float2bfloat16(a.z);
                __nv_bfloat16 h3 = __float2bfloat16(a.w);
                __nv_bfloat162 hp0; hp0.x = h0; hp0.y = h1;
                __nv_bfloat162 hp1; hp1.x = h2; hp1.y = h3;
                ((__nv_bfloat162*)(g_mp_hi + base))[0] = hp0;
                ((__nv_bfloat162*)(g_mp_hi + base))[1] = hp1;
                __nv_bfloat162 lp0, lp1;
                lp0.x = __float2bfloat16(a.x - __bfloat162float(h0));
                lp0.y = __float2bfloat16(a.y - __bfloat162float(h1));
                lp1.x = __float2bfloat16(a.z - __bfloat162float(h2));
                lp1.y = __float2bfloat16(a.w - __bfloat162float(h3));
                ((__nv_bfloat162*)(g_mp_lo + base))[0] = lp0;
                ((__nv_bfloat162*)(g_mp_lo + base))[1] = lp1;
            }
        }
    }
}

// ---------------- K3 (merged): mma.sync bf16x3 GEMM, all 3 modes in one grid ----------------
// mode0 only computes live columns 512..1088 (N=576, weight rows offset by 512).
#define K3_GRID   1494

__launch_bounds__(256, 2)
__global__ void k3_all(const float* __restrict__ bias) {
    int id = blockIdx.x;
    int mode, nbx, mby;
    if (id < 395)       { mode = 0; nbx = id % 5;            mby = id / 5; }
    else if (id < 1023) { int t = id - 395;  mode = 1; nbx = t & 3; mby = t >> 2; }
    else                { int t = id - 1023; mode = 2; nbx = t % 3; mby = t / 3; }

    const int N  = (mode==0) ? 576  : (mode==1) ? 512 : 384;
    const int K  = (mode==0) ? 1920 : (mode==1) ? 1536 : 1152;
    const int M  = (mode==0) ? E_EDGES : 2*E_EDGES;
    const int KC = K >> 5;
    const __nv_bfloat16* __restrict__ Whi = (mode==0) ? g_wm0_hi + (long)512*1920 : (mode==1) ? g_wm1_hi : g_wm2_hi;
    const __nv_bfloat16* __restrict__ Wlo = (mode==0) ? g_wm0_lo + (long)512*1920 : (mode==1) ? g_wm1_lo : g_wm2_lo;
    float* __restrict__ C = (mode==0) ? g_x0 : (mode==1) ? g_ym1 : g_ym2;

    extern __shared__ char dsm[];
    const uint32_t smb = smem_u32(dsm);
    const int tid = threadIdx.x;
    const int wid = tid >> 5, lane = tid & 31;
    const int n0 = nbx * 128;
    const int m0 = mby * 128;
    const int wm = (wid & 1) * 64;
    const int wn = (wid >> 1) * 32;

    float acc[4][4][4];
    #pragma unroll
    for (int i = 0; i < 4; i++)
        #pragma unroll
        for (int j = 0; j < 4; j++)
            #pragma unroll
            for (int q = 0; q < 4; q++) acc[i][j][q] = 0.f;

    const int lr = tid >> 2, slot = tid & 3;
    const __nv_bfloat16* aP[2];
    const __nv_bfloat16* wP[2];
    #pragma unroll
    for (int j = 0; j < 2; j++) {
        int r = lr + 64*j;
        int gr = m0 + r; if (gr >= M) gr = 0;
        long ab;
        if (mode == 0)      ab = (long)gr*MP_STRIDE;
        else if (mode == 1) ab = (long)(gr>>1)*MP_STRIDE + 1920 + (long)(gr&1)*1536;
        else                ab = (long)(gr>>1)*MP_STRIDE + 4992 + (long)(gr&1)*1152;
        aP[j] = g_mp_hi + ab + slot*8;
        int gn = n0 + r; if (gn >= N) gn = N-1;
        wP[j] = Whi + (long)gn*K + slot*8;
    }
    const long adel = (const __nv_bfloat16*)g_mp_lo - (const __nv_bfloat16*)g_mp_hi;
    const long wdel = Wlo - Whi;

    auto issue = [&](int c) {
        if (c < KC) {
            int k0 = c * 32;
            uint32_t st = smb + (c & 1) * K3_STG;
            #pragma unroll
            for (int j = 0; j < 2; j++) {
                uint32_t d = st + (lr + 64*j)*K3_ROWB + slot*16;
                cp16(d,         aP[j] + k0);
                cp16(d + 10240, aP[j] + adel + k0);
                cp16(d + 20480, wP[j] + k0);
                cp16(d + 30720, wP[j] + wdel + k0);
            }
        }
        asm volatile("cp.async.commit_group;" ::: "memory");
    };

    issue(0); issue(1);

    const int a_row = lane & 15, a_kh = lane >> 4;
    const int b_nl  = (lane & 7) | ((lane >> 4) << 3);
    const int b_kh  = (lane >> 3) & 1;

    for (int c = 0; c < KC; c++) {
        uint32_t st = smb + (c & 1) * K3_STG;
        asm volatile("cp.async.wait_group 1;" ::: "memory");
        __syncthreads();
        uint32_t aH = st +         (wm + a_row)*K3_ROWB + a_kh*16;
        uint32_t bH = st + 20480 + (wn + b_nl)*K3_ROWB + b_kh*16;
        #pragma unroll
        for (int ks = 0; ks < 2; ks++) {
            uint32_t af[4][4], bf[2][4], tb[2][4];
            #pragma unroll
            for (int mi = 0; mi < 4; mi++) ldm_x4(aH + ks*32 + mi*16*K3_ROWB, af[mi]);
            #pragma unroll
            for (int nf = 0; nf < 2; nf++) ldm_x4(bH + ks*32 + nf*16*K3_ROWB, bf[nf]);
            #pragma unroll
            for (int mi = 0; mi < 4; mi++)
                #pragma unroll
                for (int ni = 0; ni < 4; ni++)
                    mma16816(acc[mi][ni], af[mi], bf[ni>>1][(ni&1)*2], bf[ni>>1][(ni&1)*2+1]);
            #pragma unroll
            for (int nf = 0; nf < 2; nf++) ldm_x4(bH + 10240 + ks*32 + nf*16*K3_ROWB, tb[nf]);
            #pragma unroll
            for (int mi = 0; mi < 4; mi++)
                #pragma unroll
                for (int ni = 0; ni < 4; ni++)
                    mma16816(acc[mi][ni], af[mi], tb[ni>>1][(ni&1)*2], tb[ni>>1][(ni&1)*2+1]);
            #pragma unroll
            for (int mi = 0; mi < 4; mi++) ldm_x4(aH + 10240 + ks*32 + mi*16*K3_ROWB, af[mi]);
            #pragma unroll
            for (int mi = 0; mi < 4; mi++)
                #pragma unroll
                for (int ni = 0; ni < 4; ni++)
                    mma16816(acc[mi][ni], af[mi], bf[ni>>1][(ni&1)*2], bf[ni>>1][(ni&1)*2+1]);
        }
        __syncthreads();
        issue(c + 2);
    }

    int tg = lane >> 2, tig = lane & 3;
    #pragma unroll
    for (int mi = 0; mi < 4; mi++) {
        #pragma unroll
        for (int ni = 0; ni < 4; ni++) {
            int row = m0 + wm + 16*mi + tg;
            int col = n0 + wn + 8*ni + 2*tig;
            if (col < N) {
                float bx = 0.f, by = 0.f;
                if (mode == 0) { float2 bb = *(const float2*)(bias + 512 + col); bx = bb.x; by = bb.y; }
                if (row < M) {
                    float2 v = make_float2(acc[mi][ni][0] + bx, acc[mi][ni][1] + by);
                    *(float2*)(C + (long)row*N + col) = v;
                }
                if (row + 8 < M) {
                    float2 v = make_float2(acc[mi][ni][2] + bx, acc[mi][ni][3] + by);
                    *(float2*)(C + (long)(row+8)*N + col) = v;
                }
            }
        }
    }
}

// ---------------- K5a: recombine+gate + Wigner back -> g_full (bf16 split), 4 edges/block ----------------
__launch_bounds__(256)
__global__ void k5a_wback(const float* __restrict__ wig) {
    __shared__ float s_w [1900];
    __shared__ float s_hl[4864];
    int e0 = blockIdx.x * 4;
    int tid = threadIdx.x;

    for (int idx = tid; idx < 1900; idx += 256) {
        int e = idx / 475, rem = idx - e*475;
        int r = rem / 25, n = rem - r*25;
        s_w[idx] = wig[(long)(e0+e)*625 + c_MASK[r]*25 + n];
    }
    for (int idx = tid; idx < 4864; idx += 256) {
        int e = idx / 1216, rem = idx - e*1216;
        int j = rem >> 6, i = rem & 63;
        const float* x0 = g_x0  + (long)(e0+e)*X0_DIM;   // cols = old 512..1088
        const float* y1 = g_ym1 + (long)(e0+e)*1024;
        const float* y2 = g_ym2 + (long)(e0+e)*768;
        float val;
        if (j < 5)        val = x0[256 + (j<<6) + i];
        else if (j < 9)  { int jj = j-5;  val = y1[jj*64 + i]       - y1[768 + jj*64 + i]; }
        else if (j < 13) { int jj = j-9;  val = y1[512 + jj*64 + i] + y1[256 + jj*64 + i]; }
        else if (j < 16) { int jj = j-13; val = y2[jj*64 + i]       - y2[576 + jj*64 + i]; }
        else             { int jj = j-16; val = y2[384 + jj*64 + i] + y2[192 + jj*64 + i]; }
        if (j == 0) {
            val = val * sigm(val);
        } else {
            float gsrc = x0[(c_LPERM[j]-1)*64 + i];
            val *= sigm(gsrc);
        }
        s_hl[e*1216 + c_PERM[j]*64 + i] = val;
    }
    __syncthreads();
    // einsum: thread owns (e, n, i-quad): 1 broadcast s_w read + 1 LDS.128 per 4 FFMA
    for (int idx = tid; idx < 1600; idx += 256) {
        int e = idx / 400, rem = idx - e*400;
        int n = rem >> 4, q = rem & 15;
        float4 acc = make_float4(0.f,0.f,0.f,0.f);
        const float* hlb = &s_hl[e*1216 + q*4];
        const float* wb  = &s_w[e*475 + n];
        #pragma unroll
        for (int r = 0; r < 19; r++) {
            float w = wb[r*25];
            float4 f = *(const float4*)(hlb + r*64);
            acc.x += w*f.x; acc.y += w*f.y; acc.z += w*f.z; acc.w += w*f.w;
        }
        long base = (long)e0*1600 + e*1600 + n*64 + q*4;
        __nv_bfloat16 h0 = __float2bfloat16(acc.x);
        __nv_bfloat16 h1 = __float2bfloat16(acc.y);
        __nv_bfloat16 h2 = __float2bfloat16(acc.z);
        __nv_bfloat16 h3 = __float2bfloat16(acc.w);
        __nv_bfloat162 hp0; hp0.x = h0; hp0.y = h1;
        __nv_bfloat162 hp1; hp1.x = h2; hp1.y = h3;
        ((__nv_bfloat162*)(g_full_hi + base))[0] = hp0;
        ((__nv_bfloat162*)(g_full_hi + base))[1] = hp1;
        __nv_bfloat162 lp0, lp1;
        lp0.x = __float2bfloat16(acc.x - __bfloat162float(h0));
        lp0.y = __float2bfloat16(acc.y - __bfloat162float(h1));
        lp1.x = __float2bfloat16(acc.z - __bfloat162float(h2));
        lp1.y = __float2bfloat16(acc.w - __bfloat162float(h3));
        ((__nv_bfloat162*)(g_full_lo + base))[0] = lp0;
        ((__nv_bfloat162*)(g_full_lo + base))[1] = lp1;
    }
}

// ---------------- K5b (merged per-l): projection GEMM out = full @ pw[l]^T (+pb at l=0) ----------------
#define K5B_GRID 1956

__launch_bounds__(256, 2)
__global__ void k5b_proj(const float* __restrict__ pb, float* __restrict__ out) {
    int id = blockIdx.x;
    int l, mb;
    if (id < 79)        { l = 0; mb = id; }
    else if (id < 314)  { l = 1; mb = id - 79; }
    else if (id < 705)  { l = 2; mb = id - 314; }
    else if (id < 1252) { l = 3; mb = id - 705; }
    else                { l = 4; mb = id - 1252; }
    const int nl = 2*l + 1;
    const int Ml = E_EDGES * nl;
    const int nstart = l*l;
    const int m0 = mb * 128;
    const int KC = 2;   // K = 64

    extern __shared__ char dsm[];
    const uint32_t smb = smem_u32(dsm);
    const int tid = threadIdx.x;
    const int wid = tid >> 5, lane = tid & 31;
    const int wm = (wid & 1) * 64;
    const int wn = (wid >> 1) * 32;

    float acc[4][4][4];
    #pragma unroll
    for (int i = 0; i < 4; i++)
        #pragma unroll
        for (int j = 0; j < 4; j++)
            #pragma unroll
            for (int q = 0; q < 4; q++) acc[i][j][q] = 0.f;

    const int lr = tid >> 2, slot = tid & 3;
    const __nv_bfloat16* aP[2];
    const __nv_bfloat16* wP[2];
    #pragma unroll
    for (int j = 0; j < 2; j++) {
        int gr = m0 + lr + 64*j; if (gr >= Ml) gr = 0;
        int e = gr / nl, r = gr - e*nl;
        aP[j] = g_full_hi + (long)e*1600 + (nstart + r)*64 + slot*8;
        int gn = lr + 64*j;
        wP[j] = g_pw_hi + (long)l*8192 + (long)gn*64 + slot*8;
    }
    const long adel = (const __nv_bfloat16*)g_full_lo - (const __nv_bfloat16*)g_full_hi;
    const long wdel = (const __nv_bfloat16*)g_pw_lo   - (const __nv_bfloat16*)g_pw_hi;

    auto issue = [&](int c) {
        if (c < KC) {
            int k0 = c * 32;
            uint32_t st = smb + (c & 1) * K3_STG;
            #pragma unroll
            for (int j = 0; j < 2; j++) {
                uint32_t d = st + (lr + 64*j)*K3_ROWB + slot*16;
                cp16(d,         aP[j] + k0);
                cp16(d + 10240, aP[j] + adel + k0);
                cp16(d + 20480, wP[j] + k0);
                cp16(d + 30720, wP[j] + wdel + k0);
            }
        }
        asm volatile("cp.async.commit_group;" ::: "memory");
    };

    issue(0); issue(1);

    const int a_row = lane & 15, a_kh = lane >> 4;
    const int b_nl  = (lane & 7) | ((lane >> 4) << 3);
    const int b_kh  = (lane >> 3) & 1;

    for (int c = 0; c < KC; c++) {
        uint32_t st = smb + (c & 1) * K3_STG;
        asm volatile("cp.async.wait_group 1;" ::: "memory");
        __syncthreads();
        uint32_t aH = st +         (wm + a_row)*K3_ROWB + a_kh*16;
        uint32_t bH = st + 20480 + (wn + b_nl)*K3_ROWB + b_kh*16;
        #pragma unroll
        for (int ks = 0; ks < 2; ks++) {
            uint32_t af[4][4], bf[2][4], tb[2][4];
            #pragma unroll
            for (int mi = 0; mi < 4; mi++) ldm_x4(aH + ks*32 + mi*16*K3_ROWB, af[mi]);
            #pragma unroll
            for (int nf = 0; nf < 2; nf++) ldm_x4(bH + ks*32 + nf*16*K3_ROWB, bf[nf]);
            #pragma unroll
            for (int mi = 0; mi < 4; mi++)
                #pragma unroll
                for (int ni = 0; ni < 4; ni++)
                    mma16816(acc[mi][ni], af[mi], bf[ni>>1][(ni&1)*2], bf[ni>>1][(ni&1)*2+1]);
            #pragma unroll
            for (int nf = 0; nf < 2; nf++) ldm_x4(bH + 10240 + ks*32 + nf*16*K3_ROWB, tb[nf]);
            #pragma unroll
            for (int mi = 0; mi < 4; mi++)
                #pragma unroll
                for (int ni = 0; ni < 4; ni++)
                    mma16816(acc[mi][ni], af[mi], tb[ni>>1][(ni&1)*2], tb[ni>>1][(ni&1)*2+1]);
            #pragma unroll
            for (int mi = 0; mi < 4; mi++) ldm_x4(aH + 10240 + ks*32 + mi*16*K3_ROWB, af[mi]);
            #pragma unroll
            for (int mi = 0; mi < 4; mi++)
                #pragma unroll
                for (int ni = 0; ni < 4; ni++)
                    mma16816(acc[mi][ni], af[mi], bf[ni>>1][(ni&1)*2], bf[ni>>1][(ni&1)*2+1]);
        }
        __syncthreads();
        issue(c + 2);
    }

    int tg = lane >> 2, tig = lane & 3;
    #pragma unroll
    for (int mi = 0; mi < 4; mi++) {
        #pragma unroll
        for (int ni = 0; ni < 4; ni++) {
            int col = wn + 8*ni + 2*tig;
            float bx = 0.f, by = 0.f;
            if (l == 0) { float2 bb = *(const float2*)(pb + col); bx = bb.x; by = bb.y; }
            #pragma unroll
            for (int h = 0; h < 2; h++) {
                int row = m0 + wm + 16*mi + tg + 8*h;
                if (row < Ml) {
                    int e = row / nl, r = row - e*nl;
                    float2 v = make_float2(acc[mi][ni][2*h] + bx, acc[mi][ni][2*h+1] + by);
                    *(float2*)(out + (long)e*3200 + (nstart + r)*128 + col) = v;
                }
            }
        }
    }
}

// ---------------- launch ----------------
extern "C" void kernel_launch(void* const* d_in, const int* in_sizes, int n_in,
                              void* d_out, int out_size) {
    const float* x    = (const float*)d_in[0];
    const float* ef   = (const float*)d_in[1];
    const float* ed   = (const float*)d_in[2];
    const float* wig  = (const float*)d_in[3];
    const float* semb = (const float*)d_in[4];
    const float* temb = (const float*)d_in[5];
    const float* w1   = (const float*)d_in[6];
    const float* b1   = (const float*)d_in[7];
    const float* g1   = (const float*)d_in[8];
    const float* bb1  = (const float*)d_in[9];
    const float* w2   = (const float*)d_in[10];
    const float* b2   = (const float*)d_in[11];
    const float* g2   = (const float*)d_in[12];
    const float* bb2  = (const float*)d_in[13];
    const float* w3   = (const float*)d_in[14];
    const float* b3   = (const float*)d_in[15];
    const float* wm0  = (const float*)d_in[16];
    const float* bm0  = (const float*)d_in[17];
    const float* wm1  = (const float*)d_in[18];
    const float* wm2  = (const float*)d_in[19];
    const float* pw   = (const float*)d_in[20];
    const float* pb   = (const float*)d_in[21];
    const int*   an   = (const int*)d_in[22];
    const int*   ei   = (const int*)d_in[23];
    float* out = (float*)d_out;

    static bool attr_done = false;
    if (!attr_done) {
        cudaFuncSetAttribute(k3_all,   cudaFuncAttributeMaxDynamicSharedMemorySize, K3_DSMEM);
        cudaFuncSetAttribute(k1_gemm,  cudaFuncAttributeMaxDynamicSharedMemorySize, K3_DSMEM);
        cudaFuncSetAttribute(k5b_proj, cudaFuncAttributeMaxDynamicSharedMemorySize, K3_DSMEM);
        attr_done = true;
    }

    // launch 0: fused prelude (transposes + bf16 splits; wm0 live rows only)
    k0_fused<<<10496, 256>>>(w1, w2, w3, wm0, wm1, wm2, pw);

    // launch 1: radial MLP layers 1-2
    k1_radial<<<E_EDGES/16, 256>>>(ed, semb, temb, b1, g1, bb1, b2, g2, bb2, an, ei);

    // launch 2: radial layer-3 GEMM on tensor cores
    k1_gemm<<<dim3(15, 79), 256, K3_DSMEM>>>(b3);

    // launch 3 (profiled): msg * w_rad + Wigner forward
    k2_wfwd<<<E_EDGES, 256>>>(x, ef, wig, ei);

    // launch 4: merged tensor-core GEMMs (mode0 trimmed to live columns)
    k3_all<<<K3_GRID, 256, K3_DSMEM>>>(bm0);

    // launch 5: recombine + Wigner back -> bf16 split full (vectorized einsum)
    k5a_wback<<<E_EDGES/4, 256>>>(wig);

    // launch 6: projection GEMM (per-l merged)
    k5b_proj<<<K5B_GRID, 256, K3_DSMEM>>>(pb, out);
}

// round 16
// speedup vs baseline: 1.9488x; 1.0600x over previous
#include <cuda_runtime.h>
#include <cuda_bf16.h>
#include <cstdint>

// ---------------- problem constants ----------------
#define E_EDGES   10000
#define NRED      19
#define MP_STRIDE (NRED*384)   // 7296
#define X0_DIM    576          // live columns of the m0 GEMM (512..1088 of original)

// ---------------- scratch (__device__ globals) ----------------
__device__ __nv_bfloat16 g_w1s_hi[128*384];
__device__ __nv_bfloat16 g_w1s_lo[128*384];
__device__ __nv_bfloat16 g_w2s_hi[128*128];
__device__ __nv_bfloat16 g_w2s_lo[128*128];
__device__ __nv_bfloat16 g_w3s_hi[1920*128];
__device__ __nv_bfloat16 g_w3s_lo[1920*128];
__device__ __nv_bfloat16 g_wm0_hi[1088*1920];
__device__ __nv_bfloat16 g_wm0_lo[1088*1920];
__device__ __nv_bfloat16 g_wm1_hi[512*1536];
__device__ __nv_bfloat16 g_wm1_lo[512*1536];
__device__ __nv_bfloat16 g_wm2_hi[384*1152];
__device__ __nv_bfloat16 g_wm2_lo[384*1152];
__device__ __nv_bfloat16 g_pw_hi[5*128*64];
__device__ __nv_bfloat16 g_pw_lo[5*128*64];
__device__ __nv_bfloat16 g_xe_hi[(long)E_EDGES*384];
__device__ __nv_bfloat16 g_xe_lo[(long)E_EDGES*384];
__device__ float g_hpre[(long)E_EDGES*128];
__device__ __nv_bfloat16 g_h1_hi[(long)E_EDGES*128];
__device__ __nv_bfloat16 g_h1_lo[(long)E_EDGES*128];
__device__ __nv_bfloat16 g_h2_hi[(long)E_EDGES*128];
__device__ __nv_bfloat16 g_h2_lo[(long)E_EDGES*128];
__device__ float g_wrad[(long)E_EDGES*1920];
__device__ __nv_bfloat16 g_mp_hi[(long)E_EDGES*MP_STRIDE];
__device__ __nv_bfloat16 g_mp_lo[(long)E_EDGES*MP_STRIDE];
__device__ float g_x0  [(long)E_EDGES*X0_DIM];
__device__ float g_ym1 [(long)E_EDGES*2*512];
__device__ float g_ym2 [(long)E_EDGES*2*384];
__device__ __nv_bfloat16 g_full_hi[(long)E_EDGES*1600];
__device__ __nv_bfloat16 g_full_lo[(long)E_EDGES*1600];

// permutation tables
__constant__ int c_MASKP[19] = {0,2,6,12,20, 3,7,13,21, 1,5,11,19, 8,14,22, 4,10,18};
__constant__ int c_MASK [19] = {0,1,2,3,4,5,6,7,8,10,11,12,13,14,18,19,20,21,22};
__constant__ int c_PERM [19] = {0,2,6,11,16, 3,7,12,17, 1,5,10,15, 8,13,18, 4,9,14};
__constant__ int c_LPERM[19] = {0,1,2,3,4, 1,2,3,4, 1,2,3,4, 2,3,4, 2,3,4};
__constant__ int c_LFULL[25] = {0,1,1,1,2,2,2,2,2,3,3,3,3,3,3,3,4,4,4,4,4,4,4,4,4};

__device__ __forceinline__ float sigm(float x){ return 1.f/(1.f+__expf(-x)); }

__device__ __forceinline__ uint32_t smem_u32(const void* p) {
    uint32_t a;
    asm("{ .reg .u64 t; cvta.to.shared.u64 t, %1; cvt.u32.u64 %0, t; }" : "=r"(a) : "l"(p));
    return a;
}
__device__ __forceinline__ void cp16(uint32_t dst, const void* src) {
    asm volatile("cp.async.cg.shared.global [%0], [%1], 16;" :: "r"(dst), "l"(src));
}
__device__ __forceinline__ void ldm_x4(uint32_t addr, uint32_t* r) {
    asm volatile("ldmatrix.sync.aligned.m8n8.x4.shared.b16 {%0,%1,%2,%3}, [%4];"
                 : "=r"(r[0]), "=r"(r[1]), "=r"(r[2]), "=r"(r[3]) : "r"(addr));
}
__device__ __forceinline__ void mma16816(float* d, const uint32_t* a, uint32_t b0, uint32_t b1) {
    asm volatile("mma.sync.aligned.m16n8k16.row.col.f32.bf16.bf16.f32 "
                 "{%0,%1,%2,%3}, {%4,%5,%6,%7}, {%8,%9}, {%0,%1,%2,%3};"
                 : "+f"(d[0]), "+f"(d[1]), "+f"(d[2]), "+f"(d[3])
                 : "r"(a[0]), "r"(a[1]), "r"(a[2]), "r"(a[3]), "r"(b0), "r"(b1));
}

// ---------------- K0 (fused): bf16 weight splits, single launch ----------------
__global__ void k0_fused(const float* __restrict__ w1, const float* __restrict__ w2,
                         const float* __restrict__ w3, const float* __restrict__ wm0,
                         const float* __restrict__ wm1, const float* __restrict__ wm2,
                         const float* __restrict__ pw) {
    long i = (long)blockIdx.x*256 + threadIdx.x;
    if (i < 49152) {
        float v = w1[i]; __nv_bfloat16 h = __float2bfloat16(v);
        g_w1s_hi[i] = h; g_w1s_lo[i] = __float2bfloat16(v - __bfloat162float(h));
        return;
    }
    i -= 49152;
    if (i < 16384) {
        float v = w2[i]; __nv_bfloat16 h = __float2bfloat16(v);
        g_w2s_hi[i] = h; g_w2s_lo[i] = __float2bfloat16(v - __bfloat162float(h));
        return;
    }
    i -= 16384;
    if (i < 245760) {
        float v = w3[i]; __nv_bfloat16 h = __float2bfloat16(v);
        g_w3s_hi[i] = h; g_w3s_lo[i] = __float2bfloat16(v - __bfloat162float(h));
        return;
    }
    i -= 245760;
    if (i < 1105920) {   // only rows 512..1088 of wm0 are live
        long ii = i + (long)512*1920;
        float v = wm0[ii]; __nv_bfloat16 h = __float2bfloat16(v);
        g_wm0_hi[ii] = h; g_wm0_lo[ii] = __float2bfloat16(v - __bfloat162float(h));
        return;
    }
    i -= 1105920;
    if (i < 786432) {
        float v = wm1[i]; __nv_bfloat16 h = __float2bfloat16(v);
        g_wm1_hi[i] = h; g_wm1_lo[i] = __float2bfloat16(v - __bfloat162float(h));
        return;
    }
    i -= 786432;
    if (i < 442368) {
        float v = wm2[i]; __nv_bfloat16 h = __float2bfloat16(v);
        g_wm2_hi[i] = h; g_wm2_lo[i] = __float2bfloat16(v - __bfloat162float(h));
        return;
    }
    i -= 442368;
    if (i < 40960) {
        float v = pw[i]; __nv_bfloat16 h = __float2bfloat16(v);
        g_pw_hi[i] = h; g_pw_lo[i] = __float2bfloat16(v - __bfloat162float(h));
    }
}

// ---------------- K1a: gather x_edge -> bf16 split [E, 384] ----------------
__global__ void k1a_gather(const float* __restrict__ ed,
                           const float* __restrict__ semb, const float* __restrict__ temb,
                           const int* __restrict__ an, const int* __restrict__ ei) {
    long i = (long)blockIdx.x*256 + threadIdx.x;
    if (i >= (long)E_EDGES*384) return;
    int e = (int)(i / 384), c = (int)(i - (long)e*384);
    float v;
    if (c < 128)       v = ed[(long)e*128 + c];
    else if (c < 256)  v = semb[an[ei[e]]*128 + (c-128)];
    else               v = temb[an[ei[E_EDGES + e]]*128 + (c-256)];
    __nv_bfloat16 h = __float2bfloat16(v);
    g_xe_hi[i] = h;
    g_xe_lo[i] = __float2bfloat16(v - __bfloat162float(h));
}

// ---------------- K1LN: LayerNorm + silu + bf16 split (1 row/warp) ----------------
__launch_bounds__(256)
__global__ void k1ln(const float* __restrict__ gam, const float* __restrict__ bet, int sel) {
    int row = blockIdx.x*8 + (threadIdx.x >> 5);
    int lane = threadIdx.x & 31;
    const float* src = g_hpre + (long)row*128;
    float v[4];
    float s = 0.f, s2 = 0.f;
    #pragma unroll
    for (int q = 0; q < 4; q++) { v[q] = src[lane + 32*q]; s += v[q]; s2 += v[q]*v[q]; }
    #pragma unroll
    for (int off = 16; off > 0; off >>= 1) {
        s  += __shfl_xor_sync(0xffffffffu, s,  off);
        s2 += __shfl_xor_sync(0xffffffffu, s2, off);
    }
    float mu = s * (1.f/128.f);
    float var = s2 * (1.f/128.f) - mu*mu;
    float rstd = rsqrtf(var + 1e-5f);
    __nv_bfloat16* dhi = sel ? g_h2_hi : g_h1_hi;
    __nv_bfloat16* dlo = sel ? g_h2_lo : g_h1_lo;
    #pragma unroll
    for (int q = 0; q < 4; q++) {
        int oo = lane + 32*q;
        float f = (v[q] - mu)*rstd*gam[oo] + bet[oo];
        f = f * sigm(f);
        __nv_bfloat16 h = __float2bfloat16(f);
        dhi[(long)row*128 + oo] = h;
        dlo[(long)row*128 + oo] = __float2bfloat16(f - __bfloat162float(h));
    }
}

// ---------------- K1G<PHASE>: radial GEMMs on tensor cores ----------------
// PHASE 0: g_hpre = xe @ w1^T + b1    (M=10000, N=128,  K=384)
// PHASE 1: g_hpre = h1 @ w2^T + b2    (M=10000, N=128,  K=128)
// PHASE 2: g_wrad = h2 @ w3^T + b3    (M=10000, N=1920, K=128)
#define K3_ROWB   80
#define K3_STG    40960
#define K3_DSMEM  (2*K3_STG)   // 81920

template<int PHASE>
__launch_bounds__(256, 2)
__global__ void k1g(const float* __restrict__ bias) {
    const int N  = (PHASE==2) ? 1920 : 128;
    const int K  = (PHASE==0) ? 384 : 128;
    const int M  = E_EDGES;
    const int KC = K >> 5;
    const __nv_bfloat16* __restrict__ Ahi = (PHASE==0) ? g_xe_hi : (PHASE==1) ? g_h1_hi : g_h2_hi;
    const __nv_bfloat16* __restrict__ Alo = (PHASE==0) ? g_xe_lo : (PHASE==1) ? g_h1_lo : g_h2_lo;
    const __nv_bfloat16* __restrict__ Whi = (PHASE==0) ? g_w1s_hi : (PHASE==1) ? g_w2s_hi : g_w3s_hi;
    const __nv_bfloat16* __restrict__ Wlo = (PHASE==0) ? g_w1s_lo : (PHASE==1) ? g_w2s_lo : g_w3s_lo;
    float* __restrict__ C = (PHASE==2) ? g_wrad : g_hpre;

    extern __shared__ char dsm[];
    const uint32_t smb = smem_u32(dsm);
    const int tid = threadIdx.x;
    const int wid = tid >> 5, lane = tid & 31;
    const int n0 = blockIdx.x * 128;
    const int m0 = blockIdx.y * 128;
    const int wm = (wid & 1) * 64;
    const int wn = (wid >> 1) * 32;

    float acc[4][4][4];
    #pragma unroll
    for (int i = 0; i < 4; i++)
        #pragma unroll
        for (int j = 0; j < 4; j++)
            #pragma unroll
            for (int q = 0; q < 4; q++) acc[i][j][q] = 0.f;

    const int lr = tid >> 2, slot = tid & 3;
    const __nv_bfloat16* aP[2];
    const __nv_bfloat16* wP[2];
    #pragma unroll
    for (int j = 0; j < 2; j++) {
        int r = lr + 64*j;
        int gr = m0 + r; if (gr >= M) gr = 0;
        aP[j] = Ahi + (long)gr*K + slot*8;
        int gn = n0 + r;
        wP[j] = Whi + (long)gn*K + slot*8;
    }
    const long adel = Alo - Ahi;
    const long wdel = Wlo - Whi;

    auto issue = [&](int c) {
        if (c < KC) {
            int k0 = c * 32;
            uint32_t st = smb + (c & 1) * K3_STG;
            #pragma unroll
            for (int j = 0; j < 2; j++) {
                uint32_t d = st + (lr + 64*j)*K3_ROWB + slot*16;
                cp16(d,         aP[j] + k0);
                cp16(d + 10240, aP[j] + adel + k0);
                cp16(d + 20480, wP[j] + k0);
                cp16(d + 30720, wP[j] + wdel + k0);
            }
        }
        asm volatile("cp.async.commit_group;" ::: "memory");
    };

    issue(0); issue(1);

    const int a_row = lane & 15, a_kh = lane >> 4;
    const int b_nl  = (lane & 7) | ((lane >> 4) << 3);
    const int b_kh  = (lane >> 3) & 1;

    for (int c = 0; c < KC; c++) {
        uint32_t st = smb + (c & 1) * K3_STG;
        asm volatile("cp.async.wait_group 1;" ::: "memory");
        __syncthreads();
        uint32_t aH = st +         (wm + a_row)*K3_ROWB + a_kh*16;
        uint32_t bH = st + 20480 + (wn + b_nl)*K3_ROWB + b_kh*16;
        #pragma unroll
        for (int ks = 0; ks < 2; ks++) {
            uint32_t af[4][4], bf[2][4], tb[2][4];
            #pragma unroll
            for (int mi = 0; mi < 4; mi++) ldm_x4(aH + ks*32 + mi*16*K3_ROWB, af[mi]);
            #pragma unroll
            for (int nf = 0; nf < 2; nf++) ldm_x4(bH + ks*32 + nf*16*K3_ROWB, bf[nf]);
            #pragma unroll
            for (int mi = 0; mi < 4; mi++)
                #pragma unroll
                for (int ni = 0; ni < 4; ni++)
                    mma16816(acc[mi][ni], af[mi], bf[ni>>1][(ni&1)*2], bf[ni>>1][(ni&1)*2+1]);
            #pragma unroll
            for (int nf = 0; nf < 2; nf++) ldm_x4(bH + 10240 + ks*32 + nf*16*K3_ROWB, tb[nf]);
            #pragma unroll
            for (int mi = 0; mi < 4; mi++)
                #pragma unroll
                for (int ni = 0; ni < 4; ni++)
                    mma16816(acc[mi][ni], af[mi], tb[ni>>1][(ni&1)*2], tb[ni>>1][(ni&1)*2+1]);
            #pragma unroll
            for (int mi = 0; mi < 4; mi++) ldm_x4(aH + 10240 + ks*32 + mi*16*K3_ROWB, af[mi]);
            #pragma unroll
            for (int mi = 0; mi < 4; mi++)
                #pragma unroll
                for (int ni = 0; ni < 4; ni++)
                    mma16816(acc[mi][ni], af[mi], bf[ni>>1][(ni&1)*2], bf[ni>>1][(ni&1)*2+1]);
        }
        __syncthreads();
        issue(c + 2);
    }

    int tg = lane >> 2, tig = lane & 3;
    #pragma unroll
    for (int mi = 0; mi < 4; mi++) {
        #pragma unroll
        for (int ni = 0; ni < 4; ni++) {
            int row = m0 + wm + 16*mi + tg;
            int col = n0 + wn + 8*ni + 2*tig;
            float2 bb = *(const float2*)(bias + col);
            if (row < M) {
                float2 v = make_float2(acc[mi][ni][0] + bb.x, acc[mi][ni][1] + bb.y);
                *(float2*)(C + (long)row*N + col) = v;
            }
            if (row + 8 < M) {
                float2 v = make_float2(acc[mi][ni][2] + bb.x, acc[mi][ni][3] + bb.y);
                *(float2*)(C + (long)(row+8)*N + col) = v;
            }
        }
    }
}

// ---------------- K2: msg build * w_rad, Wigner fwd (5-j groups), bf16-split ----------------
__launch_bounds__(256)
__global__ void k2_wfwd(const float* __restrict__ x, const float* __restrict__ ef,
                        const float* __restrict__ wig, const int* __restrict__ ei) {
    __shared__ float msg[25*384];
    __shared__ float wp[20*25];   // row 19 = zero pad
    int e = blockIdx.x, tid = threadIdx.x;
    int src = ei[e], tgt = ei[E_EDGES + e];

    for (int idx = tid; idx < 500; idx += 256) {
        int j = idx / 25, n = idx - j*25;
        wp[idx] = (j < 19) ? wig[(long)e*625 + c_MASKP[j]*25 + n] : 0.f;
    }
    const float4* x4  = (const float4*)x;
    const float4* ef4 = (const float4*)ef;
    const float4* wr4 = (const float4*)(g_wrad + (long)e*1920);
    float4* msg4 = (float4*)msg;
    for (int idx = tid; idx < 25*96; idx += 256) {
        int n = idx / 96, c4 = idx - n*96;
        float4 v;
        if (c4 < 32)      v = x4[(long)src*800 + n*32 + c4];
        else if (c4 < 64) v = x4[(long)tgt*800 + n*32 + (c4-32)];
        else              v = ef4[(long)e*800 + n*32 + (c4-64)];
        float4 w = wr4[c_LFULL[n]*96 + c4];
        v.x *= w.x; v.y *= w.y; v.z *= w.z; v.w *= w.w;
        msg4[idx] = v;
    }
    __syncthreads();

    const float4* m4 = (const float4*)msg;
    for (int idx = tid; idx < 384; idx += 256) {
        int c4 = idx % 96, j0 = (idx / 96) * 5;
        float4 acc[5];
        #pragma unroll
        for (int jj = 0; jj < 5; jj++) acc[jj] = make_float4(0.f,0.f,0.f,0.f);
        #pragma unroll 5
        for (int n = 0; n < 25; n++) {
            float4 m = m4[n*96 + c4];
            #pragma unroll
            for (int jj = 0; jj < 5; jj++) {
                float w = wp[(j0+jj)*25 + n];
                acc[jj].x += w*m.x; acc[jj].y += w*m.y;
                acc[jj].z += w*m.z; acc[jj].w += w*m.w;
            }
        }
        #pragma unroll
        for (int jj = 0; jj < 5; jj++) {
            int j = j0 + jj;
            if (j < 19) {
                long base = (long)e*MP_STRIDE + (long)(j*96 + c4)*4;
                float4 a = acc[jj];
                __nv_bfloat16 h0 = __float2bfloat16(a.x);
                __nv_bfloat16 h1 = __float2bfloat16(a.y);
                __nv_bfloat16 h2 = __float2bfloat16(a.z);
                __nv_bfloat16 h3 = __float2bfloat16(a.w);
                __nv_bfloat162 hp0; hp0.x = h0; hp0.y = h1;
                __nv_bfloat162 hp1; hp1.x = h2; hp1.y = h3;
                ((__nv_bfloat162*)(g_mp_hi + base))[0] = hp0;
                ((__nv_bfloat162*)(g_mp_hi + base))[1] = hp1;
                __nv_bfloat162 lp0, lp1;
                lp0.x = __float2bfloat16(a.x - __bfloat162float(h0));
                lp0.y = __float2bfloat16(a.y - __bfloat162float(h1));
                lp1.x = __float2bfloat16(a.z - __bfloat162float(h2));
                lp1.y = __float2bfloat16(a.w - __bfloat162float(h3));
                ((__nv_bfloat162*)(g_mp_lo + base))[0] = lp0;
                ((__nv_bfloat162*)(g_mp_lo + base))[1] = lp1;
            }
        }
    }
}

// ---------------- K3 (merged): mma.sync bf16x3 GEMM, all 3 modes in one grid ----------------
#define K3_GRID   1494

__launch_bounds__(256, 2)
__global__ void k3_all(const float* __restrict__ bias) {
    int id = blockIdx.x;
    int mode, nbx, mby;
    if (id < 395)       { mode = 0; nbx = id % 5;            mby = id / 5; }
    else if (id < 1023) { int t = id - 395;  mode = 1; nbx = t & 3; mby = t >> 2; }
    else                { int t = id - 1023; mode = 2; nbx = t % 3; mby = t / 3; }

    const int N  = (mode==0) ? 576  : (mode==1) ? 512 : 384;
    const int K  = (mode==0) ? 1920 : (mode==1) ? 1536 : 1152;
    const int M  = (mode==0) ? E_EDGES : 2*E_EDGES;
    const int KC = K >> 5;
    const __nv_bfloat16* __restrict__ Whi = (mode==0) ? g_wm0_hi + (long)512*1920 : (mode==1) ? g_wm1_hi : g_wm2_hi;
    const __nv_bfloat16* __restrict__ Wlo = (mode==0) ? g_wm0_lo + (long)512*1920 : (mode==1) ? g_wm1_lo : g_wm2_lo;
    float* __restrict__ C = (mode==0) ? g_x0 : (mode==1) ? g_ym1 : g_ym2;

    extern __shared__ char dsm[];
    const uint32_t smb = smem_u32(dsm);
    const int tid = threadIdx.x;
    const int wid = tid >> 5, lane = tid & 31;
    const int n0 = nbx * 128;
    const int m0 = mby * 128;
    const int wm = (wid & 1) * 64;
    const int wn = (wid >> 1) * 32;

    float acc[4][4][4];
    #pragma unroll
    for (int i = 0; i < 4; i++)
        #pragma unroll
        for (int j = 0; j < 4; j++)
            #pragma unroll
            for (int q = 0; q < 4; q++) acc[i][j][q] = 0.f;

    const int lr = tid >> 2, slot = tid & 3;
    const __nv_bfloat16* aP[2];
    const __nv_bfloat16* wP[2];
    #pragma unroll
    for (int j = 0; j < 2; j++) {
        int r = lr + 64*j;
        int gr = m0 + r; if (gr >= M) gr = 0;
        long ab;
        if (mode == 0)      ab = (long)gr*MP_STRIDE;
        else if (mode == 1) ab = (long)(gr>>1)*MP_STRIDE + 1920 + (long)(gr&1)*1536;
        else                ab = (long)(gr>>1)*MP_STRIDE + 4992 + (long)(gr&1)*1152;
        aP[j] = g_mp_hi + ab + slot*8;
        int gn = n0 + r; if (gn >= N) gn = N-1;
        wP[j] = Whi + (long)gn*K + slot*8;
    }
    const long adel = (const __nv_bfloat16*)g_mp_lo - (const __nv_bfloat16*)g_mp_hi;
    const long wdel = Wlo - Whi;

    auto issue = [&](int c) {
        if (c < KC) {
            int k0 = c * 32;
            uint32_t st = smb + (c & 1) * K3_STG;
            #pragma unroll
            for (int j = 0; j < 2; j++) {
                uint32_t d = st + (lr + 64*j)*K3_ROWB + slot*16;
                cp16(d,         aP[j] + k0);
                cp16(d + 10240, aP[j] + adel + k0);
                cp16(d + 20480, wP[j] + k0);
                cp16(d + 30720, wP[j] + wdel + k0);
            }
        }
        asm volatile("cp.async.commit_group;" ::: "memory");
    };

    issue(0); issue(1);

    const int a_row = lane & 15, a_kh = lane >> 4;
    const int b_nl  = (lane & 7) | ((lane >> 4) << 3);
    const int b_kh  = (lane >> 3) & 1;

    for (int c = 0; c < KC; c++) {
        uint32_t st = smb + (c & 1) * K3_STG;
        asm volatile("cp.async.wait_group 1;" ::: "memory");
        __syncthreads();
        uint32_t aH = st +         (wm + a_row)*K3_ROWB + a_kh*16;
        uint32_t bH = st + 20480 + (wn + b_nl)*K3_ROWB + b_kh*16;
        #pragma unroll
        for (int ks = 0; ks < 2; ks++) {
            uint32_t af[4][4], bf[2][4], tb[2][4];
            #pragma unroll
            for (int mi = 0; mi < 4; mi++) ldm_x4(aH + ks*32 + mi*16*K3_ROWB, af[mi]);
            #pragma unroll
            for (int nf = 0; nf < 2; nf++) ldm_x4(bH + ks*32 + nf*16*K3_ROWB, bf[nf]);
            #pragma unroll
            for (int mi = 0; mi < 4; mi++)
                #pragma unroll
                for (int ni = 0; ni < 4; ni++)
                    mma16816(acc[mi][ni], af[mi], bf[ni>>1][(ni&1)*2], bf[ni>>1][(ni&1)*2+1]);
            #pragma unroll
            for (int nf = 0; nf < 2; nf++) ldm_x4(bH + 10240 + ks*32 + nf*16*K3_ROWB, tb[nf]);
            #pragma unroll
            for (int mi = 0; mi < 4; mi++)
                #pragma unroll
                for (int ni = 0; ni < 4; ni++)
                    mma16816(acc[mi][ni], af[mi], tb[ni>>1][(ni&1)*2], tb[ni>>1][(ni&1)*2+1]);
            #pragma unroll
            for (int mi = 0; mi < 4; mi++) ldm_x4(aH + 10240 + ks*32 + mi*16*K3_ROWB, af[mi]);
            #pragma unroll
            for (int mi = 0; mi < 4; mi++)
                #pragma unroll
                for (int ni = 0; ni < 4; ni++)
                    mma16816(acc[mi][ni], af[mi], bf[ni>>1][(ni&1)*2], bf[ni>>1][(ni&1)*2+1]);
        }
        __syncthreads();
        issue(c + 2);
    }

    int tg = lane >> 2, tig = lane & 3;
    #pragma unroll
    for (int mi = 0; mi < 4; mi++) {
        #pragma unroll
        for (int ni = 0; ni < 4; ni++) {
            int row = m0 + wm + 16*mi + tg;
            int col = n0 + wn + 8*ni + 2*tig;
            if (col < N) {
                float bx = 0.f, by = 0.f;
                if (mode == 0) { float2 bb = *(const float2*)(bias + 512 + col); bx = bb.x; by = bb.y; }
                if (row < M) {
                    float2 v = make_float2(acc[mi][ni][0] + bx, acc[mi][ni][1] + by);
                    *(float2*)(C + (long)row*N + col) = v;
                }
                if (row + 8 < M) {
                    float2 v = make_float2(acc[mi][ni][2] + bx, acc[mi][ni][3] + by);
                    *(float2*)(C + (long)(row+8)*N + col) = v;
                }
            }
        }
    }
}

// ---------------- K5a: recombine+gate + Wigner back -> g_full (bf16 split), 4 edges/block ----------------
__launch_bounds__(256)
__global__ void k5a_wback(const float* __restrict__ wig) {
    __shared__ float s_w [1900];
    __shared__ float s_hl[4864];
    int e0 = blockIdx.x * 4;
    int tid = threadIdx.x;

    for (int idx = tid; idx < 1900; idx += 256) {
        int e = idx / 475, rem = idx - e*475;
        int r = rem / 25, n = rem - r*25;
        s_w[idx] = wig[(long)(e0+e)*625 + c_MASK[r]*25 + n];
    }
    for (int idx = tid; idx < 4864; idx += 256) {
        int e = idx / 1216, rem = idx - e*1216;
        int j = rem >> 6, i = rem & 63;
        const float* x0 = g_x0  + (long)(e0+e)*X0_DIM;
        const float* y1 = g_ym1 + (long)(e0+e)*1024;
        const float* y2 = g_ym2 + (long)(e0+e)*768;
        float val;
        if (j < 5)        val = x0[256 + (j<<6) + i];
        else if (j < 9)  { int jj = j-5;  val = y1[jj*64 + i]       - y1[768 + jj*64 + i]; }
        else if (j < 13) { int jj = j-9;  val = y1[512 + jj*64 + i] + y1[256 + jj*64 + i]; }
        else if (j < 16) { int jj = j-13; val = y2[jj*64 + i]       - y2[576 + jj*64 + i]; }
        else             { int jj = j-16; val = y2[384 + jj*64 + i] + y2[192 + jj*64 + i]; }
        if (j == 0) {
            val = val * sigm(val);
        } else {
            float gsrc = x0[(c_LPERM[j]-1)*64 + i];
            val *= sigm(gsrc);
        }
        s_hl[e*1216 + c_PERM[j]*64 + i] = val;
    }
    __syncthreads();
    for (int idx = tid; idx < 1600; idx += 256) {
        int e = idx / 400, rem = idx - e*400;
        int n = rem >> 4, q = rem & 15;
        float4 acc = make_float4(0.f,0.f,0.f,0.f);
        const float* hlb = &s_hl[e*1216 + q*4];
        const float* wb  = &s_w[e*475 + n];
        #pragma unroll
        for (int r = 0; r < 19; r++) {
            float w = wb[r*25];
            float4 f = *(const float4*)(hlb + r*64);
            acc.x += w*f.x; acc.y += w*f.y; acc.z += w*f.z; acc.w += w*f.w;
        }
        long base = (long)e0*1600 + e*1600 + n*64 + q*4;
        __nv_bfloat16 h0 = __float2bfloat16(acc.x);
        __nv_bfloat16 h1 = __float2bfloat16(acc.y);
        __nv_bfloat16 h2 = __float2bfloat16(acc.z);
        __nv_bfloat16 h3 = __float2bfloat16(acc.w);
        __nv_bfloat162 hp0; hp0.x = h0; hp0.y = h1;
        __nv_bfloat162 hp1; hp1.x = h2; hp1.y = h3;
        ((__nv_bfloat162*)(g_full_hi + base))[0] = hp0;
        ((__nv_bfloat162*)(g_full_hi + base))[1] = hp1;
        __nv_bfloat162 lp0, lp1;
        lp0.x = __float2bfloat16(acc.x - __bfloat162float(h0));
        lp0.y = __float2bfloat16(acc.y - __bfloat162float(h1));
        lp1.x = __float2bfloat16(acc.z - __bfloat162float(h2));
        lp1.y = __float2bfloat16(acc.w - __bfloat162float(h3));
        ((__nv_bfloat162*)(g_full_lo + base))[0] = lp0;
        ((__nv_bfloat162*)(g_full_lo + base))[1] = lp1;
    }
}

// ---------------- K5b (merged per-l): projection GEMM out = full @ pw[l]^T (+pb at l=0) ----------------
#define K5B_GRID 1956

__launch_bounds__(256, 2)
__global__ void k5b_proj(const float* __restrict__ pb, float* __restrict__ out) {
    int id = blockIdx.x;
    int l, mb;
    if (id < 79)        { l = 0; mb = id; }
    else if (id < 314)  { l = 1; mb = id - 79; }
    else if (id < 705)  { l = 2; mb = id - 314; }
    else if (id < 1252) { l = 3; mb = id - 705; }
    else                { l = 4; mb = id - 1252; }
    const int nl = 2*l + 1;
    const int Ml = E_EDGES * nl;
    const int nstart = l*l;
    const int m0 = mb * 128;
    const int KC = 2;   // K = 64

    extern __shared__ char dsm[];
    const uint32_t smb = smem_u32(dsm);
    const int tid = threadIdx.x;
    const int wid = tid >> 5, lane = tid & 31;
    const int wm = (wid & 1) * 64;
    const int wn = (wid >> 1) * 32;

    float acc[4][4][4];
    #pragma unroll
    for (int i = 0; i < 4; i++)
        #pragma unroll
        for (int j = 0; j < 4; j++)
            #pragma unroll
            for (int q = 0; q < 4; q++) acc[i][j][q] = 0.f;

    const int lr = tid >> 2, slot = tid & 3;
    const __nv_bfloat16* aP[2];
    const __nv_bfloat16* wP[2];
    #pragma unroll
    for (int j = 0; j < 2; j++) {
        int gr = m0 + lr + 64*j; if (gr >= Ml) gr = 0;
        int e = gr / nl, r = gr - e*nl;
        aP[j] = g_full_hi + (long)e*1600 + (nstart + r)*64 + slot*8;
        int gn = lr + 64*j;
        wP[j] = g_pw_hi + (long)l*8192 + (long)gn*64 + slot*8;
    }
    const long adel = (const __nv_bfloat16*)g_full_lo - (const __nv_bfloat16*)g_full_hi;
    const long wdel = (const __nv_bfloat16*)g_pw_lo   - (const __nv_bfloat16*)g_pw_hi;

    auto issue = [&](int c) {
        if (c < KC) {
            int k0 = c * 32;
            uint32_t st = smb + (c & 1) * K3_STG;
            #pragma unroll
            for (int j = 0; j < 2; j++) {
                uint32_t d = st + (lr + 64*j)*K3_ROWB + slot*16;
                cp16(d,         aP[j] + k0);
                cp16(d + 10240, aP[j] + adel + k0);
                cp16(d + 20480, wP[j] + k0);
                cp16(d + 30720, wP[j] + wdel + k0);
            }
        }
        asm volatile("cp.async.commit_group;" ::: "memory");
    };

    issue(0); issue(1);

    const int a_row = lane & 15, a_kh = lane >> 4;
    const int b_nl  = (lane & 7) | ((lane >> 4) << 3);
    const int b_kh  = (lane >> 3) & 1;

    for (int c = 0; c < KC; c++) {
        uint32_t st = smb + (c & 1) * K3_STG;
        asm volatile("cp.async.wait_group 1;" ::: "memory");
        __syncthreads();
        uint32_t aH = st +         (wm + a_row)*K3_ROWB + a_kh*16;
        uint32_t bH = st + 20480 + (wn + b_nl)*K3_ROWB + b_kh*16;
        #pragma unroll
        for (int ks = 0; ks < 2; ks++) {
            uint32_t af[4][4], bf[2][4], tb[2][4];
            #pragma unroll
            for (int mi = 0; mi < 4; mi++) ldm_x4(aH + ks*32 + mi*16*K3_ROWB, af[mi]);
            #pragma unroll
            for (int nf = 0; nf < 2; nf++) ldm_x4(bH + ks*32 + nf*16*K3_ROWB, bf[nf]);
            #pragma unroll
            for (int mi = 0; mi < 4; mi++)
                #pragma unroll
                for (int ni = 0; ni < 4; ni++)
                    mma16816(acc[mi][ni], af[mi], bf[ni>>1][(ni&1)*2], bf[ni>>1][(ni&1)*2+1]);
            #pragma unroll
            for (int nf = 0; nf < 2; nf++) ldm_x4(bH + 10240 + ks*32 + nf*16*K3_ROWB, tb[nf]);
            #pragma unroll
            for (int mi = 0; mi < 4; mi++)
                #pragma unroll
                for (int ni = 0; ni < 4; ni++)
                    mma16816(acc[mi][ni], af[mi], tb[ni>>1][(ni&1)*2], tb[ni>>1][(ni&1)*2+1]);
            #pragma unroll
            for (int mi = 0; mi < 4; mi++) ldm_x4(aH + 10240 + ks*32 + mi*16*K3_ROWB, af[mi]);
            #pragma unroll
            for (int mi = 0; mi < 4; mi++)
                #pragma unroll
                for (int ni = 0; ni < 4; ni++)
                    mma16816(acc[mi][ni], af[mi], bf[ni>>1][(ni&1)*2], bf[ni>>1][(ni&1)*2+1]);
        }
        __syncthreads();
        issue(c + 2);
    }

    int tg = lane >> 2, tig = lane & 3;
    #pragma unroll
    for (int mi = 0; mi < 4; mi++) {
        #pragma unroll
        for (int ni = 0; ni < 4; ni++) {
            int col = wn + 8*ni + 2*tig;
            float bx = 0.f, by = 0.f;
            if (l == 0) { float2 bb = *(const float2*)(pb + col); bx = bb.x; by = bb.y; }
            #pragma unroll
            for (int h = 0; h < 2; h++) {
                int row = m0 + wm + 16*mi + tg + 8*h;
                if (row < Ml) {
                    int e = row / nl, r = row - e*nl;
                    float2 v = make_float2(acc[mi][ni][2*h] + bx, acc[mi][ni][2*h+1] + by);
                    *(float2*)(out + (long)e*3200 + (nstart + r)*128 + col) = v;
                }
            }
        }
    }
}

// ---------------- launch ----------------
extern "C" void kernel_launch(void* const* d_in, const int* in_sizes, int n_in,
                              void* d_out, int out_size) {
    const float* x    = (const float*)d_in[0];
    const float* ef   = (const float*)d_in[1];
    const float* ed   = (const float*)d_in[2];
    const float* wig  = (const float*)d_in[3];
    const float* semb = (const float*)d_in[4];
    const float* temb = (const float*)d_in[5];
    const float* w1   = (const float*)d_in[6];
    const float* b1   = (const float*)d_in[7];
    const float* g1   = (const float*)d_in[8];
    const float* bb1  = (const float*)d_in[9];
    const float* w2   = (const float*)d_in[10];
    const float* b2   = (const float*)d_in[11];
    const float* g2   = (const float*)d_in[12];
    const float* bb2  = (const float*)d_in[13];
    const float* w3   = (const float*)d_in[14];
    const float* b3   = (const float*)d_in[15];
    const float* wm0  = (const float*)d_in[16];
    const float* bm0  = (const float*)d_in[17];
    const float* wm1  = (const float*)d_in[18];
    const float* wm2  = (const float*)d_in[19];
    const float* pw   = (const float*)d_in[20];
    const float* pb   = (const float*)d_in[21];
    const int*   an   = (const int*)d_in[22];
    const int*   ei   = (const int*)d_in[23];
    float* out = (float*)d_out;

    static bool attr_done = false;
    if (!attr_done) {
        cudaFuncSetAttribute(k3_all,   cudaFuncAttributeMaxDynamicSharedMemorySize, K3_DSMEM);
        cudaFuncSetAttribute(k1g<0>,   cudaFuncAttributeMaxDynamicSharedMemorySize, K3_DSMEM);
        cudaFuncSetAttribute(k1g<1>,   cudaFuncAttributeMaxDynamicSharedMemorySize, K3_DSMEM);
        cudaFuncSetAttribute(k1g<2>,   cudaFuncAttributeMaxDynamicSharedMemorySize, K3_DSMEM);
        cudaFuncSetAttribute(k5b_proj, cudaFuncAttributeMaxDynamicSharedMemorySize, K3_DSMEM);
        attr_done = true;
    }

    // prelude: weight bf16 splits
    k0_fused<<<10496, 256>>>(w1, w2, w3, wm0, wm1, wm2, pw);

    // radial MLP on tensor cores: gather -> gemm -> LN -> gemm -> LN -> gemm
    k1a_gather<<<15000, 256>>>(ed, semb, temb, an, ei);
    k1g<0><<<dim3(1, 79), 256, K3_DSMEM>>>(b1);
    k1ln<<<1250, 256>>>(g1, bb1, 0);
    k1g<1><<<dim3(1, 79), 256, K3_DSMEM>>>(b2);
    k1ln<<<1250, 256>>>(g2, bb2, 1);
    k1g<2><<<dim3(15, 79), 256, K3_DSMEM>>>(b3);

    // msg * w_rad + Wigner forward
    k2_wfwd<<<E_EDGES, 256>>>(x, ef, wig, ei);

    // merged tensor-core GEMMs
    k3_all<<<K3_GRID, 256, K3_DSMEM>>>(bm0);

    // recombine + Wigner back -> bf16 split full
    k5a_wback<<<E_EDGES/4, 256>>>(wig);

    // projection GEMM (per-l merged)
    k5b_proj<<<K5B_GRID, 256, K3_DSMEM>>>(pb, out);
}